// round 7
// baseline (speedup 1.0000x reference)
#include <cuda_runtime.h>
#include <cuda_bf16.h>
#include <math.h>
#include <stdint.h>

// Problem constants
#define B_    8
#define N_    512
#define D_    1024
#define H_    16
#define HD_   64
#define NI_   4
#define G_    2
#define MROWS (B_*N_)      // 4096
#define SEQ   (NI_*N_)     // 2048
#define GH    (G_*H_)      // 32
#define D3    3072
#define SCALE 0.125f
#define S2    0.0078125f   // SCALE / H

// ---------------- scratch (device globals) -----------------------------------
static __device__ float g_qkvp[MROWS*D3];    // packed q|k|v projections
static __device__ float g_gacc[MROWS];
static __device__ float g_bqkv[D3];

#define AELEMS (GH*SEQ*HD_)
static __device__ __align__(256) __nv_bfloat16 g_qhg[AELEMS], g_qlg[AELEMS];
static __device__ __align__(256) __nv_bfloat16 g_khg[AELEMS], g_klg[AELEMS];
static __device__ __align__(256) __nv_bfloat16 g_vhg[AELEMS], g_vlg[AELEMS];

static __device__ __align__(256) __nv_bfloat16 g_wqkvh[D3*D_], g_wqkvl[D3*D_];
static __device__ __align__(256) __nv_bfloat16 g_wiqh[D_*D_], g_wiql[D_*D_];
static __device__ __align__(256) __nv_bfloat16 g_wikh[D_*D_], g_wikl[D_*D_];
static __device__ __align__(256) __nv_bfloat16 g_woh[D_*D_], g_wol[D_*D_];
static __device__ __align__(256) __nv_bfloat16 g_xh[MROWS*D_],  g_xl[MROWS*D_];
static __device__ __align__(256) __nv_bfloat16 g_ah[MROWS*D_],  g_al[MROWS*D_];
static __device__ __align__(256) __nv_bfloat16 g_fh[MROWS*D_],  g_fl[MROWS*D_];
static __device__ __align__(256) __nv_bfloat16 g_iqh[MROWS*D_];
static __device__ __align__(256) __nv_bfloat16 g_ikh[MROWS*D_];

// ---------------- PTX helpers --------------------------------------------------
__device__ __forceinline__ uint32_t smem_u32(const void* p) {
    uint32_t a;
    asm("{ .reg .u64 t; cvta.to.shared.u64 t, %1; cvt.u32.u64 %0, t; }"
        : "=r"(a) : "l"(p));
    return a;
}

#define LDSM4(r, addr) \
    asm volatile("ldmatrix.sync.aligned.m8n8.x4.shared.b16 {%0,%1,%2,%3}, [%4];" \
        : "=r"((r)[0]), "=r"((r)[1]), "=r"((r)[2]), "=r"((r)[3]) : "r"(addr))

#define LDSM4T(r, addr) \
    asm volatile("ldmatrix.sync.aligned.m8n8.x4.trans.shared.b16 {%0,%1,%2,%3}, [%4];" \
        : "=r"((r)[0]), "=r"((r)[1]), "=r"((r)[2]), "=r"((r)[3]) : "r"(addr))

#define MMA16816(d, a, bv0, bv1) \
    asm volatile("mma.sync.aligned.m16n8k16.row.col.f32.bf16.bf16.f32 " \
        "{%0,%1,%2,%3}, {%4,%5,%6,%7}, {%8,%9}, {%0,%1,%2,%3};" \
        : "+f"((d)[0]), "+f"((d)[1]), "+f"((d)[2]), "+f"((d)[3]) \
        : "r"((a)[0]), "r"((a)[1]), "r"((a)[2]), "r"((a)[3]), "r"(bv0), "r"(bv1))

#define CP_ASYNC16(dst, src) \
    asm volatile("cp.async.cg.shared.global [%0], [%1], 16;" \
        :: "r"(dst), "l"(__cvta_generic_to_global(src)) : "memory")
#define CP_COMMIT() asm volatile("cp.async.commit_group;" ::: "memory")
#define CP_WAIT(n)  asm volatile("cp.async.wait_group %0;" :: "n"(n) : "memory")

__device__ __forceinline__ uint32_t packbf(float a, float b) {
    uint32_t d;
    asm("cvt.rn.bf16x2.f32 %0, %1, %2;" : "=r"(d) : "f"(b), "f"(a));
    return d;
}
__device__ __forceinline__ float bflo(uint32_t v) { return __uint_as_float(v << 16); }
__device__ __forceinline__ float bfhi(uint32_t v) { return __uint_as_float(v & 0xffff0000u); }

// ---------------- HMMA split-bf16 GEMM, 3-stage pipe + frag double-buffer -----
#define TC_SMEM_3P (3*65536)   // 196608
#define TC_SMEM_1P (3*32768)   //  98304
__global__ __launch_bounds__(256, 1)
void mma_gemm_kernel(const __nv_bfloat16* __restrict__ Ahp, const __nv_bfloat16* __restrict__ Alp,
                     const __nv_bfloat16* __restrict__ Bhp, const __nv_bfloat16* __restrict__ Blp,
                     const float* __restrict__ bias, float* __restrict__ C,
                     __nv_bfloat16* __restrict__ Cbf,
                     const float* __restrict__ grow, float* __restrict__ gout,
                     const __nv_bfloat16* __restrict__ Ahp2, const __nv_bfloat16* __restrict__ Bhp2,
                     const float* __restrict__ bias2, __nv_bfloat16* __restrict__ Cbf2,
                     int M, int N, int K, long sA, long sB, long sC,
                     int three_pass, int out_mode)
{
    extern __shared__ char smem[];
    uint32_t sb = smem_u32(smem);
    int tid = threadIdx.x, wid = tid >> 5, lane = tid & 31;
    int m0 = blockIdx.y * 128, n0 = blockIdx.x * 128;
    long zb = blockIdx.z;
    const __nv_bfloat16* Ah = Ahp + zb * sA;
    const __nv_bfloat16* Al = three_pass ? (Alp + zb * sA) : Ahp;
    const __nv_bfloat16* Bh = Bhp + zb * sB;
    const __nv_bfloat16* Bl = three_pass ? (Blp + zb * sB) : Bhp;
    if (out_mode == 1 && blockIdx.z == 1) {
        Ah = Ahp2; Bh = Bhp2; bias = bias2; Cbf = Cbf2;
    }

    const int nsteps = K / 64;
    const uint32_t SS   = three_pass ? 65536 : 32768;
    const uint32_t BOFF = three_pass ? 32768 : 16384;

    auto issue = [&](int step, int stage) {
        uint32_t stb = sb + stage * SS;
        int k0 = step * 64;
        if (three_pass) {
#pragma unroll
            for (int i = 0; i < 16; i++) {
                int c = i * 256 + tid;
                int tile = c >> 10;
                int w = c & 1023;
                int row = w >> 3, ch = w & 7;
                const __nv_bfloat16* src;
                int gr;
                if      (tile == 0) { src = Ah; gr = m0 + row; }
                else if (tile == 1) { src = Al; gr = m0 + row; }
                else if (tile == 2) { src = Bh; gr = n0 + row; }
                else                { src = Bl; gr = n0 + row; }
                const __nv_bfloat16* gp = src + (long)gr * K + k0 + ch * 8;
                uint32_t dst = stb + tile * 16384 + row * 128 + ((ch ^ (row & 7)) << 4);
                CP_ASYNC16(dst, gp);
            }
        } else {
#pragma unroll
            for (int i = 0; i < 8; i++) {
                int c = i * 256 + tid;
                int half = c >> 10;
                int w = c & 1023;
                int row = w >> 3, ch = w & 7;
                const __nv_bfloat16* src = half ? Bh : Ah;
                int gr = (half ? n0 : m0) + row;
                const __nv_bfloat16* gp = src + (long)gr * K + k0 + ch * 8;
                uint32_t dst = stb + half * 16384 + row * 128 + ((ch ^ (row & 7)) << 4);
                CP_ASYNC16(dst, gp);
            }
        }
        CP_COMMIT();
    };

    int mbase = (wid >> 2) * 64;
    int nbase = (wid & 3) * 32;
    int arow = lane & 15;
    int brow = (lane & 7) + ((lane >> 4) & 1) * 8;

    float acc[4][4][4];
#pragma unroll
    for (int mt = 0; mt < 4; mt++)
#pragma unroll
        for (int nt = 0; nt < 4; nt++)
#pragma unroll
            for (int e = 0; e < 4; e++) acc[mt][nt][e] = 0.f;

    // ping-pong fragment buffers
    uint32_t ahf[2][4][4], alf[2][4][4], bhf[2][2][4], blf[2][2][4];

    auto load_frags = [&](uint32_t stb, int k16, int buf) {
        int ach = 2 * k16 + (lane >> 4);
#pragma unroll
        for (int mt = 0; mt < 4; mt++) {
            int row = mbase + mt * 16 + arow;
            uint32_t ad = stb + row * 128 + ((ach ^ (row & 7)) << 4);
            LDSM4(ahf[buf][mt], ad);
            if (three_pass) LDSM4(alf[buf][mt], ad + 16384);
        }
        int bch = 2 * k16 + ((lane >> 3) & 1);
#pragma unroll
        for (int j = 0; j < 2; j++) {
            int row = nbase + j * 16 + brow;
            uint32_t bd = stb + BOFF + row * 128 + ((bch ^ (row & 7)) << 4);
            LDSM4(bhf[buf][j], bd);
            if (three_pass) LDSM4(blf[buf][j], bd + 16384);
        }
    };

    issue(0, 0);
    if (nsteps > 1) issue(1, 1);
    if (nsteps > 2) issue(2, 2);

    for (int step = 0; step < nsteps; step++) {
        int rem = nsteps - 1 - step;
        if (rem >= 2)      { CP_WAIT(2); }
        else if (rem == 1) { CP_WAIT(1); }
        else               { CP_WAIT(0); }
        __syncthreads();

        uint32_t stb = sb + (uint32_t)(step % 3) * SS;
        load_frags(stb, 0, 0);
#pragma unroll
        for (int k16 = 0; k16 < 4; k16++) {
            int cur = k16 & 1;
            if (k16 < 3) load_frags(stb, k16 + 1, cur ^ 1);   // prefetch next frags
#pragma unroll
            for (int mt = 0; mt < 4; mt++)
#pragma unroll
                for (int nt = 0; nt < 4; nt++) {
                    int j = nt >> 1, p = (nt & 1) * 2;
                    MMA16816(acc[mt][nt], ahf[cur][mt], bhf[cur][j][p], bhf[cur][j][p+1]);
                }
            if (three_pass) {
#pragma unroll
                for (int mt = 0; mt < 4; mt++)
#pragma unroll
                    for (int nt = 0; nt < 4; nt++) {
                        int j = nt >> 1, p = (nt & 1) * 2;
                        MMA16816(acc[mt][nt], ahf[cur][mt], blf[cur][j][p], blf[cur][j][p+1]);
                    }
#pragma unroll
                for (int mt = 0; mt < 4; mt++)
#pragma unroll
                    for (int nt = 0; nt < 4; nt++) {
                        int j = nt >> 1, p = (nt & 1) * 2;
                        MMA16816(acc[mt][nt], alf[cur][mt], bhf[cur][j][p], bhf[cur][j][p+1]);
                    }
            }
        }
        __syncthreads();
        if (step + 3 < nsteps) issue(step + 3, step % 3);
    }

    // ------------------------------ epilogues ---------------------------------
    if (out_mode == 3) {
#pragma unroll
        for (int mt = 0; mt < 4; mt++) {
            int r0 = m0 + mbase + mt * 16 + (lane >> 2);
            float ps0 = 0.f, ps1 = 0.f;
#pragma unroll
            for (int nt = 0; nt < 4; nt++) {
                ps0 += 1.0f / (1.0f + __expf(-acc[mt][nt][0] * S2));
                ps0 += 1.0f / (1.0f + __expf(-acc[mt][nt][1] * S2));
                ps1 += 1.0f / (1.0f + __expf(-acc[mt][nt][2] * S2));
                ps1 += 1.0f / (1.0f + __expf(-acc[mt][nt][3] * S2));
            }
            ps0 += __shfl_xor_sync(0xffffffffu, ps0, 1, 4);
            ps0 += __shfl_xor_sync(0xffffffffu, ps0, 2, 4);
            ps1 += __shfl_xor_sync(0xffffffffu, ps1, 1, 4);
            ps1 += __shfl_xor_sync(0xffffffffu, ps1, 2, 4);
            if ((lane & 3) == 0) {
                atomicAdd(&gout[zb * 512 + r0], ps0);
                atomicAdd(&gout[zb * 512 + r0 + 8], ps1);
            }
        }
        return;
    }

#pragma unroll
    for (int mt = 0; mt < 4; mt++) {
        int r0 = m0 + mbase + mt * 16 + (lane >> 2);
        float g0 = 1.f, g1 = 1.f;
        if (out_mode == 2) {
            g0 = 1.0f + grow[r0] * (1.0f/512.0f);
            g1 = 1.0f + grow[r0 + 8] * (1.0f/512.0f);
        }
#pragma unroll
        for (int nt = 0; nt < 4; nt++) {
            int c = n0 + nbase + nt * 8 + 2 * (lane & 3);
            float b0 = 0.f, b1 = 0.f;
            if (bias) { b0 = bias[c]; b1 = bias[c + 1]; }
            float v00 = acc[mt][nt][0] * g0 + b0, v01 = acc[mt][nt][1] * g0 + b1;
            float v10 = acc[mt][nt][2] * g1 + b0, v11 = acc[mt][nt][3] * g1 + b1;
            if (out_mode == 1) {
                *(uint32_t*)&Cbf[(long)r0 * N + c]       = packbf(v00, v01);
                *(uint32_t*)&Cbf[(long)(r0 + 8) * N + c] = packbf(v10, v11);
            } else {
                float* Cc = C + zb * sC;
                float2 w0; w0.x = v00; w0.y = v01;
                *(float2*)&Cc[(long)r0 * N + c] = w0;
                float2 w1; w1.x = v10; w1.y = v11;
                *(float2*)&Cc[(long)(r0 + 8) * N + c] = w1;
            }
        }
    }
}

// ---------------- weight transpose + split (single weight) -------------------
__device__ __forceinline__ void wt_split_body(
    const float* __restrict__ W, __nv_bfloat16* __restrict__ Th, __nv_bfloat16* __restrict__ Tl,
    float (*t)[65])
{
    int n0 = blockIdx.x * 64, k0 = blockIdx.y * 64;
    int tid = threadIdx.x;
#pragma unroll
    for (int it = 0; it < 4; it++) {
        int row = (tid >> 4) + it * 16;
        int c4 = (tid & 15) * 4;
        float4 v = *(const float4*)&W[(long)(k0 + row) * D_ + n0 + c4];
        t[row][c4+0] = v.x; t[row][c4+1] = v.y; t[row][c4+2] = v.z; t[row][c4+3] = v.w;
    }
    __syncthreads();
    int n = tid >> 2, kc = (tid & 3) * 16;
    uint32_t hb[8], lb[8];
#pragma unroll
    for (int j = 0; j < 16; j += 2) {
        float f0 = t[kc + j][n], f1 = t[kc + j + 1][n];
        uint32_t h = packbf(f0, f1);
        hb[j >> 1] = h;
        lb[j >> 1] = packbf(f0 - bflo(h), f1 - bfhi(h));
    }
    long obase = (long)(n0 + n) * D_ + k0 + kc;
    *(uint4*)&Th[obase]     = make_uint4(hb[0], hb[1], hb[2], hb[3]);
    *(uint4*)&Th[obase + 8] = make_uint4(hb[4], hb[5], hb[6], hb[7]);
    *(uint4*)&Tl[obase]     = make_uint4(lb[0], lb[1], lb[2], lb[3]);
    *(uint4*)&Tl[obase + 8] = make_uint4(lb[4], lb[5], lb[6], lb[7]);
}

__global__ __launch_bounds__(256) void wt_split_kernel(
    const float* __restrict__ W, __nv_bfloat16* __restrict__ Th, __nv_bfloat16* __restrict__ Tl)
{
    __shared__ float t[64][65];
    wt_split_body(W, Th, Tl, t);
}

// fused 3-weight split (z selects weight)
__global__ __launch_bounds__(256) void wt_split3_kernel(
    const float* __restrict__ W0, __nv_bfloat16* __restrict__ Th0, __nv_bfloat16* __restrict__ Tl0,
    const float* __restrict__ W1, __nv_bfloat16* __restrict__ Th1, __nv_bfloat16* __restrict__ Tl1,
    const float* __restrict__ W2, __nv_bfloat16* __restrict__ Th2, __nv_bfloat16* __restrict__ Tl2)
{
    __shared__ float t[64][65];
    const float* W = (blockIdx.z == 0) ? W0 : (blockIdx.z == 1) ? W1 : W2;
    __nv_bfloat16* Th = (blockIdx.z == 0) ? Th0 : (blockIdx.z == 1) ? Th1 : Th2;
    __nv_bfloat16* Tl = (blockIdx.z == 0) ? Tl0 : (blockIdx.z == 1) ? Tl1 : Tl2;
    wt_split_body(W, Th, Tl, t);
}

// ---------------- bias concat (bq|bk|bv) --------------------------------------
__global__ void bias3_kernel(const float* __restrict__ a, const float* __restrict__ b,
                             const float* __restrict__ c, float* __restrict__ o)
{
    int i = blockIdx.x * 256 + threadIdx.x;
    if (i < 1024)       o[i] = a[i];
    else if (i < 2048)  o[i] = b[i - 1024];
    else if (i < 3072)  o[i] = c[i - 2048];
}

// ---------------- activation split ---------------------------------------------
__global__ __launch_bounds__(256) void split_kernel(
    const float* __restrict__ src, __nv_bfloat16* __restrict__ h,
    __nv_bfloat16* __restrict__ l, int n4)
{
    int i = blockIdx.x * 256 + threadIdx.x;
    if (i >= n4) return;
    float4 f = ((const float4*)src)[i];
    uint32_t h0 = packbf(f.x, f.y), h1 = packbf(f.z, f.w);
    ((uint32_t*)h)[i*2+0] = h0;
    ((uint32_t*)h)[i*2+1] = h1;
    ((uint32_t*)l)[i*2+0] = packbf(f.x - bflo(h0), f.y - bfhi(h0));
    ((uint32_t*)l)[i*2+1] = packbf(f.z - bflo(h1), f.w - bfhi(h1));
}

// ------- RMS-norm (q,k) + split to bf16 hi/lo, scatter into [GH, SEQ, HD] ----
__global__ __launch_bounds__(256) void rms_scatter_kernel(
    const float* __restrict__ qkv,
    const float* __restrict__ qw, const float* __restrict__ kw,
    __nv_bfloat16* __restrict__ qh, __nv_bfloat16* __restrict__ ql,
    __nv_bfloat16* __restrict__ kh, __nv_bfloat16* __restrict__ kl,
    __nv_bfloat16* __restrict__ vh, __nv_bfloat16* __restrict__ vl)
{
    int wid  = (blockIdx.x * 256 + threadIdx.x) >> 5;
    int lane = threadIdx.x & 31;
    int h  = wid & 15;
    int bn = wid >> 4;
    int b  = bn >> 9;
    long ibase = (long)bn * D3 + h * HD_;
    int g = b >> 2, inst = b & 3;
    int n = bn & 511;
    long obase = (((long)(g*16 + h)) * SEQ + inst*512 + n) * HD_;

    auto emit = [&](float v, __nv_bfloat16* ph, __nv_bfloat16* pl, long off) {
        __nv_bfloat16 hb = __float2bfloat16(v);
        ph[off] = hb;
        pl[off] = __float2bfloat16(v - __bfloat162float(hb));
    };
    {
        float v0 = qkv[ibase + lane], v1 = qkv[ibase + lane + 32];
        float ss = v0*v0 + v1*v1;
#pragma unroll
        for (int off = 16; off; off >>= 1) ss += __shfl_xor_sync(0xffffffffu, ss, off);
        float sc = rsqrtf(ss * (1.0f/64.0f) + 1e-6f) * SCALE;
        emit(v0 * sc * qw[lane],      qh, ql, obase + lane);
        emit(v1 * sc * qw[lane + 32], qh, ql, obase + lane + 32);
    }
    {
        float v0 = qkv[ibase + 1024 + lane], v1 = qkv[ibase + 1024 + lane + 32];
        float ss = v0*v0 + v1*v1;
#pragma unroll
        for (int off = 16; off; off >>= 1) ss += __shfl_xor_sync(0xffffffffu, ss, off);
        float sc = rsqrtf(ss * (1.0f/64.0f) + 1e-6f);
        emit(v0 * sc * kw[lane],      kh, kl, obase + lane);
        emit(v1 * sc * kw[lane + 32], kh, kl, obase + lane + 32);
    }
    emit(qkv[ibase + 2048 + lane],      vh, vl, obase + lane);
    emit(qkv[ibase + 2048 + lane + 32], vh, vl, obase + lane + 32);
}

// ---------------- flash attention via mma.sync (split-bf16 3-pass) -----------
#define FL_SMEM (2*65536 + 32768)
__global__ __launch_bounds__(256, 1)
void flash_mma_kernel(const __nv_bfloat16* __restrict__ Qh_, const __nv_bfloat16* __restrict__ Ql_,
                      const __nv_bfloat16* __restrict__ Kh_, const __nv_bfloat16* __restrict__ Kl_,
                      const __nv_bfloat16* __restrict__ Vh_, const __nv_bfloat16* __restrict__ Vl_,
                      __nv_bfloat16* __restrict__ Oh, __nv_bfloat16* __restrict__ Ol)
{
    extern __shared__ char smem[];
    uint32_t sb = smem_u32(smem);
    int tid = threadIdx.x, wid = tid >> 5, lane = tid & 31;
    int qt = blockIdx.x, gh = blockIdx.y;
    long ghoff = (long)gh * SEQ * HD_;
    const __nv_bfloat16* Qh = Qh_ + ghoff + (long)qt * 128 * HD_;
    const __nv_bfloat16* Ql = Ql_ + ghoff + (long)qt * 128 * HD_;
    const __nv_bfloat16* Kh = Kh_ + ghoff;
    const __nv_bfloat16* Kl = Kl_ + ghoff;
    const __nv_bfloat16* Vh = Vh_ + ghoff;
    const __nv_bfloat16* Vl = Vl_ + ghoff;

    const uint32_t QOFF = 131072;

    {
#pragma unroll
        for (int i = 0; i < 8; i++) {
            int c = i * 256 + tid;
            int arr = c >> 10, w = c & 1023, row = w >> 3, ch = w & 7;
            const __nv_bfloat16* src = (arr ? Ql : Qh) + (long)row * 64 + ch * 8;
            uint32_t dst = sb + QOFF + arr * 16384 + row * 128 + ((ch ^ (row & 7)) << 4);
            CP_ASYNC16(dst, src);
        }
        CP_COMMIT();
    }

    auto issueKV = [&](int it, int stage) {
        uint32_t stb = sb + stage * 65536;
#pragma unroll
        for (int i = 0; i < 16; i++) {
            int c = i * 256 + tid;
            int arr = c >> 10, w = c & 1023, row = w >> 3, ch = w & 7;
            const __nv_bfloat16* src;
            if      (arr == 0) src = Kh;
            else if (arr == 1) src = Kl;
            else if (arr == 2) src = Vh;
            else               src = Vl;
            src += (long)(it * 128 + row) * 64 + ch * 8;
            uint32_t dst = stb + arr * 16384 + row * 128 + ((ch ^ (row & 7)) << 4);
            CP_ASYNC16(dst, src);
        }
        CP_COMMIT();
    };

    issueKV(0, 0);
    issueKV(1, 1);
    CP_WAIT(1);
    __syncthreads();

    uint32_t qhf[4][4], qlf[4][4];
    {
        int arow = lane & 15;
#pragma unroll
        for (int kt = 0; kt < 4; kt++) {
            int row = wid * 16 + arow;
            int ach = 2 * kt + (lane >> 4);
            uint32_t ad = sb + QOFF + row * 128 + ((ach ^ (row & 7)) << 4);
            LDSM4(qhf[kt], ad);
            LDSM4(qlf[kt], ad + 16384);
        }
    }

    float o[8][4];
#pragma unroll
    for (int nt = 0; nt < 8; nt++)
#pragma unroll
        for (int e = 0; e < 4; e++) o[nt][e] = 0.f;
    float m0 = -1e30f, m1 = -1e30f, lp0 = 0.f, lp1 = 0.f;

    for (int it = 0; it < 16; it++) {
        if (it > 0) {
            if (it < 15) { CP_WAIT(1); } else { CP_WAIT(0); }
            __syncthreads();
        }
        uint32_t stb = sb + (it & 1) * 65536;

        float s[16][4];
#pragma unroll
        for (int t = 0; t < 16; t++)
#pragma unroll
            for (int e = 0; e < 4; e++) s[t][e] = 0.f;

        int brow = (lane & 7) + ((lane >> 4) & 1) * 8;
#pragma unroll
        for (int kt = 0; kt < 4; kt++) {
            int bch = 2 * kt + ((lane >> 3) & 1);
#pragma unroll
            for (int jp = 0; jp < 4; jp++) {
                uint32_t khf[2][4], klf[2][4];
#pragma unroll
                for (int j = 0; j < 2; j++) {
                    int row = (2 * jp + j) * 16 + brow;
                    uint32_t bd = stb + row * 128 + ((bch ^ (row & 7)) << 4);
                    LDSM4(khf[j], bd);
                    LDSM4(klf[j], bd + 16384);
                }
                int t0 = 4 * jp;
                MMA16816(s[t0+0], qhf[kt], khf[0][0], khf[0][1]);
                MMA16816(s[t0+1], qhf[kt], khf[0][2], khf[0][3]);
                MMA16816(s[t0+2], qhf[kt], khf[1][0], khf[1][1]);
                MMA16816(s[t0+3], qhf[kt], khf[1][2], khf[1][3]);
                MMA16816(s[t0+0], qhf[kt], klf[0][0], klf[0][1]);
                MMA16816(s[t0+1], qhf[kt], klf[0][2], klf[0][3]);
                MMA16816(s[t0+2], qhf[kt], klf[1][0], klf[1][1]);
                MMA16816(s[t0+3], qhf[kt], klf[1][2], klf[1][3]);
                MMA16816(s[t0+0], qlf[kt], khf[0][0], khf[0][1]);
                MMA16816(s[t0+1], qlf[kt], khf[0][2], khf[0][3]);
                MMA16816(s[t0+2], qlf[kt], khf[1][0], khf[1][1]);
                MMA16816(s[t0+3], qlf[kt], khf[1][2], khf[1][3]);
            }
        }

        float t0 = -1e30f, t1 = -1e30f;
#pragma unroll
        for (int t = 0; t < 16; t++) {
            t0 = fmaxf(t0, fmaxf(s[t][0], s[t][1]));
            t1 = fmaxf(t1, fmaxf(s[t][2], s[t][3]));
        }
        t0 = fmaxf(t0, __shfl_xor_sync(0xffffffffu, t0, 1, 4));
        t0 = fmaxf(t0, __shfl_xor_sync(0xffffffffu, t0, 2, 4));
        t1 = fmaxf(t1, __shfl_xor_sync(0xffffffffu, t1, 1, 4));
        t1 = fmaxf(t1, __shfl_xor_sync(0xffffffffu, t1, 2, 4));
        float mn0 = fmaxf(m0, t0), mn1 = fmaxf(m1, t1);
        float c0 = __expf(m0 - mn0), c1 = __expf(m1 - mn1);
        m0 = mn0; m1 = mn1;
        lp0 *= c0; lp1 *= c1;
#pragma unroll
        for (int nt = 0; nt < 8; nt++) {
            o[nt][0] *= c0; o[nt][1] *= c0;
            o[nt][2] *= c1; o[nt][3] *= c1;
        }
#pragma unroll
        for (int t = 0; t < 16; t++) {
            s[t][0] = __expf(s[t][0] - m0);
            s[t][1] = __expf(s[t][1] - m0);
            s[t][2] = __expf(s[t][2] - m1);
            s[t][3] = __expf(s[t][3] - m1);
            lp0 += s[t][0] + s[t][1];
            lp1 += s[t][2] + s[t][3];
        }

        int vrow = lane & 15;
#pragma unroll
        for (int kt = 0; kt < 8; kt++) {
            uint32_t pha[4], pla[4];
#pragma unroll
            for (int q = 0; q < 2; q++) {
                float a0 = s[2*kt + q][0], a1 = s[2*kt + q][1];
                float a2 = s[2*kt + q][2], a3 = s[2*kt + q][3];
                uint32_t h0 = packbf(a0, a1);
                uint32_t h1 = packbf(a2, a3);
                pha[2*q]   = h0;
                pha[2*q+1] = h1;
                pla[2*q]   = packbf(a0 - bflo(h0), a1 - bfhi(h0));
                pla[2*q+1] = packbf(a2 - bflo(h1), a3 - bfhi(h1));
            }
            int row = kt * 16 + vrow;
#pragma unroll
            for (int np = 0; np < 2; np++) {
                uint32_t vhf[2][4], vlf[2][4];
#pragma unroll
                for (int j = 0; j < 2; j++) {
                    int ch = 2 * (2 * np + j) + (lane >> 4);
                    uint32_t vd = stb + 32768 + row * 128 + ((ch ^ (row & 7)) << 4);
                    LDSM4T(vhf[j], vd);
                    LDSM4T(vlf[j], vd + 16384);
                }
                int ob = 4 * np;
                MMA16816(o[ob+0], pha, vhf[0][0], vhf[0][1]);
                MMA16816(o[ob+1], pha, vhf[0][2], vhf[0][3]);
                MMA16816(o[ob+2], pha, vhf[1][0], vhf[1][1]);
                MMA16816(o[ob+3], pha, vhf[1][2], vhf[1][3]);
                MMA16816(o[ob+0], pha, vlf[0][0], vlf[0][1]);
                MMA16816(o[ob+1], pha, vlf[0][2], vlf[0][3]);
                MMA16816(o[ob+2], pha, vlf[1][0], vlf[1][1]);
                MMA16816(o[ob+3], pha, vlf[1][2], vlf[1][3]);
                MMA16816(o[ob+0], pla, vhf[0][0], vhf[0][1]);
                MMA16816(o[ob+1], pla, vhf[0][2], vhf[0][3]);
                MMA16816(o[ob+2], pla, vhf[1][0], vhf[1][1]);
                MMA16816(o[ob+3], pla, vhf[1][2], vhf[1][3]);
            }
        }

        __syncthreads();
        if (it + 2 < 16) issueKV(it + 2, it & 1);
    }

    lp0 += __shfl_xor_sync(0xffffffffu, lp0, 1, 4);
    lp0 += __shfl_xor_sync(0xffffffffu, lp0, 2, 4);
    lp1 += __shfl_xor_sync(0xffffffffu, lp1, 1, 4);
    lp1 += __shfl_xor_sync(0xffffffffu, lp1, 2, 4);
    float inv0 = 1.0f / lp0, inv1 = 1.0f / lp1;

    int g = gh >> 4, h = gh & 15;
#pragma unroll
    for (int e = 0; e < 2; e++) {
        int r = qt * 128 + wid * 16 + (lane >> 2) + 8 * e;
        int inst = r >> 9, n = r & 511;
        int b = g * 4 + inst;
        float inv = e ? inv1 : inv0;
        long base = ((long)(b * 512 + n)) * D_ + h * HD_;
#pragma unroll
        for (int nt = 0; nt < 8; nt++) {
            float v0 = o[nt][2*e] * inv, v1 = o[nt][2*e+1] * inv;
            uint32_t hp = packbf(v0, v1);
            uint32_t lp = packbf(v0 - bflo(hp), v1 - bfhi(hp));
            long idx = base + nt * 8 + 2 * (lane & 3);
            *(uint32_t*)&Oh[idx] = hp;
            *(uint32_t*)&Ol[idx] = lp;
        }
    }
}

// ---------------- instance feature -> bf16 hi/lo ------------------------------
__global__ __launch_bounds__(256) void feat_kernel(
    const float* __restrict__ mask, const float* __restrict__ embed,
    __nv_bfloat16* __restrict__ fh, __nv_bfloat16* __restrict__ fl)
{
    int row = blockIdx.x;
    float m0 = mask[row*4+0], m1 = mask[row*4+1];
    float m2 = mask[row*4+2], m3 = mask[row*4+3];
    for (int c = threadIdx.x * 2; c < D_; c += 512) {
        float f0 = m0*embed[c]   + m1*embed[D_ + c]   + m2*embed[2*D_ + c]   + m3*embed[3*D_ + c];
        float f1 = m0*embed[c+1] + m1*embed[D_ + c+1] + m2*embed[2*D_ + c+1] + m3*embed[3*D_ + c+1];
        uint32_t h = packbf(f0, f1);
        *(uint32_t*)&fh[(long)row*D_ + c] = h;
        *(uint32_t*)&fl[(long)row*D_ + c] = packbf(f0 - bflo(h), f1 - bfhi(h));
    }
}

__global__ void zero_kernel(float* __restrict__ p, int n)
{
    int i = blockIdx.x * blockDim.x + threadIdx.x;
    if (i < n) p[i] = 0.f;
}

// ------------------------------- launch --------------------------------------
extern "C" void kernel_launch(void* const* d_in, const int* in_sizes, int n_in,
                              void* d_out, int out_size)
{
    const float* x     = (const float*)d_in[0];
    const float* mask  = (const float*)d_in[1];
    const float* Wq    = (const float*)d_in[2];
    const float* bq    = (const float*)d_in[3];
    const float* Wk    = (const float*)d_in[4];
    const float* bk    = (const float*)d_in[5];
    const float* Wv    = (const float*)d_in[6];
    const float* bv    = (const float*)d_in[7];
    const float* Wo    = (const float*)d_in[8];
    const float* bo    = (const float*)d_in[9];
    const float* Wiq   = (const float*)d_in[10];
    const float* biq   = (const float*)d_in[11];
    const float* Wik   = (const float*)d_in[12];
    const float* bik   = (const float*)d_in[13];
    const float* embed = (const float*)d_in[14];
    const float* qw    = (const float*)d_in[15];
    const float* kw    = (const float*)d_in[16];
    float* out = (float*)d_out;

    float *qkvp,*gacc,*bqkv;
    cudaGetSymbolAddress((void**)&qkvp, g_qkvp);
    cudaGetSymbolAddress((void**)&gacc, g_gacc);
    cudaGetSymbolAddress((void**)&bqkv, g_bqkv);

    __nv_bfloat16 *qhg,*qlg,*khg,*klg,*vhg,*vlg;
    cudaGetSymbolAddress((void**)&qhg, g_qhg);   cudaGetSymbolAddress((void**)&qlg, g_qlg);
    cudaGetSymbolAddress((void**)&khg, g_khg);   cudaGetSymbolAddress((void**)&klg, g_klg);
    cudaGetSymbolAddress((void**)&vhg, g_vhg);   cudaGetSymbolAddress((void**)&vlg, g_vlg);

    __nv_bfloat16 *wqkvh,*wqkvl,*wiqh,*wiql,*wikh,*wikl,*woh,*wol;
    __nv_bfloat16 *xh,*xl,*ah,*al,*fh,*fl,*iqh,*ikh;
    cudaGetSymbolAddress((void**)&wqkvh, g_wqkvh); cudaGetSymbolAddress((void**)&wqkvl, g_wqkvl);
    cudaGetSymbolAddress((void**)&wiqh, g_wiqh);   cudaGetSymbolAddress((void**)&wiql, g_wiql);
    cudaGetSymbolAddress((void**)&wikh, g_wikh);   cudaGetSymbolAddress((void**)&wikl, g_wikl);
    cudaGetSymbolAddress((void**)&woh, g_woh);     cudaGetSymbolAddress((void**)&wol, g_wol);
    cudaGetSymbolAddress((void**)&xh, g_xh);       cudaGetSymbolAddress((void**)&xl, g_xl);
    cudaGetSymbolAddress((void**)&ah, g_ah);       cudaGetSymbolAddress((void**)&al, g_al);
    cudaGetSymbolAddress((void**)&fh, g_fh);       cudaGetSymbolAddress((void**)&fl, g_fl);
    cudaGetSymbolAddress((void**)&iqh, g_iqh);     cudaGetSymbolAddress((void**)&ikh, g_ikh);

    cudaFuncSetAttribute((const void*)mma_gemm_kernel,
                         cudaFuncAttributeMaxDynamicSharedMemorySize, TC_SMEM_3P);
    cudaFuncSetAttribute((const void*)flash_mma_kernel,
                         cudaFuncAttributeMaxDynamicSharedMemorySize, FL_SMEM);

    dim3 wtg(16, 16);
    dim3 wtg3(16, 16, 3);
    const int N4 = MROWS * D_ / 4;
    const int SPLIT_BLOCKS = (N4 + 255) / 256;
    dim3 big_grid(D_/128, MROWS/128, 1);     // (8, 32)
    dim3 qkv_grid(D3/128, MROWS/128, 1);     // (24, 32)

    // launches 1-5 (so the QKV GEMM is launch #6 -> captured by ncu -s 5 -c 1)
    wt_split_kernel<<<wtg, 256>>>(Wq,  wqkvh,             wqkvl);
    wt_split_kernel<<<wtg, 256>>>(Wk,  wqkvh + 1024*1024, wqkvl + 1024*1024);
    wt_split_kernel<<<wtg, 256>>>(Wv,  wqkvh + 2048*1024, wqkvl + 2048*1024);
    bias3_kernel<<<12, 256>>>(bq, bk, bv, bqkv);
    split_kernel<<<SPLIT_BLOCKS, 256>>>(x, xh, xl, N4);

    // launch #6: fused QKV projection (3-pass, N=3072)
    mma_gemm_kernel<<<qkv_grid, 256, TC_SMEM_3P>>>(
        xh, xl, wqkvh, wqkvl, bqkv, qkvp, nullptr, nullptr, nullptr,
        nullptr, nullptr, nullptr, nullptr,
        MROWS, D3, D_, 0, 0, 0, 1, 0);

    // remaining weight splits (Wiq, Wik, Wo fused)
    wt_split3_kernel<<<wtg3, 256>>>(Wiq, wiqh, wiql, Wik, wikh, wikl, Wo, woh, wol);

    // per-head RMS norm + split/scatter; attention (writes ah/al directly)
    rms_scatter_kernel<<<(MROWS*H_)/8, 256>>>(qkvp, qw, kw,
                                              qhg, qlg, khg, klg, vhg, vlg);
    flash_mma_kernel<<<dim3(SEQ/128, GH), 256, FL_SMEM>>>(qhg, qlg, khg, klg, vhg, vlg, ah, al);

    // instance features
    feat_kernel<<<MROWS, 256>>>(mask, embed, fh, fl);

    // iq & ik projections fused (z selects operand set)
    mma_gemm_kernel<<<dim3(8, 32, 2), 256, TC_SMEM_1P>>>(
        ah, nullptr, wiqh, nullptr, biq, nullptr, iqh, nullptr, nullptr,
        fh, wikh, bik, ikh,
        MROWS, D_, D_, 0, 0, 0, 0, 1);

    // gate: per-batch iq @ ik^T with fused sigmoid row-sum (atomics)
    zero_kernel<<<(MROWS+255)/256, 256>>>(gacc, MROWS);
    mma_gemm_kernel<<<dim3(4, 4, 8), 256, TC_SMEM_1P>>>(
        iqh, nullptr, ikh, nullptr, nullptr, nullptr, nullptr, nullptr, gacc,
        nullptr, nullptr, nullptr, nullptr,
        512, 512, D_, (long)512*D_, (long)512*D_, 0, 0, 3);

    // gated output projection: out = diag(1+gacc/512) * (attn @ Wo) + bo
    mma_gemm_kernel<<<big_grid, 256, TC_SMEM_3P>>>(
        ah, al, woh, wol, bo, out, nullptr, gacc, nullptr,
        nullptr, nullptr, nullptr, nullptr,
        MROWS, D_, D_, 0, 0, 0, 1, 2);
}

// round 8
// speedup vs baseline: 1.0353x; 1.0353x over previous
#include <cuda_runtime.h>
#include <cuda_bf16.h>
#include <math.h>
#include <stdint.h>

// Problem constants
#define B_    8
#define N_    512
#define D_    1024
#define H_    16
#define HD_   64
#define NI_   4
#define G_    2
#define MROWS (B_*N_)      // 4096
#define SEQ   (NI_*N_)     // 2048
#define GH    (G_*H_)      // 32
#define D3    3072
#define SCALE 0.125f
#define S2    0.0078125f   // SCALE / H

// ---------------- scratch (device globals) -----------------------------------
static __device__ float g_qkvp[MROWS*D3];    // packed q|k|v projections
static __device__ float g_gacc[MROWS];
static __device__ float g_bqkv[D3];

#define AELEMS (GH*SEQ*HD_)
static __device__ __align__(256) __nv_bfloat16 g_qhg[AELEMS], g_qlg[AELEMS];
static __device__ __align__(256) __nv_bfloat16 g_khg[AELEMS], g_klg[AELEMS];
static __device__ __align__(256) __nv_bfloat16 g_vhg[AELEMS], g_vlg[AELEMS];

static __device__ __align__(256) __nv_bfloat16 g_wqkvh[D3*D_], g_wqkvl[D3*D_];
static __device__ __align__(256) __nv_bfloat16 g_wiqh[D_*D_], g_wiql[D_*D_];
static __device__ __align__(256) __nv_bfloat16 g_wikh[D_*D_], g_wikl[D_*D_];
static __device__ __align__(256) __nv_bfloat16 g_woh[D_*D_], g_wol[D_*D_];
static __device__ __align__(256) __nv_bfloat16 g_xh[MROWS*D_],  g_xl[MROWS*D_];
static __device__ __align__(256) __nv_bfloat16 g_ah[MROWS*D_],  g_al[MROWS*D_];
static __device__ __align__(256) __nv_bfloat16 g_fh[MROWS*D_],  g_fl[MROWS*D_];
static __device__ __align__(256) __nv_bfloat16 g_iqh[MROWS*D_];
static __device__ __align__(256) __nv_bfloat16 g_ikh[MROWS*D_];

// ---------------- PTX helpers --------------------------------------------------
__device__ __forceinline__ uint32_t smem_u32(const void* p) {
    uint32_t a;
    asm("{ .reg .u64 t; cvta.to.shared.u64 t, %1; cvt.u32.u64 %0, t; }"
        : "=r"(a) : "l"(p));
    return a;
}

#define LDSM4(r, addr) \
    asm volatile("ldmatrix.sync.aligned.m8n8.x4.shared.b16 {%0,%1,%2,%3}, [%4];" \
        : "=r"((r)[0]), "=r"((r)[1]), "=r"((r)[2]), "=r"((r)[3]) : "r"(addr))

#define LDSM4T(r, addr) \
    asm volatile("ldmatrix.sync.aligned.m8n8.x4.trans.shared.b16 {%0,%1,%2,%3}, [%4];" \
        : "=r"((r)[0]), "=r"((r)[1]), "=r"((r)[2]), "=r"((r)[3]) : "r"(addr))

#define MMA16816(d, a, bv0, bv1) \
    asm volatile("mma.sync.aligned.m16n8k16.row.col.f32.bf16.bf16.f32 " \
        "{%0,%1,%2,%3}, {%4,%5,%6,%7}, {%8,%9}, {%0,%1,%2,%3};" \
        : "+f"((d)[0]), "+f"((d)[1]), "+f"((d)[2]), "+f"((d)[3]) \
        : "r"((a)[0]), "r"((a)[1]), "r"((a)[2]), "r"((a)[3]), "r"(bv0), "r"(bv1))

#define CP_ASYNC16(dst, src) \
    asm volatile("cp.async.cg.shared.global [%0], [%1], 16;" \
        :: "r"(dst), "l"(__cvta_generic_to_global(src)) : "memory")
#define CP_COMMIT() asm volatile("cp.async.commit_group;" ::: "memory")
#define CP_WAIT(n)  asm volatile("cp.async.wait_group %0;" :: "n"(n) : "memory")

__device__ __forceinline__ uint32_t packbf(float a, float b) {
    uint32_t d;
    asm("cvt.rn.bf16x2.f32 %0, %1, %2;" : "=r"(d) : "f"(b), "f"(a));
    return d;
}
__device__ __forceinline__ float bflo(uint32_t v) { return __uint_as_float(v << 16); }
__device__ __forceinline__ float bfhi(uint32_t v) { return __uint_as_float(v & 0xffff0000u); }

// ---------------- HMMA split-bf16 GEMM: CTA 128x256, warp 64x64 ---------------
// C[z] = A[z] @ B[z]^T + bias.
// three_pass: 1 -> AhBh + AhBl + AlBh ; 0 -> AhBh only.
// out_mode: 0 fp32 C+bias; 1 bf16-hi Cbf (+bias, z selects operand set);
//           2 fp32 gate-scaled; 3 sigmoid row-sum atomics into gout.
// stage layout 3-pass (96KB): Ah@0(16K) Al@16K Bh@32K(32K,256rows) Bl@64K(32K)
// stage layout 1-pass (48KB): Ah@0(16K) Bh@16K(32K)
#define TC_SMEM_3P (2*98304)   // 196608
#define TC_SMEM_1P (2*49152)   //  98304
__global__ __launch_bounds__(256, 1)
void mma_gemm_kernel(const __nv_bfloat16* __restrict__ Ahp, const __nv_bfloat16* __restrict__ Alp,
                     const __nv_bfloat16* __restrict__ Bhp, const __nv_bfloat16* __restrict__ Blp,
                     const float* __restrict__ bias, float* __restrict__ C,
                     __nv_bfloat16* __restrict__ Cbf,
                     const float* __restrict__ grow, float* __restrict__ gout,
                     const __nv_bfloat16* __restrict__ Ahp2, const __nv_bfloat16* __restrict__ Bhp2,
                     const float* __restrict__ bias2, __nv_bfloat16* __restrict__ Cbf2,
                     int M, int N, int K, long sA, long sB, long sC,
                     int three_pass, int out_mode)
{
    extern __shared__ char smem[];
    uint32_t sb = smem_u32(smem);
    int tid = threadIdx.x, wid = tid >> 5, lane = tid & 31;
    int m0 = blockIdx.y * 128, n0 = blockIdx.x * 256;
    long zb = blockIdx.z;
    const __nv_bfloat16* Ah = Ahp + zb * sA;
    const __nv_bfloat16* Al = three_pass ? (Alp + zb * sA) : Ahp;
    const __nv_bfloat16* Bh = Bhp + zb * sB;
    const __nv_bfloat16* Bl = three_pass ? (Blp + zb * sB) : Bhp;
    if (out_mode == 1 && blockIdx.z == 1) {
        Ah = Ahp2; Bh = Bhp2; bias = bias2; Cbf = Cbf2;
    }

    const int nsteps = K / 64;
    const uint32_t SS   = three_pass ? 98304 : 49152;
    const uint32_t BOFF = three_pass ? 32768 : 16384;
    const int ncp = three_pass ? 24 : 12;   // iters of 256 threads covering tiles

    auto issue = [&](int step, int stage) {
        uint32_t stb = sb + stage * SS;
        int k0 = step * 64;
#pragma unroll
        for (int i = 0; i < 24; i++) {
            if (i >= ncp) break;
            int c = i * 256 + tid;
            int tile = c >> 10;          // 128-row tile index
            int w = c & 1023;
            int row = w >> 3, ch = w & 7;
            const __nv_bfloat16* src;
            int gr;
            uint32_t tbase;
            if (three_pass) {
                // 0:Ah 1:Al 2:Bh(lo rows) 3:Bh(hi rows) 4:Bl(lo) 5:Bl(hi)
                if      (tile == 0) { src = Ah; gr = m0 + row;        tbase = 0; }
                else if (tile == 1) { src = Al; gr = m0 + row;        tbase = 16384; }
                else if (tile == 2) { src = Bh; gr = n0 + row;        tbase = 32768; }
                else if (tile == 3) { src = Bh; gr = n0 + 128 + row;  tbase = 49152; }
                else if (tile == 4) { src = Bl; gr = n0 + row;        tbase = 65536; }
                else                { src = Bl; gr = n0 + 128 + row;  tbase = 81920; }
            } else {
                if      (tile == 0) { src = Ah; gr = m0 + row;        tbase = 0; }
                else if (tile == 1) { src = Bh; gr = n0 + row;        tbase = 16384; }
                else                { src = Bh; gr = n0 + 128 + row;  tbase = 32768; }
            }
            const __nv_bfloat16* gp = src + (long)gr * K + k0 + ch * 8;
            uint32_t dst = stb + tbase + row * 128 + ((ch ^ (row & 7)) << 4);
            CP_ASYNC16(dst, gp);
        }
        CP_COMMIT();
    };

    int mbase = (wid >> 2) * 64;    // 0 / 64
    int nbase = (wid & 3) * 64;     // 0 / 64 / 128 / 192
    int arow = lane & 15;
    int brow = (lane & 7) + ((lane >> 4) & 1) * 8;

    float acc[4][8][4];
#pragma unroll
    for (int mt = 0; mt < 4; mt++)
#pragma unroll
        for (int nt = 0; nt < 8; nt++)
#pragma unroll
            for (int e = 0; e < 4; e++) acc[mt][nt][e] = 0.f;

    issue(0, 0);
    if (nsteps > 1) issue(1, 1);

    for (int step = 0; step < nsteps; step++) {
        if (step + 1 < nsteps) { CP_WAIT(1); } else { CP_WAIT(0); }
        __syncthreads();

        uint32_t stb = sb + (uint32_t)(step & 1) * SS;
#pragma unroll
        for (int k16 = 0; k16 < 4; k16++) {
            uint32_t ahf[4][4], alf[4][4], bhf[4][4], blf[4][4];
            int ach = 2 * k16 + (lane >> 4);
#pragma unroll
            for (int mt = 0; mt < 4; mt++) {
                int row = mbase + mt * 16 + arow;
                uint32_t ad = stb + row * 128 + ((ach ^ (row & 7)) << 4);
                LDSM4(ahf[mt], ad);
                if (three_pass) LDSM4(alf[mt], ad + 16384);
            }
            int bch = 2 * k16 + ((lane >> 3) & 1);
#pragma unroll
            for (int j = 0; j < 4; j++) {
                int row = nbase + j * 16 + brow;
                uint32_t bd = stb + BOFF + row * 128 + ((bch ^ (row & 7)) << 4);
                LDSM4(bhf[j], bd);
                if (three_pass) LDSM4(blf[j], bd + 32768);
            }
            // pass 0: hi*hi
#pragma unroll
            for (int mt = 0; mt < 4; mt++)
#pragma unroll
                for (int nt = 0; nt < 8; nt++) {
                    int j = nt >> 1, p = (nt & 1) * 2;
                    MMA16816(acc[mt][nt], ahf[mt], bhf[j][p], bhf[j][p+1]);
                }
            if (three_pass) {
#pragma unroll
                for (int mt = 0; mt < 4; mt++)
#pragma unroll
                    for (int nt = 0; nt < 8; nt++) {
                        int j = nt >> 1, p = (nt & 1) * 2;
                        MMA16816(acc[mt][nt], ahf[mt], blf[j][p], blf[j][p+1]);
                    }
#pragma unroll
                for (int mt = 0; mt < 4; mt++)
#pragma unroll
                    for (int nt = 0; nt < 8; nt++) {
                        int j = nt >> 1, p = (nt & 1) * 2;
                        MMA16816(acc[mt][nt], alf[mt], bhf[j][p], bhf[j][p+1]);
                    }
            }
        }
        __syncthreads();
        if (step + 2 < nsteps) issue(step + 2, step & 1);
    }

    // ------------------------------ epilogues ---------------------------------
    if (out_mode == 3) {
#pragma unroll
        for (int mt = 0; mt < 4; mt++) {
            int r0 = m0 + mbase + mt * 16 + (lane >> 2);
            float ps0 = 0.f, ps1 = 0.f;
#pragma unroll
            for (int nt = 0; nt < 8; nt++) {
                ps0 += 1.0f / (1.0f + __expf(-acc[mt][nt][0] * S2));
                ps0 += 1.0f / (1.0f + __expf(-acc[mt][nt][1] * S2));
                ps1 += 1.0f / (1.0f + __expf(-acc[mt][nt][2] * S2));
                ps1 += 1.0f / (1.0f + __expf(-acc[mt][nt][3] * S2));
            }
            ps0 += __shfl_xor_sync(0xffffffffu, ps0, 1, 4);
            ps0 += __shfl_xor_sync(0xffffffffu, ps0, 2, 4);
            ps1 += __shfl_xor_sync(0xffffffffu, ps1, 1, 4);
            ps1 += __shfl_xor_sync(0xffffffffu, ps1, 2, 4);
            if ((lane & 3) == 0) {
                atomicAdd(&gout[zb * 512 + r0], ps0);
                atomicAdd(&gout[zb * 512 + r0 + 8], ps1);
            }
        }
        return;
    }

#pragma unroll
    for (int mt = 0; mt < 4; mt++) {
        int r0 = m0 + mbase + mt * 16 + (lane >> 2);
        float g0 = 1.f, g1 = 1.f;
        if (out_mode == 2) {
            g0 = 1.0f + grow[r0] * (1.0f/512.0f);
            g1 = 1.0f + grow[r0 + 8] * (1.0f/512.0f);
        }
#pragma unroll
        for (int nt = 0; nt < 8; nt++) {
            int c = n0 + nbase + nt * 8 + 2 * (lane & 3);
            float b0 = 0.f, b1 = 0.f;
            if (bias) { b0 = bias[c]; b1 = bias[c + 1]; }
            float v00 = acc[mt][nt][0] * g0 + b0, v01 = acc[mt][nt][1] * g0 + b1;
            float v10 = acc[mt][nt][2] * g1 + b0, v11 = acc[mt][nt][3] * g1 + b1;
            if (out_mode == 1) {
                *(uint32_t*)&Cbf[(long)r0 * N + c]       = packbf(v00, v01);
                *(uint32_t*)&Cbf[(long)(r0 + 8) * N + c] = packbf(v10, v11);
            } else {
                float* Cc = C + zb * sC;
                float2 w0; w0.x = v00; w0.y = v01;
                *(float2*)&Cc[(long)r0 * N + c] = w0;
                float2 w1; w1.x = v10; w1.y = v11;
                *(float2*)&Cc[(long)(r0 + 8) * N + c] = w1;
            }
        }
    }
}

// ---------------- weight transpose + split (fused 6 weights) ------------------
__device__ __forceinline__ void wt_split_body(
    const float* __restrict__ W, __nv_bfloat16* __restrict__ Th, __nv_bfloat16* __restrict__ Tl,
    float (*t)[65])
{
    int n0 = blockIdx.x * 64, k0 = blockIdx.y * 64;
    int tid = threadIdx.x;
#pragma unroll
    for (int it = 0; it < 4; it++) {
        int row = (tid >> 4) + it * 16;
        int c4 = (tid & 15) * 4;
        float4 v = *(const float4*)&W[(long)(k0 + row) * D_ + n0 + c4];
        t[row][c4+0] = v.x; t[row][c4+1] = v.y; t[row][c4+2] = v.z; t[row][c4+3] = v.w;
    }
    __syncthreads();
    int n = tid >> 2, kc = (tid & 3) * 16;
    uint32_t hb[8], lb[8];
#pragma unroll
    for (int j = 0; j < 16; j += 2) {
        float f0 = t[kc + j][n], f1 = t[kc + j + 1][n];
        uint32_t h = packbf(f0, f1);
        hb[j >> 1] = h;
        lb[j >> 1] = packbf(f0 - bflo(h), f1 - bfhi(h));
    }
    long obase = (long)(n0 + n) * D_ + k0 + kc;
    *(uint4*)&Th[obase]     = make_uint4(hb[0], hb[1], hb[2], hb[3]);
    *(uint4*)&Th[obase + 8] = make_uint4(hb[4], hb[5], hb[6], hb[7]);
    *(uint4*)&Tl[obase]     = make_uint4(lb[0], lb[1], lb[2], lb[3]);
    *(uint4*)&Tl[obase + 8] = make_uint4(lb[4], lb[5], lb[6], lb[7]);
}

__global__ __launch_bounds__(256) void wt_split6_kernel(
    const float* __restrict__ Wq, const float* __restrict__ Wk, const float* __restrict__ Wv,
    const float* __restrict__ Wiq, const float* __restrict__ Wik, const float* __restrict__ Wo,
    __nv_bfloat16* __restrict__ wqkvh, __nv_bfloat16* __restrict__ wqkvl,
    __nv_bfloat16* __restrict__ wiqh, __nv_bfloat16* __restrict__ wiql,
    __nv_bfloat16* __restrict__ wikh, __nv_bfloat16* __restrict__ wikl,
    __nv_bfloat16* __restrict__ woh, __nv_bfloat16* __restrict__ wol)
{
    __shared__ float t[64][65];
    const float* W;
    __nv_bfloat16 *Th, *Tl;
    switch (blockIdx.z) {
        case 0: W = Wq;  Th = wqkvh;             Tl = wqkvl;             break;
        case 1: W = Wk;  Th = wqkvh + 1024*1024; Tl = wqkvl + 1024*1024; break;
        case 2: W = Wv;  Th = wqkvh + 2048*1024; Tl = wqkvl + 2048*1024; break;
        case 3: W = Wiq; Th = wiqh;              Tl = wiql;              break;
        case 4: W = Wik; Th = wikh;              Tl = wikl;              break;
        default: W = Wo; Th = woh;               Tl = wol;               break;
    }
    wt_split_body(W, Th, Tl, t);
}

// ---------------- bias concat (bq|bk|bv) --------------------------------------
__global__ void bias3_kernel(const float* __restrict__ a, const float* __restrict__ b,
                             const float* __restrict__ c, float* __restrict__ o)
{
    int i = blockIdx.x * 256 + threadIdx.x;
    if (i < 1024)       o[i] = a[i];
    else if (i < 2048)  o[i] = b[i - 1024];
    else if (i < 3072)  o[i] = c[i - 2048];
}

// ---------------- activation split ---------------------------------------------
__global__ __launch_bounds__(256) void split_kernel(
    const float* __restrict__ src, __nv_bfloat16* __restrict__ h,
    __nv_bfloat16* __restrict__ l, int n4)
{
    int i = blockIdx.x * 256 + threadIdx.x;
    if (i >= n4) return;
    float4 f = ((const float4*)src)[i];
    uint32_t h0 = packbf(f.x, f.y), h1 = packbf(f.z, f.w);
    ((uint32_t*)h)[i*2+0] = h0;
    ((uint32_t*)h)[i*2+1] = h1;
    ((uint32_t*)l)[i*2+0] = packbf(f.x - bflo(h0), f.y - bfhi(h0));
    ((uint32_t*)l)[i*2+1] = packbf(f.z - bflo(h1), f.w - bfhi(h1));
}

// ------- RMS-norm (q,k) + split to bf16 hi/lo, scatter into [GH, SEQ, HD] ----
__global__ __launch_bounds__(256) void rms_scatter_kernel(
    const float* __restrict__ qkv,
    const float* __restrict__ qw, const float* __restrict__ kw,
    __nv_bfloat16* __restrict__ qh, __nv_bfloat16* __restrict__ ql,
    __nv_bfloat16* __restrict__ kh, __nv_bfloat16* __restrict__ kl,
    __nv_bfloat16* __restrict__ vh, __nv_bfloat16* __restrict__ vl)
{
    int wid  = (blockIdx.x * 256 + threadIdx.x) >> 5;
    int lane = threadIdx.x & 31;
    int h  = wid & 15;
    int bn = wid >> 4;
    int b  = bn >> 9;
    long ibase = (long)bn * D3 + h * HD_;
    int g = b >> 2, inst = b & 3;
    int n = bn & 511;
    long obase = (((long)(g*16 + h)) * SEQ + inst*512 + n) * HD_;

    auto emit = [&](float v, __nv_bfloat16* ph, __nv_bfloat16* pl, long off) {
        __nv_bfloat16 hb = __float2bfloat16(v);
        ph[off] = hb;
        pl[off] = __float2bfloat16(v - __bfloat162float(hb));
    };
    {
        float v0 = qkv[ibase + lane], v1 = qkv[ibase + lane + 32];
        float ss = v0*v0 + v1*v1;
#pragma unroll
        for (int off = 16; off; off >>= 1) ss += __shfl_xor_sync(0xffffffffu, ss, off);
        float sc = rsqrtf(ss * (1.0f/64.0f) + 1e-6f) * SCALE;
        emit(v0 * sc * qw[lane],      qh, ql, obase + lane);
        emit(v1 * sc * qw[lane + 32], qh, ql, obase + lane + 32);
    }
    {
        float v0 = qkv[ibase + 1024 + lane], v1 = qkv[ibase + 1024 + lane + 32];
        float ss = v0*v0 + v1*v1;
#pragma unroll
        for (int off = 16; off; off >>= 1) ss += __shfl_xor_sync(0xffffffffu, ss, off);
        float sc = rsqrtf(ss * (1.0f/64.0f) + 1e-6f);
        emit(v0 * sc * kw[lane],      kh, kl, obase + lane);
        emit(v1 * sc * kw[lane + 32], kh, kl, obase + lane + 32);
    }
    emit(qkv[ibase + 2048 + lane],      vh, vl, obase + lane);
    emit(qkv[ibase + 2048 + lane + 32], vh, vl, obase + lane + 32);
}

// ---------------- flash attention via mma.sync (split-bf16 3-pass) -----------
#define FL_SMEM (2*65536 + 32768)
__global__ __launch_bounds__(256, 1)
void flash_mma_kernel(const __nv_bfloat16* __restrict__ Qh_, const __nv_bfloat16* __restrict__ Ql_,
                      const __nv_bfloat16* __restrict__ Kh_, const __nv_bfloat16* __restrict__ Kl_,
                      const __nv_bfloat16* __restrict__ Vh_, const __nv_bfloat16* __restrict__ Vl_,
                      __nv_bfloat16* __restrict__ Oh, __nv_bfloat16* __restrict__ Ol)
{
    extern __shared__ char smem[];
    uint32_t sb = smem_u32(smem);
    int tid = threadIdx.x, wid = tid >> 5, lane = tid & 31;
    int qt = blockIdx.x, gh = blockIdx.y;
    long ghoff = (long)gh * SEQ * HD_;
    const __nv_bfloat16* Qh = Qh_ + ghoff + (long)qt * 128 * HD_;
    const __nv_bfloat16* Ql = Ql_ + ghoff + (long)qt * 128 * HD_;
    const __nv_bfloat16* Kh = Kh_ + ghoff;
    const __nv_bfloat16* Kl = Kl_ + ghoff;
    const __nv_bfloat16* Vh = Vh_ + ghoff;
    const __nv_bfloat16* Vl = Vl_ + ghoff;

    const uint32_t QOFF = 131072;

    {
#pragma unroll
        for (int i = 0; i < 8; i++) {
            int c = i * 256 + tid;
            int arr = c >> 10, w = c & 1023, row = w >> 3, ch = w & 7;
            const __nv_bfloat16* src = (arr ? Ql : Qh) + (long)row * 64 + ch * 8;
            uint32_t dst = sb + QOFF + arr * 16384 + row * 128 + ((ch ^ (row & 7)) << 4);
            CP_ASYNC16(dst, src);
        }
        CP_COMMIT();
    }

    auto issueKV = [&](int it, int stage) {
        uint32_t stb = sb + stage * 65536;
#pragma unroll
        for (int i = 0; i < 16; i++) {
            int c = i * 256 + tid;
            int arr = c >> 10, w = c & 1023, row = w >> 3, ch = w & 7;
            const __nv_bfloat16* src;
            if      (arr == 0) src = Kh;
            else if (arr == 1) src = Kl;
            else if (arr == 2) src = Vh;
            else               src = Vl;
            src += (long)(it * 128 + row) * 64 + ch * 8;
            uint32_t dst = stb + arr * 16384 + row * 128 + ((ch ^ (row & 7)) << 4);
            CP_ASYNC16(dst, src);
        }
        CP_COMMIT();
    };

    issueKV(0, 0);
    issueKV(1, 1);
    CP_WAIT(1);
    __syncthreads();

    uint32_t qhf[4][4], qlf[4][4];
    {
        int arow = lane & 15;
#pragma unroll
        for (int kt = 0; kt < 4; kt++) {
            int row = wid * 16 + arow;
            int ach = 2 * kt + (lane >> 4);
            uint32_t ad = sb + QOFF + row * 128 + ((ach ^ (row & 7)) << 4);
            LDSM4(qhf[kt], ad);
            LDSM4(qlf[kt], ad + 16384);
        }
    }

    float o[8][4];
#pragma unroll
    for (int nt = 0; nt < 8; nt++)
#pragma unroll
        for (int e = 0; e < 4; e++) o[nt][e] = 0.f;
    float m0 = -1e30f, m1 = -1e30f, lp0 = 0.f, lp1 = 0.f;

    for (int it = 0; it < 16; it++) {
        if (it > 0) {
            if (it < 15) { CP_WAIT(1); } else { CP_WAIT(0); }
            __syncthreads();
        }
        uint32_t stb = sb + (it & 1) * 65536;

        float s[16][4];
#pragma unroll
        for (int t = 0; t < 16; t++)
#pragma unroll
            for (int e = 0; e < 4; e++) s[t][e] = 0.f;

        int brow = (lane & 7) + ((lane >> 4) & 1) * 8;
#pragma unroll
        for (int kt = 0; kt < 4; kt++) {
            int bch = 2 * kt + ((lane >> 3) & 1);
#pragma unroll
            for (int jp = 0; jp < 4; jp++) {
                uint32_t khf[2][4], klf[2][4];
#pragma unroll
                for (int j = 0; j < 2; j++) {
                    int row = (2 * jp + j) * 16 + brow;
                    uint32_t bd = stb + row * 128 + ((bch ^ (row & 7)) << 4);
                    LDSM4(khf[j], bd);
                    LDSM4(klf[j], bd + 16384);
                }
                int t0 = 4 * jp;
                MMA16816(s[t0+0], qhf[kt], khf[0][0], khf[0][1]);
                MMA16816(s[t0+1], qhf[kt], khf[0][2], khf[0][3]);
                MMA16816(s[t0+2], qhf[kt], khf[1][0], khf[1][1]);
                MMA16816(s[t0+3], qhf[kt], khf[1][2], khf[1][3]);
                MMA16816(s[t0+0], qhf[kt], klf[0][0], klf[0][1]);
                MMA16816(s[t0+1], qhf[kt], klf[0][2], klf[0][3]);
                MMA16816(s[t0+2], qhf[kt], klf[1][0], klf[1][1]);
                MMA16816(s[t0+3], qhf[kt], klf[1][2], klf[1][3]);
                MMA16816(s[t0+0], qlf[kt], khf[0][0], khf[0][1]);
                MMA16816(s[t0+1], qlf[kt], khf[0][2], khf[0][3]);
                MMA16816(s[t0+2], qlf[kt], khf[1][0], khf[1][1]);
                MMA16816(s[t0+3], qlf[kt], khf[1][2], khf[1][3]);
            }
        }

        float t0 = -1e30f, t1 = -1e30f;
#pragma unroll
        for (int t = 0; t < 16; t++) {
            t0 = fmaxf(t0, fmaxf(s[t][0], s[t][1]));
            t1 = fmaxf(t1, fmaxf(s[t][2], s[t][3]));
        }
        t0 = fmaxf(t0, __shfl_xor_sync(0xffffffffu, t0, 1, 4));
        t0 = fmaxf(t0, __shfl_xor_sync(0xffffffffu, t0, 2, 4));
        t1 = fmaxf(t1, __shfl_xor_sync(0xffffffffu, t1, 1, 4));
        t1 = fmaxf(t1, __shfl_xor_sync(0xffffffffu, t1, 2, 4));
        float mn0 = fmaxf(m0, t0), mn1 = fmaxf(m1, t1);
        float c0 = __expf(m0 - mn0), c1 = __expf(m1 - mn1);
        m0 = mn0; m1 = mn1;
        lp0 *= c0; lp1 *= c1;
#pragma unroll
        for (int nt = 0; nt < 8; nt++) {
            o[nt][0] *= c0; o[nt][1] *= c0;
            o[nt][2] *= c1; o[nt][3] *= c1;
        }
#pragma unroll
        for (int t = 0; t < 16; t++) {
            s[t][0] = __expf(s[t][0] - m0);
            s[t][1] = __expf(s[t][1] - m0);
            s[t][2] = __expf(s[t][2] - m1);
            s[t][3] = __expf(s[t][3] - m1);
            lp0 += s[t][0] + s[t][1];
            lp1 += s[t][2] + s[t][3];
        }

        int vrow = lane & 15;
#pragma unroll
        for (int kt = 0; kt < 8; kt++) {
            uint32_t pha[4], pla[4];
#pragma unroll
            for (int q = 0; q < 2; q++) {
                float a0 = s[2*kt + q][0], a1 = s[2*kt + q][1];
                float a2 = s[2*kt + q][2], a3 = s[2*kt + q][3];
                uint32_t h0 = packbf(a0, a1);
                uint32_t h1 = packbf(a2, a3);
                pha[2*q]   = h0;
                pha[2*q+1] = h1;
                pla[2*q]   = packbf(a0 - bflo(h0), a1 - bfhi(h0));
                pla[2*q+1] = packbf(a2 - bflo(h1), a3 - bfhi(h1));
            }
            int row = kt * 16 + vrow;
#pragma unroll
            for (int np = 0; np < 2; np++) {
                uint32_t vhf[2][4], vlf[2][4];
#pragma unroll
                for (int j = 0; j < 2; j++) {
                    int ch = 2 * (2 * np + j) + (lane >> 4);
                    uint32_t vd = stb + 32768 + row * 128 + ((ch ^ (row & 7)) << 4);
                    LDSM4T(vhf[j], vd);
                    LDSM4T(vlf[j], vd + 16384);
                }
                int ob = 4 * np;
                MMA16816(o[ob+0], pha, vhf[0][0], vhf[0][1]);
                MMA16816(o[ob+1], pha, vhf[0][2], vhf[0][3]);
                MMA16816(o[ob+2], pha, vhf[1][0], vhf[1][1]);
                MMA16816(o[ob+3], pha, vhf[1][2], vhf[1][3]);
                MMA16816(o[ob+0], pha, vlf[0][0], vlf[0][1]);
                MMA16816(o[ob+1], pha, vlf[0][2], vlf[0][3]);
                MMA16816(o[ob+2], pha, vlf[1][0], vlf[1][1]);
                MMA16816(o[ob+3], pha, vlf[1][2], vlf[1][3]);
                MMA16816(o[ob+0], pla, vhf[0][0], vhf[0][1]);
                MMA16816(o[ob+1], pla, vhf[0][2], vhf[0][3]);
                MMA16816(o[ob+2], pla, vhf[1][0], vhf[1][1]);
                MMA16816(o[ob+3], pla, vhf[1][2], vhf[1][3]);
            }
        }

        __syncthreads();
        if (it + 2 < 16) issueKV(it + 2, it & 1);
    }

    lp0 += __shfl_xor_sync(0xffffffffu, lp0, 1, 4);
    lp0 += __shfl_xor_sync(0xffffffffu, lp0, 2, 4);
    lp1 += __shfl_xor_sync(0xffffffffu, lp1, 1, 4);
    lp1 += __shfl_xor_sync(0xffffffffu, lp1, 2, 4);
    float inv0 = 1.0f / lp0, inv1 = 1.0f / lp1;

    int g = gh >> 4, h = gh & 15;
#pragma unroll
    for (int e = 0; e < 2; e++) {
        int r = qt * 128 + wid * 16 + (lane >> 2) + 8 * e;
        int inst = r >> 9, n = r & 511;
        int b = g * 4 + inst;
        float inv = e ? inv1 : inv0;
        long base = ((long)(b * 512 + n)) * D_ + h * HD_;
#pragma unroll
        for (int nt = 0; nt < 8; nt++) {
            float v0 = o[nt][2*e] * inv, v1 = o[nt][2*e+1] * inv;
            uint32_t hp = packbf(v0, v1);
            uint32_t lp = packbf(v0 - bflo(hp), v1 - bfhi(hp));
            long idx = base + nt * 8 + 2 * (lane & 3);
            *(uint32_t*)&Oh[idx] = hp;
            *(uint32_t*)&Ol[idx] = lp;
        }
    }
}

// ---------------- instance feature -> bf16 hi/lo ------------------------------
__global__ __launch_bounds__(256) void feat_kernel(
    const float* __restrict__ mask, const float* __restrict__ embed,
    __nv_bfloat16* __restrict__ fh, __nv_bfloat16* __restrict__ fl)
{
    int row = blockIdx.x;
    float m0 = mask[row*4+0], m1 = mask[row*4+1];
    float m2 = mask[row*4+2], m3 = mask[row*4+3];
    for (int c = threadIdx.x * 2; c < D_; c += 512) {
        float f0 = m0*embed[c]   + m1*embed[D_ + c]   + m2*embed[2*D_ + c]   + m3*embed[3*D_ + c];
        float f1 = m0*embed[c+1] + m1*embed[D_ + c+1] + m2*embed[2*D_ + c+1] + m3*embed[3*D_ + c+1];
        uint32_t h = packbf(f0, f1);
        *(uint32_t*)&fh[(long)row*D_ + c] = h;
        *(uint32_t*)&fl[(long)row*D_ + c] = packbf(f0 - bflo(h), f1 - bfhi(h));
    }
}

__global__ void zero_kernel(float* __restrict__ p, int n)
{
    int i = blockIdx.x * blockDim.x + threadIdx.x;
    if (i < n) p[i] = 0.f;
}

// ------------------------------- launch --------------------------------------
extern "C" void kernel_launch(void* const* d_in, const int* in_sizes, int n_in,
                              void* d_out, int out_size)
{
    const float* x     = (const float*)d_in[0];
    const float* mask  = (const float*)d_in[1];
    const float* Wq    = (const float*)d_in[2];
    const float* bq    = (const float*)d_in[3];
    const float* Wk    = (const float*)d_in[4];
    const float* bk    = (const float*)d_in[5];
    const float* Wv    = (const float*)d_in[6];
    const float* bv    = (const float*)d_in[7];
    const float* Wo    = (const float*)d_in[8];
    const float* bo    = (const float*)d_in[9];
    const float* Wiq   = (const float*)d_in[10];
    const float* biq   = (const float*)d_in[11];
    const float* Wik   = (const float*)d_in[12];
    const float* bik   = (const float*)d_in[13];
    const float* embed = (const float*)d_in[14];
    const float* qw    = (const float*)d_in[15];
    const float* kw    = (const float*)d_in[16];
    float* out = (float*)d_out;

    float *qkvp,*gacc,*bqkv;
    cudaGetSymbolAddress((void**)&qkvp, g_qkvp);
    cudaGetSymbolAddress((void**)&gacc, g_gacc);
    cudaGetSymbolAddress((void**)&bqkv, g_bqkv);

    __nv_bfloat16 *qhg,*qlg,*khg,*klg,*vhg,*vlg;
    cudaGetSymbolAddress((void**)&qhg, g_qhg);   cudaGetSymbolAddress((void**)&qlg, g_qlg);
    cudaGetSymbolAddress((void**)&khg, g_khg);   cudaGetSymbolAddress((void**)&klg, g_klg);
    cudaGetSymbolAddress((void**)&vhg, g_vhg);   cudaGetSymbolAddress((void**)&vlg, g_vlg);

    __nv_bfloat16 *wqkvh,*wqkvl,*wiqh,*wiql,*wikh,*wikl,*woh,*wol;
    __nv_bfloat16 *xh,*xl,*ah,*al,*fh,*fl,*iqh,*ikh;
    cudaGetSymbolAddress((void**)&wqkvh, g_wqkvh); cudaGetSymbolAddress((void**)&wqkvl, g_wqkvl);
    cudaGetSymbolAddress((void**)&wiqh, g_wiqh);   cudaGetSymbolAddress((void**)&wiql, g_wiql);
    cudaGetSymbolAddress((void**)&wikh, g_wikh);   cudaGetSymbolAddress((void**)&wikl, g_wikl);
    cudaGetSymbolAddress((void**)&woh, g_woh);     cudaGetSymbolAddress((void**)&wol, g_wol);
    cudaGetSymbolAddress((void**)&xh, g_xh);       cudaGetSymbolAddress((void**)&xl, g_xl);
    cudaGetSymbolAddress((void**)&ah, g_ah);       cudaGetSymbolAddress((void**)&al, g_al);
    cudaGetSymbolAddress((void**)&fh, g_fh);       cudaGetSymbolAddress((void**)&fl, g_fl);
    cudaGetSymbolAddress((void**)&iqh, g_iqh);     cudaGetSymbolAddress((void**)&ikh, g_ikh);

    cudaFuncSetAttribute((const void*)mma_gemm_kernel,
                         cudaFuncAttributeMaxDynamicSharedMemorySize, TC_SMEM_3P);
    cudaFuncSetAttribute((const void*)flash_mma_kernel,
                         cudaFuncAttributeMaxDynamicSharedMemorySize, FL_SMEM);

    const int N4 = MROWS * D_ / 4;
    const int SPLIT_BLOCKS = (N4 + 255) / 256;

    // prep
    wt_split6_kernel<<<dim3(16, 16, 6), 256>>>(Wq, Wk, Wv, Wiq, Wik, Wo,
                                               wqkvh, wqkvl, wiqh, wiql, wikh, wikl, woh, wol);
    bias3_kernel<<<12, 256>>>(bq, bk, bv, bqkv);
    split_kernel<<<SPLIT_BLOCKS, 256>>>(x, xh, xl, N4);
    zero_kernel<<<(MROWS+255)/256, 256>>>(gacc, MROWS);
    feat_kernel<<<MROWS, 256>>>(mask, embed, fh, fl);

    // launch #6: fused QKV projection (3-pass, N=3072, CTA 128x256)
    mma_gemm_kernel<<<dim3(D3/256, MROWS/128), 256, TC_SMEM_3P>>>(
        xh, xl, wqkvh, wqkvl, bqkv, qkvp, nullptr, nullptr, nullptr,
        nullptr, nullptr, nullptr, nullptr,
        MROWS, D3, D_, 0, 0, 0, 1, 0);

    // per-head RMS norm + split/scatter; attention (writes ah/al directly)
    rms_scatter_kernel<<<(MROWS*H_)/8, 256>>>(qkvp, qw, kw,
                                              qhg, qlg, khg, klg, vhg, vlg);
    flash_mma_kernel<<<dim3(SEQ/128, GH), 256, FL_SMEM>>>(qhg, qlg, khg, klg, vhg, vlg, ah, al);

    // iq & ik projections fused (z selects operand set)
    mma_gemm_kernel<<<dim3(D_/256, MROWS/128, 2), 256, TC_SMEM_1P>>>(
        ah, nullptr, wiqh, nullptr, biq, nullptr, iqh, nullptr, nullptr,
        fh, wikh, bik, ikh,
        MROWS, D_, D_, 0, 0, 0, 0, 1);

    // gate: per-batch iq @ ik^T with fused sigmoid row-sum (atomics)
    mma_gemm_kernel<<<dim3(2, 4, 8), 256, TC_SMEM_1P>>>(
        iqh, nullptr, ikh, nullptr, nullptr, nullptr, nullptr, nullptr, gacc,
        nullptr, nullptr, nullptr, nullptr,
        512, 512, D_, (long)512*D_, (long)512*D_, 0, 0, 3);

    // gated output projection: out = diag(1+gacc/512) * (attn @ Wo) + bo
    mma_gemm_kernel<<<dim3(D_/256, MROWS/128), 256, TC_SMEM_3P>>>(
        ah, al, woh, wol, bo, out, nullptr, gacc, nullptr,
        nullptr, nullptr, nullptr, nullptr,
        MROWS, D_, D_, 0, 0, 0, 1, 2);
}

// round 9
// speedup vs baseline: 1.0354x; 1.0000x over previous
#include <cuda_runtime.h>
#include <cuda_bf16.h>
#include <math.h>
#include <stdint.h>

// Problem constants
#define B_    8
#define N_    512
#define D_    1024
#define H_    16
#define HD_   64
#define NI_   4
#define G_    2
#define MROWS (B_*N_)      // 4096
#define SEQ   (NI_*N_)     // 2048
#define GH    (G_*H_)      // 32
#define D3    3072
#define SCALE 0.125f
#define S2    0.0078125f   // SCALE / H

// ---------------- scratch (device globals) -----------------------------------
static __device__ float g_gacc[MROWS];
static __device__ float g_bqkv[D3];

#define AELEMS (GH*SEQ*HD_)
static __device__ __align__(256) __nv_bfloat16 g_qhg[AELEMS], g_qlg[AELEMS];
static __device__ __align__(256) __nv_bfloat16 g_khg[AELEMS], g_klg[AELEMS];
static __device__ __align__(256) __nv_bfloat16 g_vhg[AELEMS], g_vlg[AELEMS];

static __device__ __align__(256) __nv_bfloat16 g_wqkvh[D3*D_], g_wqkvl[D3*D_];
static __device__ __align__(256) __nv_bfloat16 g_wiqh[D_*D_], g_wiql[D_*D_];
static __device__ __align__(256) __nv_bfloat16 g_wikh[D_*D_], g_wikl[D_*D_];
static __device__ __align__(256) __nv_bfloat16 g_woh[D_*D_], g_wol[D_*D_];
static __device__ __align__(256) __nv_bfloat16 g_xh[MROWS*D_],  g_xl[MROWS*D_];
static __device__ __align__(256) __nv_bfloat16 g_ah[MROWS*D_],  g_al[MROWS*D_];
static __device__ __align__(256) __nv_bfloat16 g_fh[MROWS*D_],  g_fl[MROWS*D_];
static __device__ __align__(256) __nv_bfloat16 g_iqh[MROWS*D_];
static __device__ __align__(256) __nv_bfloat16 g_ikh[MROWS*D_];

// ---------------- PTX helpers --------------------------------------------------
__device__ __forceinline__ uint32_t smem_u32(const void* p) {
    uint32_t a;
    asm("{ .reg .u64 t; cvta.to.shared.u64 t, %1; cvt.u32.u64 %0, t; }"
        : "=r"(a) : "l"(p));
    return a;
}

#define LDSM4(r, addr) \
    asm volatile("ldmatrix.sync.aligned.m8n8.x4.shared.b16 {%0,%1,%2,%3}, [%4];" \
        : "=r"((r)[0]), "=r"((r)[1]), "=r"((r)[2]), "=r"((r)[3]) : "r"(addr))

#define LDSM4T(r, addr) \
    asm volatile("ldmatrix.sync.aligned.m8n8.x4.trans.shared.b16 {%0,%1,%2,%3}, [%4];" \
        : "=r"((r)[0]), "=r"((r)[1]), "=r"((r)[2]), "=r"((r)[3]) : "r"(addr))

#define MMA16816(d, a, bv0, bv1) \
    asm volatile("mma.sync.aligned.m16n8k16.row.col.f32.bf16.bf16.f32 " \
        "{%0,%1,%2,%3}, {%4,%5,%6,%7}, {%8,%9}, {%0,%1,%2,%3};" \
        : "+f"((d)[0]), "+f"((d)[1]), "+f"((d)[2]), "+f"((d)[3]) \
        : "r"((a)[0]), "r"((a)[1]), "r"((a)[2]), "r"((a)[3]), "r"(bv0), "r"(bv1))

#define CP_ASYNC16(dst, src) \
    asm volatile("cp.async.cg.shared.global [%0], [%1], 16;" \
        :: "r"(dst), "l"(__cvta_generic_to_global(src)) : "memory")
#define CP_COMMIT() asm volatile("cp.async.commit_group;" ::: "memory")
#define CP_WAIT(n)  asm volatile("cp.async.wait_group %0;" :: "n"(n) : "memory")

__device__ __forceinline__ uint32_t packbf(float a, float b) {
    uint32_t d;
    asm("cvt.rn.bf16x2.f32 %0, %1, %2;" : "=r"(d) : "f"(b), "f"(a));
    return d;
}
__device__ __forceinline__ float bflo(uint32_t v) { return __uint_as_float(v << 16); }
__device__ __forceinline__ float bfhi(uint32_t v) { return __uint_as_float(v & 0xffff0000u); }

// ---------------- HMMA split-bf16 GEMM: CTA 128x256, warp 64x64 ---------------
// three_pass: 1 -> AhBh + AhBl + AlBh ; 0 -> AhBh only.
// out_mode: 0 fp32 C+bias; 1 bf16-hi Cbf (+bias, z selects operand set);
//           2 fp32 gate-scaled; 3 sigmoid row-sum atomics into gout;
//           4 QKV epilogue: bias + per-head RMS norm (q,k) + split + scatter.
#define TC_SMEM_3P (2*98304)   // 196608
#define TC_SMEM_1P (2*49152)   //  98304
__global__ __launch_bounds__(256, 1)
void mma_gemm_kernel(const __nv_bfloat16* __restrict__ Ahp, const __nv_bfloat16* __restrict__ Alp,
                     const __nv_bfloat16* __restrict__ Bhp, const __nv_bfloat16* __restrict__ Blp,
                     const float* __restrict__ bias, float* __restrict__ C,
                     __nv_bfloat16* __restrict__ Cbf,
                     const float* __restrict__ grow, float* __restrict__ gout,
                     const __nv_bfloat16* __restrict__ Ahp2, const __nv_bfloat16* __restrict__ Bhp2,
                     const float* __restrict__ bias2, __nv_bfloat16* __restrict__ Cbf2,
                     const float* __restrict__ qw, const float* __restrict__ kw,
                     __nv_bfloat16* __restrict__ qh_, __nv_bfloat16* __restrict__ ql_,
                     __nv_bfloat16* __restrict__ kh_, __nv_bfloat16* __restrict__ kl_,
                     __nv_bfloat16* __restrict__ vh_, __nv_bfloat16* __restrict__ vl_,
                     int M, int N, int K, long sA, long sB, long sC,
                     int three_pass, int out_mode)
{
    extern __shared__ char smem[];
    uint32_t sb = smem_u32(smem);
    int tid = threadIdx.x, wid = tid >> 5, lane = tid & 31;
    int m0 = blockIdx.y * 128, n0 = blockIdx.x * 256;
    long zb = blockIdx.z;
    const __nv_bfloat16* Ah = Ahp + zb * sA;
    const __nv_bfloat16* Al = three_pass ? (Alp + zb * sA) : Ahp;
    const __nv_bfloat16* Bh = Bhp + zb * sB;
    const __nv_bfloat16* Bl = three_pass ? (Blp + zb * sB) : Bhp;
    if (out_mode == 1 && blockIdx.z == 1) {
        Ah = Ahp2; Bh = Bhp2; bias = bias2; Cbf = Cbf2;
    }

    const int nsteps = K / 64;
    const uint32_t SS   = three_pass ? 98304 : 49152;
    const uint32_t BOFF = three_pass ? 32768 : 16384;
    const int ncp = three_pass ? 24 : 12;

    auto issue = [&](int step, int stage) {
        uint32_t stb = sb + stage * SS;
        int k0 = step * 64;
#pragma unroll
        for (int i = 0; i < 24; i++) {
            if (i >= ncp) break;
            int c = i * 256 + tid;
            int tile = c >> 10;
            int w = c & 1023;
            int row = w >> 3, ch = w & 7;
            const __nv_bfloat16* src;
            int gr;
            uint32_t tbase;
            if (three_pass) {
                if      (tile == 0) { src = Ah; gr = m0 + row;        tbase = 0; }
                else if (tile == 1) { src = Al; gr = m0 + row;        tbase = 16384; }
                else if (tile == 2) { src = Bh; gr = n0 + row;        tbase = 32768; }
                else if (tile == 3) { src = Bh; gr = n0 + 128 + row;  tbase = 49152; }
                else if (tile == 4) { src = Bl; gr = n0 + row;        tbase = 65536; }
                else                { src = Bl; gr = n0 + 128 + row;  tbase = 81920; }
            } else {
                if      (tile == 0) { src = Ah; gr = m0 + row;        tbase = 0; }
                else if (tile == 1) { src = Bh; gr = n0 + row;        tbase = 16384; }
                else                { src = Bh; gr = n0 + 128 + row;  tbase = 32768; }
            }
            const __nv_bfloat16* gp = src + (long)gr * K + k0 + ch * 8;
            uint32_t dst = stb + tbase + row * 128 + ((ch ^ (row & 7)) << 4);
            CP_ASYNC16(dst, gp);
        }
        CP_COMMIT();
    };

    int mbase = (wid >> 2) * 64;
    int nbase = (wid & 3) * 64;
    int arow = lane & 15;
    int brow = (lane & 7) + ((lane >> 4) & 1) * 8;

    float acc[4][8][4];
#pragma unroll
    for (int mt = 0; mt < 4; mt++)
#pragma unroll
        for (int nt = 0; nt < 8; nt++)
#pragma unroll
            for (int e = 0; e < 4; e++) acc[mt][nt][e] = 0.f;

    issue(0, 0);
    if (nsteps > 1) issue(1, 1);

    for (int step = 0; step < nsteps; step++) {
        if (step + 1 < nsteps) { CP_WAIT(1); } else { CP_WAIT(0); }
        __syncthreads();

        uint32_t stb = sb + (uint32_t)(step & 1) * SS;
#pragma unroll
        for (int k16 = 0; k16 < 4; k16++) {
            uint32_t ahf[4][4], alf[4][4], bhf[4][4], blf[4][4];
            int ach = 2 * k16 + (lane >> 4);
#pragma unroll
            for (int mt = 0; mt < 4; mt++) {
                int row = mbase + mt * 16 + arow;
                uint32_t ad = stb + row * 128 + ((ach ^ (row & 7)) << 4);
                LDSM4(ahf[mt], ad);
                if (three_pass) LDSM4(alf[mt], ad + 16384);
            }
            int bch = 2 * k16 + ((lane >> 3) & 1);
#pragma unroll
            for (int j = 0; j < 4; j++) {
                int row = nbase + j * 16 + brow;
                uint32_t bd = stb + BOFF + row * 128 + ((bch ^ (row & 7)) << 4);
                LDSM4(bhf[j], bd);
                if (three_pass) LDSM4(blf[j], bd + 32768);
            }
#pragma unroll
            for (int mt = 0; mt < 4; mt++)
#pragma unroll
                for (int nt = 0; nt < 8; nt++) {
                    int j = nt >> 1, p = (nt & 1) * 2;
                    MMA16816(acc[mt][nt], ahf[mt], bhf[j][p], bhf[j][p+1]);
                }
            if (three_pass) {
#pragma unroll
                for (int mt = 0; mt < 4; mt++)
#pragma unroll
                    for (int nt = 0; nt < 8; nt++) {
                        int j = nt >> 1, p = (nt & 1) * 2;
                        MMA16816(acc[mt][nt], ahf[mt], blf[j][p], blf[j][p+1]);
                    }
#pragma unroll
                for (int mt = 0; mt < 4; mt++)
#pragma unroll
                    for (int nt = 0; nt < 8; nt++) {
                        int j = nt >> 1, p = (nt & 1) * 2;
                        MMA16816(acc[mt][nt], alf[mt], bhf[j][p], bhf[j][p+1]);
                    }
            }
        }
        __syncthreads();
        if (step + 2 < nsteps) issue(step + 2, step & 1);
    }

    // ------------------------------ epilogues ---------------------------------
    if (out_mode == 4) {
        // fused: bias + per-head RMS norm (q,k only) + bf16 hi/lo split +
        // scatter into grouped [GH, SEQ, HD] layout. warp N-tile (64) == 1 head.
        int c0 = n0 + nbase;             // multiple of 64
        int type = c0 >> 10;             // 0=q 1=k 2=v
        int hh = (c0 & 1023) >> 6;       // head index
        const float* wv = (type == 0) ? qw : kw;
        __nv_bfloat16 *ph, *pl;
        if (type == 0)      { ph = qh_; pl = ql_; }
        else if (type == 1) { ph = kh_; pl = kl_; }
        else                { ph = vh_; pl = vl_; }
#pragma unroll
        for (int mt = 0; mt < 4; mt++) {
            float vals[8][4];
            float ss0 = 0.f, ss1 = 0.f;
            int r0 = m0 + mbase + mt * 16 + (lane >> 2);
#pragma unroll
            for (int nt = 0; nt < 8; nt++) {
                int c = c0 + nt * 8 + 2 * (lane & 3);
                float b0 = bias[c], b1 = bias[c + 1];
                vals[nt][0] = acc[mt][nt][0] + b0;
                vals[nt][1] = acc[mt][nt][1] + b1;
                vals[nt][2] = acc[mt][nt][2] + b0;
                vals[nt][3] = acc[mt][nt][3] + b1;
                ss0 += vals[nt][0]*vals[nt][0] + vals[nt][1]*vals[nt][1];
                ss1 += vals[nt][2]*vals[nt][2] + vals[nt][3]*vals[nt][3];
            }
            ss0 += __shfl_xor_sync(0xffffffffu, ss0, 1, 4);
            ss0 += __shfl_xor_sync(0xffffffffu, ss0, 2, 4);
            ss1 += __shfl_xor_sync(0xffffffffu, ss1, 1, 4);
            ss1 += __shfl_xor_sync(0xffffffffu, ss1, 2, 4);
            float sc0 = 1.f, sc1 = 1.f;
            if (type == 0) {
                sc0 = rsqrtf(ss0 * (1.0f/64.0f) + 1e-6f) * SCALE;
                sc1 = rsqrtf(ss1 * (1.0f/64.0f) + 1e-6f) * SCALE;
            } else if (type == 1) {
                sc0 = rsqrtf(ss0 * (1.0f/64.0f) + 1e-6f);
                sc1 = rsqrtf(ss1 * (1.0f/64.0f) + 1e-6f);
            }
#pragma unroll
            for (int e = 0; e < 2; e++) {
                int r = r0 + 8 * e;
                int b = r >> 9, n = r & 511;
                int g = b >> 2, inst = b & 3;
                long obase = (((long)(g*16 + hh)) * SEQ + inst*512 + n) * HD_;
                float sc = e ? sc1 : sc0;
#pragma unroll
                for (int nt = 0; nt < 8; nt++) {
                    int colh = nt * 8 + 2 * (lane & 3);
                    float wa = (type < 2) ? wv[colh]     : 1.f;
                    float wb = (type < 2) ? wv[colh + 1] : 1.f;
                    float u0 = vals[nt][2*e]   * sc * wa;
                    float u1 = vals[nt][2*e+1] * sc * wb;
                    uint32_t hp = packbf(u0, u1);
                    uint32_t lp = packbf(u0 - bflo(hp), u1 - bfhi(hp));
                    *(uint32_t*)&ph[obase + colh] = hp;
                    *(uint32_t*)&pl[obase + colh] = lp;
                }
            }
        }
        return;
    }

    if (out_mode == 3) {
#pragma unroll
        for (int mt = 0; mt < 4; mt++) {
            int r0 = m0 + mbase + mt * 16 + (lane >> 2);
            float ps0 = 0.f, ps1 = 0.f;
#pragma unroll
            for (int nt = 0; nt < 8; nt++) {
                ps0 += 1.0f / (1.0f + __expf(-acc[mt][nt][0] * S2));
                ps0 += 1.0f / (1.0f + __expf(-acc[mt][nt][1] * S2));
                ps1 += 1.0f / (1.0f + __expf(-acc[mt][nt][2] * S2));
                ps1 += 1.0f / (1.0f + __expf(-acc[mt][nt][3] * S2));
            }
            ps0 += __shfl_xor_sync(0xffffffffu, ps0, 1, 4);
            ps0 += __shfl_xor_sync(0xffffffffu, ps0, 2, 4);
            ps1 += __shfl_xor_sync(0xffffffffu, ps1, 1, 4);
            ps1 += __shfl_xor_sync(0xffffffffu, ps1, 2, 4);
            if ((lane & 3) == 0) {
                atomicAdd(&gout[zb * 512 + r0], ps0);
                atomicAdd(&gout[zb * 512 + r0 + 8], ps1);
            }
        }
        return;
    }

#pragma unroll
    for (int mt = 0; mt < 4; mt++) {
        int r0 = m0 + mbase + mt * 16 + (lane >> 2);
        float g0 = 1.f, g1 = 1.f;
        if (out_mode == 2) {
            g0 = 1.0f + grow[r0] * (1.0f/512.0f);
            g1 = 1.0f + grow[r0 + 8] * (1.0f/512.0f);
        }
#pragma unroll
        for (int nt = 0; nt < 8; nt++) {
            int c = n0 + nbase + nt * 8 + 2 * (lane & 3);
            float b0 = 0.f, b1 = 0.f;
            if (bias) { b0 = bias[c]; b1 = bias[c + 1]; }
            float v00 = acc[mt][nt][0] * g0 + b0, v01 = acc[mt][nt][1] * g0 + b1;
            float v10 = acc[mt][nt][2] * g1 + b0, v11 = acc[mt][nt][3] * g1 + b1;
            if (out_mode == 1) {
                *(uint32_t*)&Cbf[(long)r0 * N + c]       = packbf(v00, v01);
                *(uint32_t*)&Cbf[(long)(r0 + 8) * N + c] = packbf(v10, v11);
            } else {
                float* Cc = C + zb * sC;
                float2 w0; w0.x = v00; w0.y = v01;
                *(float2*)&Cc[(long)r0 * N + c] = w0;
                float2 w1; w1.x = v10; w1.y = v11;
                *(float2*)&Cc[(long)(r0 + 8) * N + c] = w1;
            }
        }
    }
}

// ---------------- weight transpose + split (fused 6 weights) ------------------
__device__ __forceinline__ void wt_split_body(
    const float* __restrict__ W, __nv_bfloat16* __restrict__ Th, __nv_bfloat16* __restrict__ Tl,
    float (*t)[65])
{
    int n0 = blockIdx.x * 64, k0 = blockIdx.y * 64;
    int tid = threadIdx.x;
#pragma unroll
    for (int it = 0; it < 4; it++) {
        int row = (tid >> 4) + it * 16;
        int c4 = (tid & 15) * 4;
        float4 v = *(const float4*)&W[(long)(k0 + row) * D_ + n0 + c4];
        t[row][c4+0] = v.x; t[row][c4+1] = v.y; t[row][c4+2] = v.z; t[row][c4+3] = v.w;
    }
    __syncthreads();
    int n = tid >> 2, kc = (tid & 3) * 16;
    uint32_t hb[8], lb[8];
#pragma unroll
    for (int j = 0; j < 16; j += 2) {
        float f0 = t[kc + j][n], f1 = t[kc + j + 1][n];
        uint32_t h = packbf(f0, f1);
        hb[j >> 1] = h;
        lb[j >> 1] = packbf(f0 - bflo(h), f1 - bfhi(h));
    }
    long obase = (long)(n0 + n) * D_ + k0 + kc;
    *(uint4*)&Th[obase]     = make_uint4(hb[0], hb[1], hb[2], hb[3]);
    *(uint4*)&Th[obase + 8] = make_uint4(hb[4], hb[5], hb[6], hb[7]);
    *(uint4*)&Tl[obase]     = make_uint4(lb[0], lb[1], lb[2], lb[3]);
    *(uint4*)&Tl[obase + 8] = make_uint4(lb[4], lb[5], lb[6], lb[7]);
}

__global__ __launch_bounds__(256) void wt_split6_kernel(
    const float* __restrict__ Wq, const float* __restrict__ Wk, const float* __restrict__ Wv,
    const float* __restrict__ Wiq, const float* __restrict__ Wik, const float* __restrict__ Wo,
    __nv_bfloat16* __restrict__ wqkvh, __nv_bfloat16* __restrict__ wqkvl,
    __nv_bfloat16* __restrict__ wiqh, __nv_bfloat16* __restrict__ wiql,
    __nv_bfloat16* __restrict__ wikh, __nv_bfloat16* __restrict__ wikl,
    __nv_bfloat16* __restrict__ woh, __nv_bfloat16* __restrict__ wol)
{
    __shared__ float t[64][65];
    const float* W;
    __nv_bfloat16 *Th, *Tl;
    switch (blockIdx.z) {
        case 0: W = Wq;  Th = wqkvh;             Tl = wqkvl;             break;
        case 1: W = Wk;  Th = wqkvh + 1024*1024; Tl = wqkvl + 1024*1024; break;
        case 2: W = Wv;  Th = wqkvh + 2048*1024; Tl = wqkvl + 2048*1024; break;
        case 3: W = Wiq; Th = wiqh;              Tl = wiql;              break;
        case 4: W = Wik; Th = wikh;              Tl = wikl;              break;
        default: W = Wo; Th = woh;               Tl = wol;               break;
    }
    wt_split_body(W, Th, Tl, t);
}

// ---------------- bias concat (bq|bk|bv) --------------------------------------
__global__ void bias3_kernel(const float* __restrict__ a, const float* __restrict__ b,
                             const float* __restrict__ c, float* __restrict__ o)
{
    int i = blockIdx.x * 256 + threadIdx.x;
    if (i < 1024)       o[i] = a[i];
    else if (i < 2048)  o[i] = b[i - 1024];
    else if (i < 3072)  o[i] = c[i - 2048];
}

// ---------------- activation split ---------------------------------------------
__global__ __launch_bounds__(256) void split_kernel(
    const float* __restrict__ src, __nv_bfloat16* __restrict__ h,
    __nv_bfloat16* __restrict__ l, int n4)
{
    int i = blockIdx.x * 256 + threadIdx.x;
    if (i >= n4) return;
    float4 f = ((const float4*)src)[i];
    uint32_t h0 = packbf(f.x, f.y), h1 = packbf(f.z, f.w);
    ((uint32_t*)h)[i*2+0] = h0;
    ((uint32_t*)h)[i*2+1] = h1;
    ((uint32_t*)l)[i*2+0] = packbf(f.x - bflo(h0), f.y - bfhi(h0));
    ((uint32_t*)l)[i*2+1] = packbf(f.z - bflo(h1), f.w - bfhi(h1));
}

// ---------------- flash attention via mma.sync (split-bf16 3-pass) -----------
#define FL_SMEM (2*65536 + 32768)
__global__ __launch_bounds__(256, 1)
void flash_mma_kernel(const __nv_bfloat16* __restrict__ Qh_, const __nv_bfloat16* __restrict__ Ql_,
                      const __nv_bfloat16* __restrict__ Kh_, const __nv_bfloat16* __restrict__ Kl_,
                      const __nv_bfloat16* __restrict__ Vh_, const __nv_bfloat16* __restrict__ Vl_,
                      __nv_bfloat16* __restrict__ Oh, __nv_bfloat16* __restrict__ Ol)
{
    extern __shared__ char smem[];
    uint32_t sb = smem_u32(smem);
    int tid = threadIdx.x, wid = tid >> 5, lane = tid & 31;
    int qt = blockIdx.x, gh = blockIdx.y;
    long ghoff = (long)gh * SEQ * HD_;
    const __nv_bfloat16* Qh = Qh_ + ghoff + (long)qt * 128 * HD_;
    const __nv_bfloat16* Ql = Ql_ + ghoff + (long)qt * 128 * HD_;
    const __nv_bfloat16* Kh = Kh_ + ghoff;
    const __nv_bfloat16* Kl = Kl_ + ghoff;
    const __nv_bfloat16* Vh = Vh_ + ghoff;
    const __nv_bfloat16* Vl = Vl_ + ghoff;

    const uint32_t QOFF = 131072;

    {
#pragma unroll
        for (int i = 0; i < 8; i++) {
            int c = i * 256 + tid;
            int arr = c >> 10, w = c & 1023, row = w >> 3, ch = w & 7;
            const __nv_bfloat16* src = (arr ? Ql : Qh) + (long)row * 64 + ch * 8;
            uint32_t dst = sb + QOFF + arr * 16384 + row * 128 + ((ch ^ (row & 7)) << 4);
            CP_ASYNC16(dst, src);
        }
        CP_COMMIT();
    }

    auto issueKV = [&](int it, int stage) {
        uint32_t stb = sb + stage * 65536;
#pragma unroll
        for (int i = 0; i < 16; i++) {
            int c = i * 256 + tid;
            int arr = c >> 10, w = c & 1023, row = w >> 3, ch = w & 7;
            const __nv_bfloat16* src;
            if      (arr == 0) src = Kh;
            else if (arr == 1) src = Kl;
            else if (arr == 2) src = Vh;
            else               src = Vl;
            src += (long)(it * 128 + row) * 64 + ch * 8;
            uint32_t dst = stb + arr * 16384 + row * 128 + ((ch ^ (row & 7)) << 4);
            CP_ASYNC16(dst, src);
        }
        CP_COMMIT();
    };

    issueKV(0, 0);
    issueKV(1, 1);
    CP_WAIT(1);
    __syncthreads();

    uint32_t qhf[4][4], qlf[4][4];
    {
        int arow = lane & 15;
#pragma unroll
        for (int kt = 0; kt < 4; kt++) {
            int row = wid * 16 + arow;
            int ach = 2 * kt + (lane >> 4);
            uint32_t ad = sb + QOFF + row * 128 + ((ach ^ (row & 7)) << 4);
            LDSM4(qhf[kt], ad);
            LDSM4(qlf[kt], ad + 16384);
        }
    }

    float o[8][4];
#pragma unroll
    for (int nt = 0; nt < 8; nt++)
#pragma unroll
        for (int e = 0; e < 4; e++) o[nt][e] = 0.f;
    float m0 = -1e30f, m1 = -1e30f, lp0 = 0.f, lp1 = 0.f;

    for (int it = 0; it < 16; it++) {
        if (it > 0) {
            if (it < 15) { CP_WAIT(1); } else { CP_WAIT(0); }
            __syncthreads();
        }
        uint32_t stb = sb + (it & 1) * 65536;

        float s[16][4];
#pragma unroll
        for (int t = 0; t < 16; t++)
#pragma unroll
            for (int e = 0; e < 4; e++) s[t][e] = 0.f;

        int brow = (lane & 7) + ((lane >> 4) & 1) * 8;
#pragma unroll
        for (int kt = 0; kt < 4; kt++) {
            int bch = 2 * kt + ((lane >> 3) & 1);
#pragma unroll
            for (int jp = 0; jp < 4; jp++) {
                uint32_t khf[2][4], klf[2][4];
#pragma unroll
                for (int j = 0; j < 2; j++) {
                    int row = (2 * jp + j) * 16 + brow;
                    uint32_t bd = stb + row * 128 + ((bch ^ (row & 7)) << 4);
                    LDSM4(khf[j], bd);
                    LDSM4(klf[j], bd + 16384);
                }
                int t0 = 4 * jp;
                MMA16816(s[t0+0], qhf[kt], khf[0][0], khf[0][1]);
                MMA16816(s[t0+1], qhf[kt], khf[0][2], khf[0][3]);
                MMA16816(s[t0+2], qhf[kt], khf[1][0], khf[1][1]);
                MMA16816(s[t0+3], qhf[kt], khf[1][2], khf[1][3]);
                MMA16816(s[t0+0], qhf[kt], klf[0][0], klf[0][1]);
                MMA16816(s[t0+1], qhf[kt], klf[0][2], klf[0][3]);
                MMA16816(s[t0+2], qhf[kt], klf[1][0], klf[1][1]);
                MMA16816(s[t0+3], qhf[kt], klf[1][2], klf[1][3]);
                MMA16816(s[t0+0], qlf[kt], khf[0][0], khf[0][1]);
                MMA16816(s[t0+1], qlf[kt], khf[0][2], khf[0][3]);
                MMA16816(s[t0+2], qlf[kt], khf[1][0], khf[1][1]);
                MMA16816(s[t0+3], qlf[kt], khf[1][2], khf[1][3]);
            }
        }

        float t0 = -1e30f, t1 = -1e30f;
#pragma unroll
        for (int t = 0; t < 16; t++) {
            t0 = fmaxf(t0, fmaxf(s[t][0], s[t][1]));
            t1 = fmaxf(t1, fmaxf(s[t][2], s[t][3]));
        }
        t0 = fmaxf(t0, __shfl_xor_sync(0xffffffffu, t0, 1, 4));
        t0 = fmaxf(t0, __shfl_xor_sync(0xffffffffu, t0, 2, 4));
        t1 = fmaxf(t1, __shfl_xor_sync(0xffffffffu, t1, 1, 4));
        t1 = fmaxf(t1, __shfl_xor_sync(0xffffffffu, t1, 2, 4));
        float mn0 = fmaxf(m0, t0), mn1 = fmaxf(m1, t1);
        float c0 = __expf(m0 - mn0), c1 = __expf(m1 - mn1);
        m0 = mn0; m1 = mn1;
        lp0 *= c0; lp1 *= c1;
#pragma unroll
        for (int nt = 0; nt < 8; nt++) {
            o[nt][0] *= c0; o[nt][1] *= c0;
            o[nt][2] *= c1; o[nt][3] *= c1;
        }
#pragma unroll
        for (int t = 0; t < 16; t++) {
            s[t][0] = __expf(s[t][0] - m0);
            s[t][1] = __expf(s[t][1] - m0);
            s[t][2] = __expf(s[t][2] - m1);
            s[t][3] = __expf(s[t][3] - m1);
            lp0 += s[t][0] + s[t][1];
            lp1 += s[t][2] + s[t][3];
        }

        int vrow = lane & 15;
#pragma unroll
        for (int kt = 0; kt < 8; kt++) {
            uint32_t pha[4], pla[4];
#pragma unroll
            for (int q = 0; q < 2; q++) {
                float a0 = s[2*kt + q][0], a1 = s[2*kt + q][1];
                float a2 = s[2*kt + q][2], a3 = s[2*kt + q][3];
                uint32_t h0 = packbf(a0, a1);
                uint32_t h1 = packbf(a2, a3);
                pha[2*q]   = h0;
                pha[2*q+1] = h1;
                pla[2*q]   = packbf(a0 - bflo(h0), a1 - bfhi(h0));
                pla[2*q+1] = packbf(a2 - bflo(h1), a3 - bfhi(h1));
            }
            int row = kt * 16 + vrow;
#pragma unroll
            for (int np = 0; np < 2; np++) {
                uint32_t vhf[2][4], vlf[2][4];
#pragma unroll
                for (int j = 0; j < 2; j++) {
                    int ch = 2 * (2 * np + j) + (lane >> 4);
                    uint32_t vd = stb + 32768 + row * 128 + ((ch ^ (row & 7)) << 4);
                    LDSM4T(vhf[j], vd);
                    LDSM4T(vlf[j], vd + 16384);
                }
                int ob = 4 * np;
                MMA16816(o[ob+0], pha, vhf[0][0], vhf[0][1]);
                MMA16816(o[ob+1], pha, vhf[0][2], vhf[0][3]);
                MMA16816(o[ob+2], pha, vhf[1][0], vhf[1][1]);
                MMA16816(o[ob+3], pha, vhf[1][2], vhf[1][3]);
                MMA16816(o[ob+0], pha, vlf[0][0], vlf[0][1]);
                MMA16816(o[ob+1], pha, vlf[0][2], vlf[0][3]);
                MMA16816(o[ob+2], pha, vlf[1][0], vlf[1][1]);
                MMA16816(o[ob+3], pha, vlf[1][2], vlf[1][3]);
                MMA16816(o[ob+0], pla, vhf[0][0], vhf[0][1]);
                MMA16816(o[ob+1], pla, vhf[0][2], vhf[0][3]);
                MMA16816(o[ob+2], pla, vhf[1][0], vhf[1][1]);
                MMA16816(o[ob+3], pla, vhf[1][2], vhf[1][3]);
            }
        }

        __syncthreads();
        if (it + 2 < 16) issueKV(it + 2, it & 1);
    }

    lp0 += __shfl_xor_sync(0xffffffffu, lp0, 1, 4);
    lp0 += __shfl_xor_sync(0xffffffffu, lp0, 2, 4);
    lp1 += __shfl_xor_sync(0xffffffffu, lp1, 1, 4);
    lp1 += __shfl_xor_sync(0xffffffffu, lp1, 2, 4);
    float inv0 = 1.0f / lp0, inv1 = 1.0f / lp1;

    int g = gh >> 4, h = gh & 15;
#pragma unroll
    for (int e = 0; e < 2; e++) {
        int r = qt * 128 + wid * 16 + (lane >> 2) + 8 * e;
        int inst = r >> 9, n = r & 511;
        int b = g * 4 + inst;
        float inv = e ? inv1 : inv0;
        long base = ((long)(b * 512 + n)) * D_ + h * HD_;
#pragma unroll
        for (int nt = 0; nt < 8; nt++) {
            float v0 = o[nt][2*e] * inv, v1 = o[nt][2*e+1] * inv;
            uint32_t hp = packbf(v0, v1);
            uint32_t lp = packbf(v0 - bflo(hp), v1 - bfhi(hp));
            long idx = base + nt * 8 + 2 * (lane & 3);
            *(uint32_t*)&Oh[idx] = hp;
            *(uint32_t*)&Ol[idx] = lp;
        }
    }
}

// ---------------- instance feature -> bf16 hi/lo ------------------------------
__global__ __launch_bounds__(256) void feat_kernel(
    const float* __restrict__ mask, const float* __restrict__ embed,
    __nv_bfloat16* __restrict__ fh, __nv_bfloat16* __restrict__ fl)
{
    int row = blockIdx.x;
    float m0 = mask[row*4+0], m1 = mask[row*4+1];
    float m2 = mask[row*4+2], m3 = mask[row*4+3];
    for (int c = threadIdx.x * 2; c < D_; c += 512) {
        float f0 = m0*embed[c]   + m1*embed[D_ + c]   + m2*embed[2*D_ + c]   + m3*embed[3*D_ + c];
        float f1 = m0*embed[c+1] + m1*embed[D_ + c+1] + m2*embed[2*D_ + c+1] + m3*embed[3*D_ + c+1];
        uint32_t h = packbf(f0, f1);
        *(uint32_t*)&fh[(long)row*D_ + c] = h;
        *(uint32_t*)&fl[(long)row*D_ + c] = packbf(f0 - bflo(h), f1 - bfhi(h));
    }
}

__global__ void zero_kernel(float* __restrict__ p, int n)
{
    int i = blockIdx.x * blockDim.x + threadIdx.x;
    if (i < n) p[i] = 0.f;
}

// ------------------------------- launch --------------------------------------
extern "C" void kernel_launch(void* const* d_in, const int* in_sizes, int n_in,
                              void* d_out, int out_size)
{
    const float* x     = (const float*)d_in[0];
    const float* mask  = (const float*)d_in[1];
    const float* Wq    = (const float*)d_in[2];
    const float* bq    = (const float*)d_in[3];
    const float* Wk    = (const float*)d_in[4];
    const float* bk    = (const float*)d_in[5];
    const float* Wv    = (const float*)d_in[6];
    const float* bv    = (const float*)d_in[7];
    const float* Wo    = (const float*)d_in[8];
    const float* bo    = (const float*)d_in[9];
    const float* Wiq   = (const float*)d_in[10];
    const float* biq   = (const float*)d_in[11];
    const float* Wik   = (const float*)d_in[12];
    const float* bik   = (const float*)d_in[13];
    const float* embed = (const float*)d_in[14];
    const float* qw    = (const float*)d_in[15];
    const float* kw    = (const float*)d_in[16];
    float* out = (float*)d_out;

    float *gacc,*bqkv;
    cudaGetSymbolAddress((void**)&gacc, g_gacc);
    cudaGetSymbolAddress((void**)&bqkv, g_bqkv);

    __nv_bfloat16 *qhg,*qlg,*khg,*klg,*vhg,*vlg;
    cudaGetSymbolAddress((void**)&qhg, g_qhg);   cudaGetSymbolAddress((void**)&qlg, g_qlg);
    cudaGetSymbolAddress((void**)&khg, g_khg);   cudaGetSymbolAddress((void**)&klg, g_klg);
    cudaGetSymbolAddress((void**)&vhg, g_vhg);   cudaGetSymbolAddress((void**)&vlg, g_vlg);

    __nv_bfloat16 *wqkvh,*wqkvl,*wiqh,*wiql,*wikh,*wikl,*woh,*wol;
    __nv_bfloat16 *xh,*xl,*ah,*al,*fh,*fl,*iqh,*ikh;
    cudaGetSymbolAddress((void**)&wqkvh, g_wqkvh); cudaGetSymbolAddress((void**)&wqkvl, g_wqkvl);
    cudaGetSymbolAddress((void**)&wiqh, g_wiqh);   cudaGetSymbolAddress((void**)&wiql, g_wiql);
    cudaGetSymbolAddress((void**)&wikh, g_wikh);   cudaGetSymbolAddress((void**)&wikl, g_wikl);
    cudaGetSymbolAddress((void**)&woh, g_woh);     cudaGetSymbolAddress((void**)&wol, g_wol);
    cudaGetSymbolAddress((void**)&xh, g_xh);       cudaGetSymbolAddress((void**)&xl, g_xl);
    cudaGetSymbolAddress((void**)&ah, g_ah);       cudaGetSymbolAddress((void**)&al, g_al);
    cudaGetSymbolAddress((void**)&fh, g_fh);       cudaGetSymbolAddress((void**)&fl, g_fl);
    cudaGetSymbolAddress((void**)&iqh, g_iqh);     cudaGetSymbolAddress((void**)&ikh, g_ikh);

    cudaFuncSetAttribute((const void*)mma_gemm_kernel,
                         cudaFuncAttributeMaxDynamicSharedMemorySize, TC_SMEM_3P);
    cudaFuncSetAttribute((const void*)flash_mma_kernel,
                         cudaFuncAttributeMaxDynamicSharedMemorySize, FL_SMEM);

    const int N4 = MROWS * D_ / 4;
    const int SPLIT_BLOCKS = (N4 + 255) / 256;

    // launches 1-3
    wt_split6_kernel<<<dim3(16, 16, 6), 256>>>(Wq, Wk, Wv, Wiq, Wik, Wo,
                                               wqkvh, wqkvl, wiqh, wiql, wikh, wikl, woh, wol);
    bias3_kernel<<<12, 256>>>(bq, bk, bv, bqkv);
    split_kernel<<<SPLIT_BLOCKS, 256>>>(x, xh, xl, N4);

    // launch #4 (profiled): fused QKV projection + RMS/split/scatter epilogue
    mma_gemm_kernel<<<dim3(D3/256, MROWS/128), 256, TC_SMEM_3P>>>(
        xh, xl, wqkvh, wqkvl, bqkv, nullptr, nullptr, nullptr, nullptr,
        nullptr, nullptr, nullptr, nullptr,
        qw, kw, qhg, qlg, khg, klg, vhg, vlg,
        MROWS, D3, D_, 0, 0, 0, 1, 4);

    // small prep (independent of QKV)
    zero_kernel<<<(MROWS+255)/256, 256>>>(gacc, MROWS);
    feat_kernel<<<MROWS, 256>>>(mask, embed, fh, fl);

    // attention (writes ah/al directly)
    flash_mma_kernel<<<dim3(SEQ/128, GH), 256, FL_SMEM>>>(qhg, qlg, khg, klg, vhg, vlg, ah, al);

    // iq & ik projections fused (z selects operand set)
    mma_gemm_kernel<<<dim3(D_/256, MROWS/128, 2), 256, TC_SMEM_1P>>>(
        ah, nullptr, wiqh, nullptr, biq, nullptr, iqh, nullptr, nullptr,
        fh, wikh, bik, ikh,
        nullptr, nullptr, nullptr, nullptr, nullptr, nullptr, nullptr, nullptr,
        MROWS, D_, D_, 0, 0, 0, 0, 1);

    // gate: per-batch iq @ ik^T with fused sigmoid row-sum (atomics)
    mma_gemm_kernel<<<dim3(2, 4, 8), 256, TC_SMEM_1P>>>(
        iqh, nullptr, ikh, nullptr, nullptr, nullptr, nullptr, nullptr, gacc,
        nullptr, nullptr, nullptr, nullptr,
        nullptr, nullptr, nullptr, nullptr, nullptr, nullptr, nullptr, nullptr,
        512, 512, D_, (long)512*D_, (long)512*D_, 0, 0, 3);

    // gated output projection: out = diag(1+gacc/512) * (attn @ Wo) + bo
    mma_gemm_kernel<<<dim3(D_/256, MROWS/128), 256, TC_SMEM_3P>>>(
        ah, al, woh, wol, bo, out, nullptr, gacc, nullptr,
        nullptr, nullptr, nullptr, nullptr,
        nullptr, nullptr, nullptr, nullptr, nullptr, nullptr, nullptr, nullptr,
        MROWS, D_, D_, 0, 0, 0, 1, 2);
}

// round 10
// speedup vs baseline: 1.2096x; 1.1683x over previous
#include <cuda_runtime.h>
#include <cuda_bf16.h>
#include <cuda_fp16.h>
#include <math.h>
#include <stdint.h>

// Problem constants
#define B_    8
#define N_    512
#define D_    1024
#define H_    16
#define HD_   64
#define NI_   4
#define G_    2
#define MROWS (B_*N_)      // 4096
#define SEQ   (NI_*N_)     // 2048
#define GH    (G_*H_)      // 32
#define D3    3072
#define SCALE 0.125f
#define S2    0.0078125f   // SCALE / H

// ---------------- scratch (device globals) -----------------------------------
static __device__ float g_gacc[MROWS];
static __device__ float g_bqkv[D3];

// attention operands (bf16 hi/lo, grouped [GH, SEQ, HD]) — flash stays bf16 3-pass
#define AELEMS (GH*SEQ*HD_)
static __device__ __align__(256) __nv_bfloat16 g_qhg[AELEMS], g_qlg[AELEMS];
static __device__ __align__(256) __nv_bfloat16 g_khg[AELEMS], g_klg[AELEMS];
static __device__ __align__(256) __nv_bfloat16 g_vhg[AELEMS], g_vlg[AELEMS];

// fp16 weights (hi only) and fp16 activations (hi/lo where needed)
static __device__ __align__(256) __half g_wqkvh[D3*D_];
static __device__ __align__(256) __half g_wiqh[D_*D_];
static __device__ __align__(256) __half g_wikh[D_*D_];
static __device__ __align__(256) __half g_woh[D_*D_];
static __device__ __align__(256) __half g_xh[MROWS*D_],  g_xl[MROWS*D_];
static __device__ __align__(256) __half g_ah[MROWS*D_],  g_al[MROWS*D_];   // attn hi/lo
static __device__ __align__(256) __half g_fh[MROWS*D_];
static __device__ __align__(256) __half g_iqh[MROWS*D_];
static __device__ __align__(256) __half g_ikh[MROWS*D_];

// ---------------- PTX helpers --------------------------------------------------
__device__ __forceinline__ uint32_t smem_u32(const void* p) {
    uint32_t a;
    asm("{ .reg .u64 t; cvta.to.shared.u64 t, %1; cvt.u32.u64 %0, t; }"
        : "=r"(a) : "l"(p));
    return a;
}

#define LDSM4(r, addr) \
    asm volatile("ldmatrix.sync.aligned.m8n8.x4.shared.b16 {%0,%1,%2,%3}, [%4];" \
        : "=r"((r)[0]), "=r"((r)[1]), "=r"((r)[2]), "=r"((r)[3]) : "r"(addr))

#define LDSM4T(r, addr) \
    asm volatile("ldmatrix.sync.aligned.m8n8.x4.trans.shared.b16 {%0,%1,%2,%3}, [%4];" \
        : "=r"((r)[0]), "=r"((r)[1]), "=r"((r)[2]), "=r"((r)[3]) : "r"(addr))

// bf16 MMA (flash)
#define MMAB(d, a, bv0, bv1) \
    asm volatile("mma.sync.aligned.m16n8k16.row.col.f32.bf16.bf16.f32 " \
        "{%0,%1,%2,%3}, {%4,%5,%6,%7}, {%8,%9}, {%0,%1,%2,%3};" \
        : "+f"((d)[0]), "+f"((d)[1]), "+f"((d)[2]), "+f"((d)[3]) \
        : "r"((a)[0]), "r"((a)[1]), "r"((a)[2]), "r"((a)[3]), "r"(bv0), "r"(bv1))

// fp16 MMA (projection GEMMs)
#define MMAH(d, a, bv0, bv1) \
    asm volatile("mma.sync.aligned.m16n8k16.row.col.f32.f16.f16.f32 " \
        "{%0,%1,%2,%3}, {%4,%5,%6,%7}, {%8,%9}, {%0,%1,%2,%3};" \
        : "+f"((d)[0]), "+f"((d)[1]), "+f"((d)[2]), "+f"((d)[3]) \
        : "r"((a)[0]), "r"((a)[1]), "r"((a)[2]), "r"((a)[3]), "r"(bv0), "r"(bv1))

#define CP_ASYNC16(dst, src) \
    asm volatile("cp.async.cg.shared.global [%0], [%1], 16;" \
        :: "r"(dst), "l"(__cvta_generic_to_global(src)) : "memory")
#define CP_COMMIT() asm volatile("cp.async.commit_group;" ::: "memory")
#define CP_WAIT(n)  asm volatile("cp.async.wait_group %0;" :: "n"(n) : "memory")

__device__ __forceinline__ uint32_t packbf(float a, float b) {
    uint32_t d;
    asm("cvt.rn.bf16x2.f32 %0, %1, %2;" : "=r"(d) : "f"(b), "f"(a));
    return d;
}
__device__ __forceinline__ float bflo(uint32_t v) { return __uint_as_float(v << 16); }
__device__ __forceinline__ float bfhi(uint32_t v) { return __uint_as_float(v & 0xffff0000u); }

__device__ __forceinline__ uint32_t packhf(float a, float b) {
    __half2 t = __floats2half2_rn(a, b);   // low = a, high = b
    return *reinterpret_cast<uint32_t*>(&t);
}
__device__ __forceinline__ float hflo(uint32_t v) {
    __half2 t = *reinterpret_cast<__half2*>(&v);
    return __low2float(t);
}
__device__ __forceinline__ float hfhi(uint32_t v) {
    __half2 t = *reinterpret_cast<__half2*>(&v);
    return __high2float(t);
}

// -------- fp16 HMMA GEMM: CTA 128x256, warp 64x64, 2-pass or 1-pass ----------
// 2-pass: C = (Ah+Al) @ Bh^T (+bias) — error = fp16 rounding of B only.
// out_mode: 0 fp32 C+bias; 1 fp16 Chf (+bias, z selects operand set);
//           2 fp32 gate-scaled; 3 sigmoid row-sum atomics into gout;
//           4 QKV epilogue: bias + per-head RMS norm (q,k) + bf16 split + scatter.
// stage 2-pass (64KB): Ah@0(16K) Al@16K Bh@32K(32K,256rows)
// stage 1-pass (48KB): Ah@0(16K) Bh@16K(32K)
#define TC_SMEM_2P (2*65536)   // 131072
#define TC_SMEM_1P (2*49152)   //  98304
__global__ __launch_bounds__(256, 1)
void mma_gemm_kernel(const __half* __restrict__ Ahp, const __half* __restrict__ Alp,
                     const __half* __restrict__ Bhp,
                     const float* __restrict__ bias, float* __restrict__ C,
                     __half* __restrict__ Chf,
                     const float* __restrict__ grow, float* __restrict__ gout,
                     const __half* __restrict__ Ahp2, const __half* __restrict__ Bhp2,
                     const float* __restrict__ bias2, __half* __restrict__ Chf2,
                     const float* __restrict__ qw, const float* __restrict__ kw,
                     __nv_bfloat16* __restrict__ qh_, __nv_bfloat16* __restrict__ ql_,
                     __nv_bfloat16* __restrict__ kh_, __nv_bfloat16* __restrict__ kl_,
                     __nv_bfloat16* __restrict__ vh_, __nv_bfloat16* __restrict__ vl_,
                     int M, int N, int K, long sA, long sB, long sC,
                     int npass, int out_mode)
{
    extern __shared__ char smem[];
    uint32_t sb = smem_u32(smem);
    int tid = threadIdx.x, wid = tid >> 5, lane = tid & 31;
    int m0 = blockIdx.y * 128, n0 = blockIdx.x * 256;
    long zb = blockIdx.z;
    const __half* Ah = Ahp + zb * sA;
    const __half* Al = (npass == 2) ? (Alp + zb * sA) : Ahp;
    const __half* Bh = Bhp + zb * sB;
    if (out_mode == 1 && blockIdx.z == 1) {
        Ah = Ahp2; Bh = Bhp2; bias = bias2; Chf = Chf2;
    }

    const int nsteps = K / 64;
    const uint32_t SS   = (npass == 2) ? 65536 : 49152;
    const uint32_t BOFF = (npass == 2) ? 32768 : 16384;
    const int ncp = (npass == 2) ? 16 : 12;

    auto issue = [&](int step, int stage) {
        uint32_t stb = sb + stage * SS;
        int k0 = step * 64;
#pragma unroll
        for (int i = 0; i < 16; i++) {
            if (i >= ncp) break;
            int c = i * 256 + tid;
            int tile = c >> 10;
            int w = c & 1023;
            int row = w >> 3, ch = w & 7;
            const __half* src;
            int gr;
            uint32_t tbase;
            if (npass == 2) {
                if      (tile == 0) { src = Ah; gr = m0 + row;        tbase = 0; }
                else if (tile == 1) { src = Al; gr = m0 + row;        tbase = 16384; }
                else if (tile == 2) { src = Bh; gr = n0 + row;        tbase = 32768; }
                else                { src = Bh; gr = n0 + 128 + row;  tbase = 49152; }
            } else {
                if      (tile == 0) { src = Ah; gr = m0 + row;        tbase = 0; }
                else if (tile == 1) { src = Bh; gr = n0 + row;        tbase = 16384; }
                else                { src = Bh; gr = n0 + 128 + row;  tbase = 32768; }
            }
            const __half* gp = src + (long)gr * K + k0 + ch * 8;
            uint32_t dst = stb + tbase + row * 128 + ((ch ^ (row & 7)) << 4);
            CP_ASYNC16(dst, gp);
        }
        CP_COMMIT();
    };

    int mbase = (wid >> 2) * 64;
    int nbase = (wid & 3) * 64;
    int arow = lane & 15;
    int brow = (lane & 7) + ((lane >> 4) & 1) * 8;

    float acc[4][8][4];
#pragma unroll
    for (int mt = 0; mt < 4; mt++)
#pragma unroll
        for (int nt = 0; nt < 8; nt++)
#pragma unroll
            for (int e = 0; e < 4; e++) acc[mt][nt][e] = 0.f;

    issue(0, 0);
    if (nsteps > 1) issue(1, 1);

    for (int step = 0; step < nsteps; step++) {
        if (step + 1 < nsteps) { CP_WAIT(1); } else { CP_WAIT(0); }
        __syncthreads();

        uint32_t stb = sb + (uint32_t)(step & 1) * SS;
#pragma unroll
        for (int k16 = 0; k16 < 4; k16++) {
            uint32_t ahf[4][4], alf[4][4], bhf[4][4];
            int ach = 2 * k16 + (lane >> 4);
#pragma unroll
            for (int mt = 0; mt < 4; mt++) {
                int row = mbase + mt * 16 + arow;
                uint32_t ad = stb + row * 128 + ((ach ^ (row & 7)) << 4);
                LDSM4(ahf[mt], ad);
                if (npass == 2) LDSM4(alf[mt], ad + 16384);
            }
            int bch = 2 * k16 + ((lane >> 3) & 1);
#pragma unroll
            for (int j = 0; j < 4; j++) {
                int row = nbase + j * 16 + brow;
                uint32_t bd = stb + BOFF + row * 128 + ((bch ^ (row & 7)) << 4);
                LDSM4(bhf[j], bd);
            }
            // pass 0: Ah * Bh
#pragma unroll
            for (int mt = 0; mt < 4; mt++)
#pragma unroll
                for (int nt = 0; nt < 8; nt++) {
                    int j = nt >> 1, p = (nt & 1) * 2;
                    MMAH(acc[mt][nt], ahf[mt], bhf[j][p], bhf[j][p+1]);
                }
            if (npass == 2) {
                // pass 1: Al * Bh
#pragma unroll
                for (int mt = 0; mt < 4; mt++)
#pragma unroll
                    for (int nt = 0; nt < 8; nt++) {
                        int j = nt >> 1, p = (nt & 1) * 2;
                        MMAH(acc[mt][nt], alf[mt], bhf[j][p], bhf[j][p+1]);
                    }
            }
        }
        __syncthreads();
        if (step + 2 < nsteps) issue(step + 2, step & 1);
    }

    // ------------------------------ epilogues ---------------------------------
    if (out_mode == 4) {
        // bias + per-head RMS norm (q,k) + bf16 hi/lo split + grouped scatter
        int c0 = n0 + nbase;             // multiple of 64
        int type = c0 >> 10;             // 0=q 1=k 2=v
        int hh = (c0 & 1023) >> 6;       // head index
        const float* wv = (type == 0) ? qw : kw;
        __nv_bfloat16 *ph, *pl;
        if (type == 0)      { ph = qh_; pl = ql_; }
        else if (type == 1) { ph = kh_; pl = kl_; }
        else                { ph = vh_; pl = vl_; }
#pragma unroll
        for (int mt = 0; mt < 4; mt++) {
            float vals[8][4];
            float ss0 = 0.f, ss1 = 0.f;
            int r0 = m0 + mbase + mt * 16 + (lane >> 2);
#pragma unroll
            for (int nt = 0; nt < 8; nt++) {
                int c = c0 + nt * 8 + 2 * (lane & 3);
                float b0 = bias[c], b1 = bias[c + 1];
                vals[nt][0] = acc[mt][nt][0] + b0;
                vals[nt][1] = acc[mt][nt][1] + b1;
                vals[nt][2] = acc[mt][nt][2] + b0;
                vals[nt][3] = acc[mt][nt][3] + b1;
                ss0 += vals[nt][0]*vals[nt][0] + vals[nt][1]*vals[nt][1];
                ss1 += vals[nt][2]*vals[nt][2] + vals[nt][3]*vals[nt][3];
            }
            ss0 += __shfl_xor_sync(0xffffffffu, ss0, 1, 4);
            ss0 += __shfl_xor_sync(0xffffffffu, ss0, 2, 4);
            ss1 += __shfl_xor_sync(0xffffffffu, ss1, 1, 4);
            ss1 += __shfl_xor_sync(0xffffffffu, ss1, 2, 4);
            float sc0 = 1.f, sc1 = 1.f;
            if (type == 0) {
                sc0 = rsqrtf(ss0 * (1.0f/64.0f) + 1e-6f) * SCALE;
                sc1 = rsqrtf(ss1 * (1.0f/64.0f) + 1e-6f) * SCALE;
            } else if (type == 1) {
                sc0 = rsqrtf(ss0 * (1.0f/64.0f) + 1e-6f);
                sc1 = rsqrtf(ss1 * (1.0f/64.0f) + 1e-6f);
            }
#pragma unroll
            for (int e = 0; e < 2; e++) {
                int r = r0 + 8 * e;
                int b = r >> 9, n = r & 511;
                int g = b >> 2, inst = b & 3;
                long obase = (((long)(g*16 + hh)) * SEQ + inst*512 + n) * HD_;
                float sc = e ? sc1 : sc0;
#pragma unroll
                for (int nt = 0; nt < 8; nt++) {
                    int colh = nt * 8 + 2 * (lane & 3);
                    float wa = (type < 2) ? wv[colh]     : 1.f;
                    float wb = (type < 2) ? wv[colh + 1] : 1.f;
                    float u0 = vals[nt][2*e]   * sc * wa;
                    float u1 = vals[nt][2*e+1] * sc * wb;
                    uint32_t hp = packbf(u0, u1);
                    uint32_t lp = packbf(u0 - bflo(hp), u1 - bfhi(hp));
                    *(uint32_t*)&ph[obase + colh] = hp;
                    *(uint32_t*)&pl[obase + colh] = lp;
                }
            }
        }
        return;
    }

    if (out_mode == 3) {
#pragma unroll
        for (int mt = 0; mt < 4; mt++) {
            int r0 = m0 + mbase + mt * 16 + (lane >> 2);
            float ps0 = 0.f, ps1 = 0.f;
#pragma unroll
            for (int nt = 0; nt < 8; nt++) {
                ps0 += 1.0f / (1.0f + __expf(-acc[mt][nt][0] * S2));
                ps0 += 1.0f / (1.0f + __expf(-acc[mt][nt][1] * S2));
                ps1 += 1.0f / (1.0f + __expf(-acc[mt][nt][2] * S2));
                ps1 += 1.0f / (1.0f + __expf(-acc[mt][nt][3] * S2));
            }
            ps0 += __shfl_xor_sync(0xffffffffu, ps0, 1, 4);
            ps0 += __shfl_xor_sync(0xffffffffu, ps0, 2, 4);
            ps1 += __shfl_xor_sync(0xffffffffu, ps1, 1, 4);
            ps1 += __shfl_xor_sync(0xffffffffu, ps1, 2, 4);
            if ((lane & 3) == 0) {
                atomicAdd(&gout[zb * 512 + r0], ps0);
                atomicAdd(&gout[zb * 512 + r0 + 8], ps1);
            }
        }
        return;
    }

#pragma unroll
    for (int mt = 0; mt < 4; mt++) {
        int r0 = m0 + mbase + mt * 16 + (lane >> 2);
        float g0 = 1.f, g1 = 1.f;
        if (out_mode == 2) {
            g0 = 1.0f + grow[r0] * (1.0f/512.0f);
            g1 = 1.0f + grow[r0 + 8] * (1.0f/512.0f);
        }
#pragma unroll
        for (int nt = 0; nt < 8; nt++) {
            int c = n0 + nbase + nt * 8 + 2 * (lane & 3);
            float b0 = 0.f, b1 = 0.f;
            if (bias) { b0 = bias[c]; b1 = bias[c + 1]; }
            float v00 = acc[mt][nt][0] * g0 + b0, v01 = acc[mt][nt][1] * g0 + b1;
            float v10 = acc[mt][nt][2] * g1 + b0, v11 = acc[mt][nt][3] * g1 + b1;
            if (out_mode == 1) {
                *(uint32_t*)&Chf[(long)r0 * N + c]       = packhf(v00, v01);
                *(uint32_t*)&Chf[(long)(r0 + 8) * N + c] = packhf(v10, v11);
            } else {
                float* Cc = C + zb * sC;
                float2 w0; w0.x = v00; w0.y = v01;
                *(float2*)&Cc[(long)r0 * N + c] = w0;
                float2 w1; w1.x = v10; w1.y = v11;
                *(float2*)&Cc[(long)(r0 + 8) * N + c] = w1;
            }
        }
    }
}

// ---------------- weight transpose + fp16 convert (6 weights fused) ----------
__device__ __forceinline__ void wt_split_body(
    const float* __restrict__ W, __half* __restrict__ Th, float (*t)[65])
{
    int n0 = blockIdx.x * 64, k0 = blockIdx.y * 64;
    int tid = threadIdx.x;
#pragma unroll
    for (int it = 0; it < 4; it++) {
        int row = (tid >> 4) + it * 16;
        int c4 = (tid & 15) * 4;
        float4 v = *(const float4*)&W[(long)(k0 + row) * D_ + n0 + c4];
        t[row][c4+0] = v.x; t[row][c4+1] = v.y; t[row][c4+2] = v.z; t[row][c4+3] = v.w;
    }
    __syncthreads();
    int n = tid >> 2, kc = (tid & 3) * 16;
    uint32_t hb[8];
#pragma unroll
    for (int j = 0; j < 16; j += 2)
        hb[j >> 1] = packhf(t[kc + j][n], t[kc + j + 1][n]);
    long obase = (long)(n0 + n) * D_ + k0 + kc;
    *(uint4*)&Th[obase]     = make_uint4(hb[0], hb[1], hb[2], hb[3]);
    *(uint4*)&Th[obase + 8] = make_uint4(hb[4], hb[5], hb[6], hb[7]);
}

__global__ __launch_bounds__(256) void wt_split6_kernel(
    const float* __restrict__ Wq, const float* __restrict__ Wk, const float* __restrict__ Wv,
    const float* __restrict__ Wiq, const float* __restrict__ Wik, const float* __restrict__ Wo,
    __half* __restrict__ wqkvh, __half* __restrict__ wiqh,
    __half* __restrict__ wikh, __half* __restrict__ woh)
{
    __shared__ float t[64][65];
    const float* W;
    __half* Th;
    switch (blockIdx.z) {
        case 0: W = Wq;  Th = wqkvh;             break;
        case 1: W = Wk;  Th = wqkvh + 1024*1024; break;
        case 2: W = Wv;  Th = wqkvh + 2048*1024; break;
        case 3: W = Wiq; Th = wiqh;              break;
        case 4: W = Wik; Th = wikh;              break;
        default: W = Wo; Th = woh;               break;
    }
    wt_split_body(W, Th, t);
}

// ---------------- bias concat (bq|bk|bv) --------------------------------------
__global__ void bias3_kernel(const float* __restrict__ a, const float* __restrict__ b,
                             const float* __restrict__ c, float* __restrict__ o)
{
    int i = blockIdx.x * 256 + threadIdx.x;
    if (i < 1024)       o[i] = a[i];
    else if (i < 2048)  o[i] = b[i - 1024];
    else if (i < 3072)  o[i] = c[i - 2048];
}

// ---------------- activation split (fp16 hi/lo) -------------------------------
__global__ __launch_bounds__(256) void split_kernel(
    const float* __restrict__ src, __half* __restrict__ h,
    __half* __restrict__ l, int n4)
{
    int i = blockIdx.x * 256 + threadIdx.x;
    if (i >= n4) return;
    float4 f = ((const float4*)src)[i];
    uint32_t h0 = packhf(f.x, f.y), h1 = packhf(f.z, f.w);
    ((uint32_t*)h)[i*2+0] = h0;
    ((uint32_t*)h)[i*2+1] = h1;
    ((uint32_t*)l)[i*2+0] = packhf(f.x - hflo(h0), f.y - hfhi(h0));
    ((uint32_t*)l)[i*2+1] = packhf(f.z - hflo(h1), f.w - hfhi(h1));
}

// ---------------- flash attention via mma.sync (split-bf16 3-pass) -----------
// unchanged except epilogue emits fp16 ah/al for the Wo 2-pass GEMM
#define FL_SMEM (2*65536 + 32768)
__global__ __launch_bounds__(256, 1)
void flash_mma_kernel(const __nv_bfloat16* __restrict__ Qh_, const __nv_bfloat16* __restrict__ Ql_,
                      const __nv_bfloat16* __restrict__ Kh_, const __nv_bfloat16* __restrict__ Kl_,
                      const __nv_bfloat16* __restrict__ Vh_, const __nv_bfloat16* __restrict__ Vl_,
                      __half* __restrict__ Oh, __half* __restrict__ Ol)
{
    extern __shared__ char smem[];
    uint32_t sb = smem_u32(smem);
    int tid = threadIdx.x, wid = tid >> 5, lane = tid & 31;
    int qt = blockIdx.x, gh = blockIdx.y;
    long ghoff = (long)gh * SEQ * HD_;
    const __nv_bfloat16* Qh = Qh_ + ghoff + (long)qt * 128 * HD_;
    const __nv_bfloat16* Ql = Ql_ + ghoff + (long)qt * 128 * HD_;
    const __nv_bfloat16* Kh = Kh_ + ghoff;
    const __nv_bfloat16* Kl = Kl_ + ghoff;
    const __nv_bfloat16* Vh = Vh_ + ghoff;
    const __nv_bfloat16* Vl = Vl_ + ghoff;

    const uint32_t QOFF = 131072;

    {
#pragma unroll
        for (int i = 0; i < 8; i++) {
            int c = i * 256 + tid;
            int arr = c >> 10, w = c & 1023, row = w >> 3, ch = w & 7;
            const __nv_bfloat16* src = (arr ? Ql : Qh) + (long)row * 64 + ch * 8;
            uint32_t dst = sb + QOFF + arr * 16384 + row * 128 + ((ch ^ (row & 7)) << 4);
            CP_ASYNC16(dst, src);
        }
        CP_COMMIT();
    }

    auto issueKV = [&](int it, int stage) {
        uint32_t stb = sb + stage * 65536;
#pragma unroll
        for (int i = 0; i < 16; i++) {
            int c = i * 256 + tid;
            int arr = c >> 10, w = c & 1023, row = w >> 3, ch = w & 7;
            const __nv_bfloat16* src;
            if      (arr == 0) src = Kh;
            else if (arr == 1) src = Kl;
            else if (arr == 2) src = Vh;
            else               src = Vl;
            src += (long)(it * 128 + row) * 64 + ch * 8;
            uint32_t dst = stb + arr * 16384 + row * 128 + ((ch ^ (row & 7)) << 4);
            CP_ASYNC16(dst, src);
        }
        CP_COMMIT();
    };

    issueKV(0, 0);
    issueKV(1, 1);
    CP_WAIT(1);
    __syncthreads();

    uint32_t qhf[4][4], qlf[4][4];
    {
        int arow = lane & 15;
#pragma unroll
        for (int kt = 0; kt < 4; kt++) {
            int row = wid * 16 + arow;
            int ach = 2 * kt + (lane >> 4);
            uint32_t ad = sb + QOFF + row * 128 + ((ach ^ (row & 7)) << 4);
            LDSM4(qhf[kt], ad);
            LDSM4(qlf[kt], ad + 16384);
        }
    }

    float o[8][4];
#pragma unroll
    for (int nt = 0; nt < 8; nt++)
#pragma unroll
        for (int e = 0; e < 4; e++) o[nt][e] = 0.f;
    float m0 = -1e30f, m1 = -1e30f, lp0 = 0.f, lp1 = 0.f;

    for (int it = 0; it < 16; it++) {
        if (it > 0) {
            if (it < 15) { CP_WAIT(1); } else { CP_WAIT(0); }
            __syncthreads();
        }
        uint32_t stb = sb + (it & 1) * 65536;

        float s[16][4];
#pragma unroll
        for (int t = 0; t < 16; t++)
#pragma unroll
            for (int e = 0; e < 4; e++) s[t][e] = 0.f;

        int brow = (lane & 7) + ((lane >> 4) & 1) * 8;
#pragma unroll
        for (int kt = 0; kt < 4; kt++) {
            int bch = 2 * kt + ((lane >> 3) & 1);
#pragma unroll
            for (int jp = 0; jp < 4; jp++) {
                uint32_t khf[2][4], klf[2][4];
#pragma unroll
                for (int j = 0; j < 2; j++) {
                    int row = (2 * jp + j) * 16 + brow;
                    uint32_t bd = stb + row * 128 + ((bch ^ (row & 7)) << 4);
                    LDSM4(khf[j], bd);
                    LDSM4(klf[j], bd + 16384);
                }
                int t0 = 4 * jp;
                MMAB(s[t0+0], qhf[kt], khf[0][0], khf[0][1]);
                MMAB(s[t0+1], qhf[kt], khf[0][2], khf[0][3]);
                MMAB(s[t0+2], qhf[kt], khf[1][0], khf[1][1]);
                MMAB(s[t0+3], qhf[kt], khf[1][2], khf[1][3]);
                MMAB(s[t0+0], qhf[kt], klf[0][0], klf[0][1]);
                MMAB(s[t0+1], qhf[kt], klf[0][2], klf[0][3]);
                MMAB(s[t0+2], qhf[kt], klf[1][0], klf[1][1]);
                MMAB(s[t0+3], qhf[kt], klf[1][2], klf[1][3]);
                MMAB(s[t0+0], qlf[kt], khf[0][0], khf[0][1]);
                MMAB(s[t0+1], qlf[kt], khf[0][2], khf[0][3]);
                MMAB(s[t0+2], qlf[kt], khf[1][0], khf[1][1]);
                MMAB(s[t0+3], qlf[kt], khf[1][2], khf[1][3]);
            }
        }

        float t0 = -1e30f, t1 = -1e30f;
#pragma unroll
        for (int t = 0; t < 16; t++) {
            t0 = fmaxf(t0, fmaxf(s[t][0], s[t][1]));
            t1 = fmaxf(t1, fmaxf(s[t][2], s[t][3]));
        }
        t0 = fmaxf(t0, __shfl_xor_sync(0xffffffffu, t0, 1, 4));
        t0 = fmaxf(t0, __shfl_xor_sync(0xffffffffu, t0, 2, 4));
        t1 = fmaxf(t1, __shfl_xor_sync(0xffffffffu, t1, 1, 4));
        t1 = fmaxf(t1, __shfl_xor_sync(0xffffffffu, t1, 2, 4));
        float mn0 = fmaxf(m0, t0), mn1 = fmaxf(m1, t1);
        float c0 = __expf(m0 - mn0), c1 = __expf(m1 - mn1);
        m0 = mn0; m1 = mn1;
        lp0 *= c0; lp1 *= c1;
#pragma unroll
        for (int nt = 0; nt < 8; nt++) {
            o[nt][0] *= c0; o[nt][1] *= c0;
            o[nt][2] *= c1; o[nt][3] *= c1;
        }
#pragma unroll
        for (int t = 0; t < 16; t++) {
            s[t][0] = __expf(s[t][0] - m0);
            s[t][1] = __expf(s[t][1] - m0);
            s[t][2] = __expf(s[t][2] - m1);
            s[t][3] = __expf(s[t][3] - m1);
            lp0 += s[t][0] + s[t][1];
            lp1 += s[t][2] + s[t][3];
        }

        int vrow = lane & 15;
#pragma unroll
        for (int kt = 0; kt < 8; kt++) {
            uint32_t pha[4], pla[4];
#pragma unroll
            for (int q = 0; q < 2; q++) {
                float a0 = s[2*kt + q][0], a1 = s[2*kt + q][1];
                float a2 = s[2*kt + q][2], a3 = s[2*kt + q][3];
                uint32_t h0 = packbf(a0, a1);
                uint32_t h1 = packbf(a2, a3);
                pha[2*q]   = h0;
                pha[2*q+1] = h1;
                pla[2*q]   = packbf(a0 - bflo(h0), a1 - bfhi(h0));
                pla[2*q+1] = packbf(a2 - bflo(h1), a3 - bfhi(h1));
            }
            int row = kt * 16 + vrow;
#pragma unroll
            for (int np = 0; np < 2; np++) {
                uint32_t vhf[2][4], vlf[2][4];
#pragma unroll
                for (int j = 0; j < 2; j++) {
                    int ch = 2 * (2 * np + j) + (lane >> 4);
                    uint32_t vd = stb + 32768 + row * 128 + ((ch ^ (row & 7)) << 4);
                    LDSM4T(vhf[j], vd);
                    LDSM4T(vlf[j], vd + 16384);
                }
                int ob = 4 * np;
                MMAB(o[ob+0], pha, vhf[0][0], vhf[0][1]);
                MMAB(o[ob+1], pha, vhf[0][2], vhf[0][3]);
                MMAB(o[ob+2], pha, vhf[1][0], vhf[1][1]);
                MMAB(o[ob+3], pha, vhf[1][2], vhf[1][3]);
                MMAB(o[ob+0], pha, vlf[0][0], vlf[0][1]);
                MMAB(o[ob+1], pha, vlf[0][2], vlf[0][3]);
                MMAB(o[ob+2], pha, vlf[1][0], vlf[1][1]);
                MMAB(o[ob+3], pha, vlf[1][2], vlf[1][3]);
                MMAB(o[ob+0], pla, vhf[0][0], vhf[0][1]);
                MMAB(o[ob+1], pla, vhf[0][2], vhf[0][3]);
                MMAB(o[ob+2], pla, vhf[1][0], vhf[1][1]);
                MMAB(o[ob+3], pla, vhf[1][2], vhf[1][3]);
            }
        }

        __syncthreads();
        if (it + 2 < 16) issueKV(it + 2, it & 1);
    }

    lp0 += __shfl_xor_sync(0xffffffffu, lp0, 1, 4);
    lp0 += __shfl_xor_sync(0xffffffffu, lp0, 2, 4);
    lp1 += __shfl_xor_sync(0xffffffffu, lp1, 1, 4);
    lp1 += __shfl_xor_sync(0xffffffffu, lp1, 2, 4);
    float inv0 = 1.0f / lp0, inv1 = 1.0f / lp1;

    int g = gh >> 4, h = gh & 15;
#pragma unroll
    for (int e = 0; e < 2; e++) {
        int r = qt * 128 + wid * 16 + (lane >> 2) + 8 * e;
        int inst = r >> 9, n = r & 511;
        int b = g * 4 + inst;
        float inv = e ? inv1 : inv0;
        long base = ((long)(b * 512 + n)) * D_ + h * HD_;
#pragma unroll
        for (int nt = 0; nt < 8; nt++) {
            float v0 = o[nt][2*e] * inv, v1 = o[nt][2*e+1] * inv;
            uint32_t hp = packhf(v0, v1);
            uint32_t lp = packhf(v0 - hflo(hp), v1 - hfhi(hp));
            long idx = base + nt * 8 + 2 * (lane & 3);
            *(uint32_t*)&Oh[idx] = hp;
            *(uint32_t*)&Ol[idx] = lp;
        }
    }
}

// ---------------- instance feature -> fp16 ------------------------------------
__global__ __launch_bounds__(256) void feat_kernel(
    const float* __restrict__ mask, const float* __restrict__ embed,
    __half* __restrict__ fh)
{
    int row = blockIdx.x;
    float m0 = mask[row*4+0], m1 = mask[row*4+1];
    float m2 = mask[row*4+2], m3 = mask[row*4+3];
    for (int c = threadIdx.x * 2; c < D_; c += 512) {
        float f0 = m0*embed[c]   + m1*embed[D_ + c]   + m2*embed[2*D_ + c]   + m3*embed[3*D_ + c];
        float f1 = m0*embed[c+1] + m1*embed[D_ + c+1] + m2*embed[2*D_ + c+1] + m3*embed[3*D_ + c+1];
        *(uint32_t*)&fh[(long)row*D_ + c] = packhf(f0, f1);
    }
}

__global__ void zero_kernel(float* __restrict__ p, int n)
{
    int i = blockIdx.x * blockDim.x + threadIdx.x;
    if (i < n) p[i] = 0.f;
}

// ------------------------------- launch --------------------------------------
extern "C" void kernel_launch(void* const* d_in, const int* in_sizes, int n_in,
                              void* d_out, int out_size)
{
    const float* x     = (const float*)d_in[0];
    const float* mask  = (const float*)d_in[1];
    const float* Wq    = (const float*)d_in[2];
    const float* bq    = (const float*)d_in[3];
    const float* Wk    = (const float*)d_in[4];
    const float* bk    = (const float*)d_in[5];
    const float* Wv    = (const float*)d_in[6];
    const float* bv    = (const float*)d_in[7];
    const float* Wo    = (const float*)d_in[8];
    const float* bo    = (const float*)d_in[9];
    const float* Wiq   = (const float*)d_in[10];
    const float* biq   = (const float*)d_in[11];
    const float* Wik   = (const float*)d_in[12];
    const float* bik   = (const float*)d_in[13];
    const float* embed = (const float*)d_in[14];
    const float* qw    = (const float*)d_in[15];
    const float* kw    = (const float*)d_in[16];
    float* out = (float*)d_out;

    float *gacc,*bqkv;
    cudaGetSymbolAddress((void**)&gacc, g_gacc);
    cudaGetSymbolAddress((void**)&bqkv, g_bqkv);

    __nv_bfloat16 *qhg,*qlg,*khg,*klg,*vhg,*vlg;
    cudaGetSymbolAddress((void**)&qhg, g_qhg);   cudaGetSymbolAddress((void**)&qlg, g_qlg);
    cudaGetSymbolAddress((void**)&khg, g_khg);   cudaGetSymbolAddress((void**)&klg, g_klg);
    cudaGetSymbolAddress((void**)&vhg, g_vhg);   cudaGetSymbolAddress((void**)&vlg, g_vlg);

    __half *wqkvh,*wiqh,*wikh,*woh,*xh,*xl,*ah,*al,*fh,*iqh,*ikh;
    cudaGetSymbolAddress((void**)&wqkvh, g_wqkvh);
    cudaGetSymbolAddress((void**)&wiqh, g_wiqh);
    cudaGetSymbolAddress((void**)&wikh, g_wikh);
    cudaGetSymbolAddress((void**)&woh, g_woh);
    cudaGetSymbolAddress((void**)&xh, g_xh);       cudaGetSymbolAddress((void**)&xl, g_xl);
    cudaGetSymbolAddress((void**)&ah, g_ah);       cudaGetSymbolAddress((void**)&al, g_al);
    cudaGetSymbolAddress((void**)&fh, g_fh);
    cudaGetSymbolAddress((void**)&iqh, g_iqh);     cudaGetSymbolAddress((void**)&ikh, g_ikh);

    cudaFuncSetAttribute((const void*)mma_gemm_kernel,
                         cudaFuncAttributeMaxDynamicSharedMemorySize, TC_SMEM_2P);
    cudaFuncSetAttribute((const void*)flash_mma_kernel,
                         cudaFuncAttributeMaxDynamicSharedMemorySize, FL_SMEM);

    const int N4 = MROWS * D_ / 4;
    const int SPLIT_BLOCKS = (N4 + 255) / 256;

    // launches 1-3
    wt_split6_kernel<<<dim3(16, 16, 6), 256>>>(Wq, Wk, Wv, Wiq, Wik, Wo,
                                               wqkvh, wiqh, wikh, woh);
    bias3_kernel<<<12, 256>>>(bq, bk, bv, bqkv);
    split_kernel<<<SPLIT_BLOCKS, 256>>>(x, xh, xl, N4);

    // launch #4 (profiled): fused QKV projection (fp16 2-pass) + RMS epilogue
    mma_gemm_kernel<<<dim3(D3/256, MROWS/128), 256, TC_SMEM_2P>>>(
        xh, xl, wqkvh, bqkv, nullptr, nullptr, nullptr, nullptr,
        nullptr, nullptr, nullptr, nullptr,
        qw, kw, qhg, qlg, khg, klg, vhg, vlg,
        MROWS, D3, D_, 0, 0, 0, 2, 4);

    // small prep
    zero_kernel<<<(MROWS+255)/256, 256>>>(gacc, MROWS);
    feat_kernel<<<MROWS, 256>>>(mask, embed, fh);

    // attention (bf16 3-pass; emits fp16 ah/al)
    flash_mma_kernel<<<dim3(SEQ/128, GH), 256, FL_SMEM>>>(qhg, qlg, khg, klg, vhg, vlg, ah, al);

    // iq & ik projections fused (fp16 1-pass; z selects operand set)
    mma_gemm_kernel<<<dim3(D_/256, MROWS/128, 2), 256, TC_SMEM_1P>>>(
        ah, nullptr, wiqh, biq, nullptr, iqh, nullptr, nullptr,
        fh, wikh, bik, ikh,
        nullptr, nullptr, nullptr, nullptr, nullptr, nullptr, nullptr, nullptr,
        MROWS, D_, D_, 0, 0, 0, 1, 1);

    // gate: per-batch iq @ ik^T (fp16 1-pass) with fused sigmoid row-sum
    mma_gemm_kernel<<<dim3(2, 4, 8), 256, TC_SMEM_1P>>>(
        iqh, nullptr, ikh, nullptr, nullptr, nullptr, nullptr, gacc,
        nullptr, nullptr, nullptr, nullptr,
        nullptr, nullptr, nullptr, nullptr, nullptr, nullptr, nullptr, nullptr,
        512, 512, D_, (long)512*D_, (long)512*D_, 0, 1, 3);

    // gated output projection (fp16 2-pass): out = diag(1+gacc/512)*(attn@Wo)+bo
    mma_gemm_kernel<<<dim3(D_/256, MROWS/128), 256, TC_SMEM_2P>>>(
        ah, al, woh, bo, out, nullptr, gacc, nullptr,
        nullptr, nullptr, nullptr, nullptr,
        nullptr, nullptr, nullptr, nullptr, nullptr, nullptr, nullptr, nullptr,
        MROWS, D_, D_, 0, 0, 0, 2, 2);
}

// round 11
// speedup vs baseline: 1.3023x; 1.0767x over previous
#include <cuda_runtime.h>
#include <cuda_bf16.h>
#include <cuda_fp16.h>
#include <math.h>
#include <stdint.h>

// Problem constants
#define B_    8
#define N_    512
#define D_    1024
#define H_    16
#define HD_   64
#define NI_   4
#define G_    2
#define MROWS (B_*N_)      // 4096
#define SEQ   (NI_*N_)     // 2048
#define GH    (G_*H_)      // 32
#define D3    3072
#define SCALE 0.125f
#define S2    0.0078125f   // SCALE / H

// ---------------- scratch (device globals) -----------------------------------
static __device__ float g_gacc[MROWS];
static __device__ float g_bqkv[D3];

// attention operands, grouped [GH, SEQ, HD]: q/k bf16 hi/lo (3-pass S), v fp16
#define AELEMS (GH*SEQ*HD_)
static __device__ __align__(256) __nv_bfloat16 g_qhg[AELEMS], g_qlg[AELEMS];
static __device__ __align__(256) __nv_bfloat16 g_khg[AELEMS], g_klg[AELEMS];
static __device__ __align__(256) __half g_vhg[AELEMS];

// fp16 weights (hi only) and fp16 activations (hi/lo where needed)
static __device__ __align__(256) __half g_wqkvh[D3*D_];
static __device__ __align__(256) __half g_wiqh[D_*D_];
static __device__ __align__(256) __half g_wikh[D_*D_];
static __device__ __align__(256) __half g_woh[D_*D_];
static __device__ __align__(256) __half g_xh[MROWS*D_],  g_xl[MROWS*D_];
static __device__ __align__(256) __half g_ah[MROWS*D_],  g_al[MROWS*D_];   // attn hi/lo
static __device__ __align__(256) __half g_fh[MROWS*D_];
static __device__ __align__(256) __half g_iqh[MROWS*D_];
static __device__ __align__(256) __half g_ikh[MROWS*D_];

// ---------------- PTX helpers --------------------------------------------------
__device__ __forceinline__ uint32_t smem_u32(const void* p) {
    uint32_t a;
    asm("{ .reg .u64 t; cvta.to.shared.u64 t, %1; cvt.u32.u64 %0, t; }"
        : "=r"(a) : "l"(p));
    return a;
}

#define LDSM4(r, addr) \
    asm volatile("ldmatrix.sync.aligned.m8n8.x4.shared.b16 {%0,%1,%2,%3}, [%4];" \
        : "=r"((r)[0]), "=r"((r)[1]), "=r"((r)[2]), "=r"((r)[3]) : "r"(addr))

#define LDSM4T(r, addr) \
    asm volatile("ldmatrix.sync.aligned.m8n8.x4.trans.shared.b16 {%0,%1,%2,%3}, [%4];" \
        : "=r"((r)[0]), "=r"((r)[1]), "=r"((r)[2]), "=r"((r)[3]) : "r"(addr))

// bf16 MMA (flash S)
#define MMAB(d, a, bv0, bv1) \
    asm volatile("mma.sync.aligned.m16n8k16.row.col.f32.bf16.bf16.f32 " \
        "{%0,%1,%2,%3}, {%4,%5,%6,%7}, {%8,%9}, {%0,%1,%2,%3};" \
        : "+f"((d)[0]), "+f"((d)[1]), "+f"((d)[2]), "+f"((d)[3]) \
        : "r"((a)[0]), "r"((a)[1]), "r"((a)[2]), "r"((a)[3]), "r"(bv0), "r"(bv1))

// fp16 MMA (projection GEMMs + flash PV)
#define MMAH(d, a, bv0, bv1) \
    asm volatile("mma.sync.aligned.m16n8k16.row.col.f32.f16.f16.f32 " \
        "{%0,%1,%2,%3}, {%4,%5,%6,%7}, {%8,%9}, {%0,%1,%2,%3};" \
        : "+f"((d)[0]), "+f"((d)[1]), "+f"((d)[2]), "+f"((d)[3]) \
        : "r"((a)[0]), "r"((a)[1]), "r"((a)[2]), "r"((a)[3]), "r"(bv0), "r"(bv1))

#define CP_ASYNC16(dst, src) \
    asm volatile("cp.async.cg.shared.global [%0], [%1], 16;" \
        :: "r"(dst), "l"(__cvta_generic_to_global(src)) : "memory")
#define CP_COMMIT() asm volatile("cp.async.commit_group;" ::: "memory")
#define CP_WAIT(n)  asm volatile("cp.async.wait_group %0;" :: "n"(n) : "memory")

__device__ __forceinline__ uint32_t packbf(float a, float b) {
    uint32_t d;
    asm("cvt.rn.bf16x2.f32 %0, %1, %2;" : "=r"(d) : "f"(b), "f"(a));
    return d;
}
__device__ __forceinline__ float bflo(uint32_t v) { return __uint_as_float(v << 16); }
__device__ __forceinline__ float bfhi(uint32_t v) { return __uint_as_float(v & 0xffff0000u); }

__device__ __forceinline__ uint32_t packhf(float a, float b) {
    __half2 t = __floats2half2_rn(a, b);   // low = a, high = b
    return *reinterpret_cast<uint32_t*>(&t);
}
__device__ __forceinline__ float hflo(uint32_t v) {
    __half2 t = *reinterpret_cast<__half2*>(&v);
    return __low2float(t);
}
__device__ __forceinline__ float hfhi(uint32_t v) {
    __half2 t = *reinterpret_cast<__half2*>(&v);
    return __high2float(t);
}

// -------- fp16 HMMA GEMM: CTA 128x256, warp 64x64, 2-pass or 1-pass ----------
// out_mode: 0 fp32 C+bias; 1 fp16 Chf (+bias, z selects operand set);
//           2 fp32 gate-scaled; 3 sigmoid row-sum atomics into gout;
//           4 QKV epilogue: bias + per-head RMS norm (q,k, bf16 hi/lo) + v fp16.
#define TC_SMEM_2P (2*65536)   // 131072
#define TC_SMEM_1P (2*49152)   //  98304
__global__ __launch_bounds__(256, 1)
void mma_gemm_kernel(const __half* __restrict__ Ahp, const __half* __restrict__ Alp,
                     const __half* __restrict__ Bhp,
                     const float* __restrict__ bias, float* __restrict__ C,
                     __half* __restrict__ Chf,
                     const float* __restrict__ grow, float* __restrict__ gout,
                     const __half* __restrict__ Ahp2, const __half* __restrict__ Bhp2,
                     const float* __restrict__ bias2, __half* __restrict__ Chf2,
                     const float* __restrict__ qw, const float* __restrict__ kw,
                     __nv_bfloat16* __restrict__ qh_, __nv_bfloat16* __restrict__ ql_,
                     __nv_bfloat16* __restrict__ kh_, __nv_bfloat16* __restrict__ kl_,
                     __half* __restrict__ vhf_,
                     int M, int N, int K, long sA, long sB, long sC,
                     int npass, int out_mode)
{
    extern __shared__ char smem[];
    uint32_t sb = smem_u32(smem);
    int tid = threadIdx.x, wid = tid >> 5, lane = tid & 31;
    int m0 = blockIdx.y * 128, n0 = blockIdx.x * 256;
    long zb = blockIdx.z;
    const __half* Ah = Ahp + zb * sA;
    const __half* Al = (npass == 2) ? (Alp + zb * sA) : Ahp;
    const __half* Bh = Bhp + zb * sB;
    if (out_mode == 1 && blockIdx.z == 1) {
        Ah = Ahp2; Bh = Bhp2; bias = bias2; Chf = Chf2;
    }

    const int nsteps = K / 64;
    const uint32_t SS   = (npass == 2) ? 65536 : 49152;
    const uint32_t BOFF = (npass == 2) ? 32768 : 16384;
    const int ncp = (npass == 2) ? 16 : 12;

    auto issue = [&](int step, int stage) {
        uint32_t stb = sb + stage * SS;
        int k0 = step * 64;
#pragma unroll
        for (int i = 0; i < 16; i++) {
            if (i >= ncp) break;
            int c = i * 256 + tid;
            int tile = c >> 10;
            int w = c & 1023;
            int row = w >> 3, ch = w & 7;
            const __half* src;
            int gr;
            uint32_t tbase;
            if (npass == 2) {
                if      (tile == 0) { src = Ah; gr = m0 + row;        tbase = 0; }
                else if (tile == 1) { src = Al; gr = m0 + row;        tbase = 16384; }
                else if (tile == 2) { src = Bh; gr = n0 + row;        tbase = 32768; }
                else                { src = Bh; gr = n0 + 128 + row;  tbase = 49152; }
            } else {
                if      (tile == 0) { src = Ah; gr = m0 + row;        tbase = 0; }
                else if (tile == 1) { src = Bh; gr = n0 + row;        tbase = 16384; }
                else                { src = Bh; gr = n0 + 128 + row;  tbase = 32768; }
            }
            const __half* gp = src + (long)gr * K + k0 + ch * 8;
            uint32_t dst = stb + tbase + row * 128 + ((ch ^ (row & 7)) << 4);
            CP_ASYNC16(dst, gp);
        }
        CP_COMMIT();
    };

    int mbase = (wid >> 2) * 64;
    int nbase = (wid & 3) * 64;
    int arow = lane & 15;
    int brow = (lane & 7) + ((lane >> 4) & 1) * 8;

    float acc[4][8][4];
#pragma unroll
    for (int mt = 0; mt < 4; mt++)
#pragma unroll
        for (int nt = 0; nt < 8; nt++)
#pragma unroll
            for (int e = 0; e < 4; e++) acc[mt][nt][e] = 0.f;

    issue(0, 0);
    if (nsteps > 1) issue(1, 1);

    for (int step = 0; step < nsteps; step++) {
        if (step + 1 < nsteps) { CP_WAIT(1); } else { CP_WAIT(0); }
        __syncthreads();

        uint32_t stb = sb + (uint32_t)(step & 1) * SS;
#pragma unroll
        for (int k16 = 0; k16 < 4; k16++) {
            uint32_t ahf[4][4], alf[4][4], bhf[4][4];
            int ach = 2 * k16 + (lane >> 4);
#pragma unroll
            for (int mt = 0; mt < 4; mt++) {
                int row = mbase + mt * 16 + arow;
                uint32_t ad = stb + row * 128 + ((ach ^ (row & 7)) << 4);
                LDSM4(ahf[mt], ad);
                if (npass == 2) LDSM4(alf[mt], ad + 16384);
            }
            int bch = 2 * k16 + ((lane >> 3) & 1);
#pragma unroll
            for (int j = 0; j < 4; j++) {
                int row = nbase + j * 16 + brow;
                uint32_t bd = stb + BOFF + row * 128 + ((bch ^ (row & 7)) << 4);
                LDSM4(bhf[j], bd);
            }
#pragma unroll
            for (int mt = 0; mt < 4; mt++)
#pragma unroll
                for (int nt = 0; nt < 8; nt++) {
                    int j = nt >> 1, p = (nt & 1) * 2;
                    MMAH(acc[mt][nt], ahf[mt], bhf[j][p], bhf[j][p+1]);
                }
            if (npass == 2) {
#pragma unroll
                for (int mt = 0; mt < 4; mt++)
#pragma unroll
                    for (int nt = 0; nt < 8; nt++) {
                        int j = nt >> 1, p = (nt & 1) * 2;
                        MMAH(acc[mt][nt], alf[mt], bhf[j][p], bhf[j][p+1]);
                    }
            }
        }
        __syncthreads();
        if (step + 2 < nsteps) issue(step + 2, step & 1);
    }

    // ------------------------------ epilogues ---------------------------------
    if (out_mode == 4) {
        int c0 = n0 + nbase;             // multiple of 64
        int type = c0 >> 10;             // 0=q 1=k 2=v
        int hh = (c0 & 1023) >> 6;       // head index
        const float* wv = (type == 0) ? qw : kw;
        __nv_bfloat16 *ph = (type == 0) ? qh_ : kh_;
        __nv_bfloat16 *pl = (type == 0) ? ql_ : kl_;
#pragma unroll
        for (int mt = 0; mt < 4; mt++) {
            float vals[8][4];
            float ss0 = 0.f, ss1 = 0.f;
            int r0 = m0 + mbase + mt * 16 + (lane >> 2);
#pragma unroll
            for (int nt = 0; nt < 8; nt++) {
                int c = c0 + nt * 8 + 2 * (lane & 3);
                float b0 = bias[c], b1 = bias[c + 1];
                vals[nt][0] = acc[mt][nt][0] + b0;
                vals[nt][1] = acc[mt][nt][1] + b1;
                vals[nt][2] = acc[mt][nt][2] + b0;
                vals[nt][3] = acc[mt][nt][3] + b1;
                ss0 += vals[nt][0]*vals[nt][0] + vals[nt][1]*vals[nt][1];
                ss1 += vals[nt][2]*vals[nt][2] + vals[nt][3]*vals[nt][3];
            }
            ss0 += __shfl_xor_sync(0xffffffffu, ss0, 1, 4);
            ss0 += __shfl_xor_sync(0xffffffffu, ss0, 2, 4);
            ss1 += __shfl_xor_sync(0xffffffffu, ss1, 1, 4);
            ss1 += __shfl_xor_sync(0xffffffffu, ss1, 2, 4);
            float sc0 = 1.f, sc1 = 1.f;
            if (type == 0) {
                sc0 = rsqrtf(ss0 * (1.0f/64.0f) + 1e-6f) * SCALE;
                sc1 = rsqrtf(ss1 * (1.0f/64.0f) + 1e-6f) * SCALE;
            } else if (type == 1) {
                sc0 = rsqrtf(ss0 * (1.0f/64.0f) + 1e-6f);
                sc1 = rsqrtf(ss1 * (1.0f/64.0f) + 1e-6f);
            }
#pragma unroll
            for (int e = 0; e < 2; e++) {
                int r = r0 + 8 * e;
                int b = r >> 9, n = r & 511;
                int g = b >> 2, inst = b & 3;
                long obase = (((long)(g*16 + hh)) * SEQ + inst*512 + n) * HD_;
                float sc = e ? sc1 : sc0;
#pragma unroll
                for (int nt = 0; nt < 8; nt++) {
                    int colh = nt * 8 + 2 * (lane & 3);
                    if (type == 2) {
                        // v: fp16 single
                        *(uint32_t*)&vhf_[obase + colh] =
                            packhf(vals[nt][2*e], vals[nt][2*e+1]);
                    } else {
                        float u0 = vals[nt][2*e]   * sc * wv[colh];
                        float u1 = vals[nt][2*e+1] * sc * wv[colh + 1];
                        uint32_t hp = packbf(u0, u1);
                        uint32_t lp = packbf(u0 - bflo(hp), u1 - bfhi(hp));
                        *(uint32_t*)&ph[obase + colh] = hp;
                        *(uint32_t*)&pl[obase + colh] = lp;
                    }
                }
            }
        }
        return;
    }

    if (out_mode == 3) {
#pragma unroll
        for (int mt = 0; mt < 4; mt++) {
            int r0 = m0 + mbase + mt * 16 + (lane >> 2);
            float ps0 = 0.f, ps1 = 0.f;
#pragma unroll
            for (int nt = 0; nt < 8; nt++) {
                ps0 += 1.0f / (1.0f + __expf(-acc[mt][nt][0] * S2));
                ps0 += 1.0f / (1.0f + __expf(-acc[mt][nt][1] * S2));
                ps1 += 1.0f / (1.0f + __expf(-acc[mt][nt][2] * S2));
                ps1 += 1.0f / (1.0f + __expf(-acc[mt][nt][3] * S2));
            }
            ps0 += __shfl_xor_sync(0xffffffffu, ps0, 1, 4);
            ps0 += __shfl_xor_sync(0xffffffffu, ps0, 2, 4);
            ps1 += __shfl_xor_sync(0xffffffffu, ps1, 1, 4);
            ps1 += __shfl_xor_sync(0xffffffffu, ps1, 2, 4);
            if ((lane & 3) == 0) {
                atomicAdd(&gout[zb * 512 + r0], ps0);
                atomicAdd(&gout[zb * 512 + r0 + 8], ps1);
            }
        }
        return;
    }

#pragma unroll
    for (int mt = 0; mt < 4; mt++) {
        int r0 = m0 + mbase + mt * 16 + (lane >> 2);
        float g0 = 1.f, g1 = 1.f;
        if (out_mode == 2) {
            g0 = 1.0f + grow[r0] * (1.0f/512.0f);
            g1 = 1.0f + grow[r0 + 8] * (1.0f/512.0f);
        }
#pragma unroll
        for (int nt = 0; nt < 8; nt++) {
            int c = n0 + nbase + nt * 8 + 2 * (lane & 3);
            float b0 = 0.f, b1 = 0.f;
            if (bias) { b0 = bias[c]; b1 = bias[c + 1]; }
            float v00 = acc[mt][nt][0] * g0 + b0, v01 = acc[mt][nt][1] * g0 + b1;
            float v10 = acc[mt][nt][2] * g1 + b0, v11 = acc[mt][nt][3] * g1 + b1;
            if (out_mode == 1) {
                *(uint32_t*)&Chf[(long)r0 * N + c]       = packhf(v00, v01);
                *(uint32_t*)&Chf[(long)(r0 + 8) * N + c] = packhf(v10, v11);
            } else {
                float* Cc = C + zb * sC;
                float2 w0; w0.x = v00; w0.y = v01;
                *(float2*)&Cc[(long)r0 * N + c] = w0;
                float2 w1; w1.x = v10; w1.y = v11;
                *(float2*)&Cc[(long)(r0 + 8) * N + c] = w1;
            }
        }
    }
}

// ---------------- weight transpose + fp16 convert (6 weights fused) ----------
__device__ __forceinline__ void wt_split_body(
    const float* __restrict__ W, __half* __restrict__ Th, float (*t)[65])
{
    int n0 = blockIdx.x * 64, k0 = blockIdx.y * 64;
    int tid = threadIdx.x;
#pragma unroll
    for (int it = 0; it < 4; it++) {
        int row = (tid >> 4) + it * 16;
        int c4 = (tid & 15) * 4;
        float4 v = *(const float4*)&W[(long)(k0 + row) * D_ + n0 + c4];
        t[row][c4+0] = v.x; t[row][c4+1] = v.y; t[row][c4+2] = v.z; t[row][c4+3] = v.w;
    }
    __syncthreads();
    int n = tid >> 2, kc = (tid & 3) * 16;
    uint32_t hb[8];
#pragma unroll
    for (int j = 0; j < 16; j += 2)
        hb[j >> 1] = packhf(t[kc + j][n], t[kc + j + 1][n]);
    long obase = (long)(n0 + n) * D_ + k0 + kc;
    *(uint4*)&Th[obase]     = make_uint4(hb[0], hb[1], hb[2], hb[3]);
    *(uint4*)&Th[obase + 8] = make_uint4(hb[4], hb[5], hb[6], hb[7]);
}

__global__ __launch_bounds__(256) void wt_split6_kernel(
    const float* __restrict__ Wq, const float* __restrict__ Wk, const float* __restrict__ Wv,
    const float* __restrict__ Wiq, const float* __restrict__ Wik, const float* __restrict__ Wo,
    __half* __restrict__ wqkvh, __half* __restrict__ wiqh,
    __half* __restrict__ wikh, __half* __restrict__ woh)
{
    __shared__ float t[64][65];
    const float* W;
    __half* Th;
    switch (blockIdx.z) {
        case 0: W = Wq;  Th = wqkvh;             break;
        case 1: W = Wk;  Th = wqkvh + 1024*1024; break;
        case 2: W = Wv;  Th = wqkvh + 2048*1024; break;
        case 3: W = Wiq; Th = wiqh;              break;
        case 4: W = Wik; Th = wikh;              break;
        default: W = Wo; Th = woh;               break;
    }
    wt_split_body(W, Th, t);
}

// ---------------- bias concat (bq|bk|bv) --------------------------------------
__global__ void bias3_kernel(const float* __restrict__ a, const float* __restrict__ b,
                             const float* __restrict__ c, float* __restrict__ o)
{
    int i = blockIdx.x * 256 + threadIdx.x;
    if (i < 1024)       o[i] = a[i];
    else if (i < 2048)  o[i] = b[i - 1024];
    else if (i < 3072)  o[i] = c[i - 2048];
}

// ---------------- activation split (fp16 hi/lo) -------------------------------
__global__ __launch_bounds__(256) void split_kernel(
    const float* __restrict__ src, __half* __restrict__ h,
    __half* __restrict__ l, int n4)
{
    int i = blockIdx.x * 256 + threadIdx.x;
    if (i >= n4) return;
    float4 f = ((const float4*)src)[i];
    uint32_t h0 = packhf(f.x, f.y), h1 = packhf(f.z, f.w);
    ((uint32_t*)h)[i*2+0] = h0;
    ((uint32_t*)h)[i*2+1] = h1;
    ((uint32_t*)l)[i*2+0] = packhf(f.x - hflo(h0), f.y - hfhi(h0));
    ((uint32_t*)l)[i*2+1] = packhf(f.z - hflo(h1), f.w - hfhi(h1));
}

// ---------------- flash attention: S bf16 3-pass, PV fp16 2-pass --------------
// SMEM: 2 stages x {Kh,Kl bf16, Vh fp16}[128x64] (48KB each) + {Qh,Ql} (32KB)
#define FL_SMEM (2*49152 + 32768)   // 131072
__global__ __launch_bounds__(256, 1)
void flash_mma_kernel(const __nv_bfloat16* __restrict__ Qh_, const __nv_bfloat16* __restrict__ Ql_,
                      const __nv_bfloat16* __restrict__ Kh_, const __nv_bfloat16* __restrict__ Kl_,
                      const __half* __restrict__ Vh_,
                      __half* __restrict__ Oh, __half* __restrict__ Ol)
{
    extern __shared__ char smem[];
    uint32_t sb = smem_u32(smem);
    int tid = threadIdx.x, wid = tid >> 5, lane = tid & 31;
    int qt = blockIdx.x, gh = blockIdx.y;
    long ghoff = (long)gh * SEQ * HD_;
    const __nv_bfloat16* Qh = Qh_ + ghoff + (long)qt * 128 * HD_;
    const __nv_bfloat16* Ql = Ql_ + ghoff + (long)qt * 128 * HD_;
    const __nv_bfloat16* Kh = Kh_ + ghoff;
    const __nv_bfloat16* Kl = Kl_ + ghoff;
    const __half*        Vh = Vh_ + ghoff;

    const uint32_t QOFF = 98304;

    {
#pragma unroll
        for (int i = 0; i < 8; i++) {
            int c = i * 256 + tid;
            int arr = c >> 10, w = c & 1023, row = w >> 3, ch = w & 7;
            const __nv_bfloat16* src = (arr ? Ql : Qh) + (long)row * 64 + ch * 8;
            uint32_t dst = sb + QOFF + arr * 16384 + row * 128 + ((ch ^ (row & 7)) << 4);
            CP_ASYNC16(dst, src);
        }
        CP_COMMIT();
    }

    auto issueKV = [&](int it, int stage) {
        uint32_t stb = sb + stage * 49152;
#pragma unroll
        for (int i = 0; i < 12; i++) {
            int c = i * 256 + tid;
            int arr = c >> 10, w = c & 1023, row = w >> 3, ch = w & 7;
            uint32_t dst = stb + arr * 16384 + row * 128 + ((ch ^ (row & 7)) << 4);
            if (arr == 2) {
                const __half* src = Vh + (long)(it * 128 + row) * 64 + ch * 8;
                CP_ASYNC16(dst, src);
            } else {
                const __nv_bfloat16* src = (arr ? Kl : Kh) + (long)(it * 128 + row) * 64 + ch * 8;
                CP_ASYNC16(dst, src);
            }
        }
        CP_COMMIT();
    };

    issueKV(0, 0);
    issueKV(1, 1);
    CP_WAIT(1);
    __syncthreads();

    uint32_t qhf[4][4], qlf[4][4];
    {
        int arow = lane & 15;
#pragma unroll
        for (int kt = 0; kt < 4; kt++) {
            int row = wid * 16 + arow;
            int ach = 2 * kt + (lane >> 4);
            uint32_t ad = sb + QOFF + row * 128 + ((ach ^ (row & 7)) << 4);
            LDSM4(qhf[kt], ad);
            LDSM4(qlf[kt], ad + 16384);
        }
    }

    float o[8][4];
#pragma unroll
    for (int nt = 0; nt < 8; nt++)
#pragma unroll
        for (int e = 0; e < 4; e++) o[nt][e] = 0.f;
    float m0 = -1e30f, m1 = -1e30f, lp0 = 0.f, lp1 = 0.f;

    for (int it = 0; it < 16; it++) {
        if (it > 0) {
            if (it < 15) { CP_WAIT(1); } else { CP_WAIT(0); }
            __syncthreads();
        }
        uint32_t stb = sb + (it & 1) * 49152;

        float s[16][4];
#pragma unroll
        for (int t = 0; t < 16; t++)
#pragma unroll
            for (int e = 0; e < 4; e++) s[t][e] = 0.f;

        int brow = (lane & 7) + ((lane >> 4) & 1) * 8;
#pragma unroll
        for (int kt = 0; kt < 4; kt++) {
            int bch = 2 * kt + ((lane >> 3) & 1);
#pragma unroll
            for (int jp = 0; jp < 4; jp++) {
                uint32_t khf[2][4], klf[2][4];
#pragma unroll
                for (int j = 0; j < 2; j++) {
                    int row = (2 * jp + j) * 16 + brow;
                    uint32_t bd = stb + row * 128 + ((bch ^ (row & 7)) << 4);
                    LDSM4(khf[j], bd);
                    LDSM4(klf[j], bd + 16384);
                }
                int t0 = 4 * jp;
                MMAB(s[t0+0], qhf[kt], khf[0][0], khf[0][1]);
                MMAB(s[t0+1], qhf[kt], khf[0][2], khf[0][3]);
                MMAB(s[t0+2], qhf[kt], khf[1][0], khf[1][1]);
                MMAB(s[t0+3], qhf[kt], khf[1][2], khf[1][3]);
                MMAB(s[t0+0], qhf[kt], klf[0][0], klf[0][1]);
                MMAB(s[t0+1], qhf[kt], klf[0][2], klf[0][3]);
                MMAB(s[t0+2], qhf[kt], klf[1][0], klf[1][1]);
                MMAB(s[t0+3], qhf[kt], klf[1][2], klf[1][3]);
                MMAB(s[t0+0], qlf[kt], khf[0][0], khf[0][1]);
                MMAB(s[t0+1], qlf[kt], khf[0][2], khf[0][3]);
                MMAB(s[t0+2], qlf[kt], khf[1][0], khf[1][1]);
                MMAB(s[t0+3], qlf[kt], khf[1][2], khf[1][3]);
            }
        }

        float t0 = -1e30f, t1 = -1e30f;
#pragma unroll
        for (int t = 0; t < 16; t++) {
            t0 = fmaxf(t0, fmaxf(s[t][0], s[t][1]));
            t1 = fmaxf(t1, fmaxf(s[t][2], s[t][3]));
        }
        t0 = fmaxf(t0, __shfl_xor_sync(0xffffffffu, t0, 1, 4));
        t0 = fmaxf(t0, __shfl_xor_sync(0xffffffffu, t0, 2, 4));
        t1 = fmaxf(t1, __shfl_xor_sync(0xffffffffu, t1, 1, 4));
        t1 = fmaxf(t1, __shfl_xor_sync(0xffffffffu, t1, 2, 4));
        float mn0 = fmaxf(m0, t0), mn1 = fmaxf(m1, t1);
        float c0 = __expf(m0 - mn0), c1 = __expf(m1 - mn1);
        m0 = mn0; m1 = mn1;
        lp0 *= c0; lp1 *= c1;
#pragma unroll
        for (int nt = 0; nt < 8; nt++) {
            o[nt][0] *= c0; o[nt][1] *= c0;
            o[nt][2] *= c1; o[nt][3] *= c1;
        }
#pragma unroll
        for (int t = 0; t < 16; t++) {
            s[t][0] = __expf(s[t][0] - m0);
            s[t][1] = __expf(s[t][1] - m0);
            s[t][2] = __expf(s[t][2] - m1);
            s[t][3] = __expf(s[t][3] - m1);
            lp0 += s[t][0] + s[t][1];
            lp1 += s[t][2] + s[t][3];
        }

        // ---- O += P @ V : fp16 2-pass (P hi/lo fp16, V fp16) ----
        int vrow = lane & 15;
#pragma unroll
        for (int kt = 0; kt < 8; kt++) {
            uint32_t pha[4], pla[4];
#pragma unroll
            for (int q = 0; q < 2; q++) {
                float a0 = s[2*kt + q][0], a1 = s[2*kt + q][1];
                float a2 = s[2*kt + q][2], a3 = s[2*kt + q][3];
                uint32_t h0 = packhf(a0, a1);
                uint32_t h1 = packhf(a2, a3);
                pha[2*q]   = h0;
                pha[2*q+1] = h1;
                pla[2*q]   = packhf(a0 - hflo(h0), a1 - hfhi(h0));
                pla[2*q+1] = packhf(a2 - hflo(h1), a3 - hfhi(h1));
            }
            int row = kt * 16 + vrow;
#pragma unroll
            for (int np = 0; np < 2; np++) {
                uint32_t vhf[2][4];
#pragma unroll
                for (int j = 0; j < 2; j++) {
                    int ch = 2 * (2 * np + j) + (lane >> 4);
                    uint32_t vd = stb + 32768 + row * 128 + ((ch ^ (row & 7)) << 4);
                    LDSM4T(vhf[j], vd);
                }
                int ob = 4 * np;
                MMAH(o[ob+0], pha, vhf[0][0], vhf[0][1]);
                MMAH(o[ob+1], pha, vhf[0][2], vhf[0][3]);
                MMAH(o[ob+2], pha, vhf[1][0], vhf[1][1]);
                MMAH(o[ob+3], pha, vhf[1][2], vhf[1][3]);
                MMAH(o[ob+0], pla, vhf[0][0], vhf[0][1]);
                MMAH(o[ob+1], pla, vhf[0][2], vhf[0][3]);
                MMAH(o[ob+2], pla, vhf[1][0], vhf[1][1]);
                MMAH(o[ob+3], pla, vhf[1][2], vhf[1][3]);
            }
        }

        __syncthreads();
        if (it + 2 < 16) issueKV(it + 2, it & 1);
    }

    lp0 += __shfl_xor_sync(0xffffffffu, lp0, 1, 4);
    lp0 += __shfl_xor_sync(0xffffffffu, lp0, 2, 4);
    lp1 += __shfl_xor_sync(0xffffffffu, lp1, 1, 4);
    lp1 += __shfl_xor_sync(0xffffffffu, lp1, 2, 4);
    float inv0 = 1.0f / lp0, inv1 = 1.0f / lp1;

    int g = gh >> 4, h = gh & 15;
#pragma unroll
    for (int e = 0; e < 2; e++) {
        int r = qt * 128 + wid * 16 + (lane >> 2) + 8 * e;
        int inst = r >> 9, n = r & 511;
        int b = g * 4 + inst;
        float inv = e ? inv1 : inv0;
        long base = ((long)(b * 512 + n)) * D_ + h * HD_;
#pragma unroll
        for (int nt = 0; nt < 8; nt++) {
            float v0 = o[nt][2*e] * inv, v1 = o[nt][2*e+1] * inv;
            uint32_t hp = packhf(v0, v1);
            uint32_t lp = packhf(v0 - hflo(hp), v1 - hfhi(hp));
            long idx = base + nt * 8 + 2 * (lane & 3);
            *(uint32_t*)&Oh[idx] = hp;
            *(uint32_t*)&Ol[idx] = lp;
        }
    }
}

// ---------------- instance feature -> fp16 ------------------------------------
__global__ __launch_bounds__(256) void feat_kernel(
    const float* __restrict__ mask, const float* __restrict__ embed,
    __half* __restrict__ fh)
{
    int row = blockIdx.x;
    float m0 = mask[row*4+0], m1 = mask[row*4+1];
    float m2 = mask[row*4+2], m3 = mask[row*4+3];
    for (int c = threadIdx.x * 2; c < D_; c += 512) {
        float f0 = m0*embed[c]   + m1*embed[D_ + c]   + m2*embed[2*D_ + c]   + m3*embed[3*D_ + c];
        float f1 = m0*embed[c+1] + m1*embed[D_ + c+1] + m2*embed[2*D_ + c+1] + m3*embed[3*D_ + c+1];
        *(uint32_t*)&fh[(long)row*D_ + c] = packhf(f0, f1);
    }
}

__global__ void zero_kernel(float* __restrict__ p, int n)
{
    int i = blockIdx.x * blockDim.x + threadIdx.x;
    if (i < n) p[i] = 0.f;
}

// ------------------------------- launch --------------------------------------
extern "C" void kernel_launch(void* const* d_in, const int* in_sizes, int n_in,
                              void* d_out, int out_size)
{
    const float* x     = (const float*)d_in[0];
    const float* mask  = (const float*)d_in[1];
    const float* Wq    = (const float*)d_in[2];
    const float* bq    = (const float*)d_in[3];
    const float* Wk    = (const float*)d_in[4];
    const float* bk    = (const float*)d_in[5];
    const float* Wv    = (const float*)d_in[6];
    const float* bv    = (const float*)d_in[7];
    const float* Wo    = (const float*)d_in[8];
    const float* bo    = (const float*)d_in[9];
    const float* Wiq   = (const float*)d_in[10];
    const float* biq   = (const float*)d_in[11];
    const float* Wik   = (const float*)d_in[12];
    const float* bik   = (const float*)d_in[13];
    const float* embed = (const float*)d_in[14];
    const float* qw    = (const float*)d_in[15];
    const float* kw    = (const float*)d_in[16];
    float* out = (float*)d_out;

    float *gacc,*bqkv;
    cudaGetSymbolAddress((void**)&gacc, g_gacc);
    cudaGetSymbolAddress((void**)&bqkv, g_bqkv);

    __nv_bfloat16 *qhg,*qlg,*khg,*klg;
    __half *vhg;
    cudaGetSymbolAddress((void**)&qhg, g_qhg);   cudaGetSymbolAddress((void**)&qlg, g_qlg);
    cudaGetSymbolAddress((void**)&khg, g_khg);   cudaGetSymbolAddress((void**)&klg, g_klg);
    cudaGetSymbolAddress((void**)&vhg, g_vhg);

    __half *wqkvh,*wiqh,*wikh,*woh,*xh,*xl,*ah,*al,*fh,*iqh,*ikh;
    cudaGetSymbolAddress((void**)&wqkvh, g_wqkvh);
    cudaGetSymbolAddress((void**)&wiqh, g_wiqh);
    cudaGetSymbolAddress((void**)&wikh, g_wikh);
    cudaGetSymbolAddress((void**)&woh, g_woh);
    cudaGetSymbolAddress((void**)&xh, g_xh);       cudaGetSymbolAddress((void**)&xl, g_xl);
    cudaGetSymbolAddress((void**)&ah, g_ah);       cudaGetSymbolAddress((void**)&al, g_al);
    cudaGetSymbolAddress((void**)&fh, g_fh);
    cudaGetSymbolAddress((void**)&iqh, g_iqh);     cudaGetSymbolAddress((void**)&ikh, g_ikh);

    cudaFuncSetAttribute((const void*)mma_gemm_kernel,
                         cudaFuncAttributeMaxDynamicSharedMemorySize, TC_SMEM_2P);
    cudaFuncSetAttribute((const void*)flash_mma_kernel,
                         cudaFuncAttributeMaxDynamicSharedMemorySize, FL_SMEM);

    const int N4 = MROWS * D_ / 4;
    const int SPLIT_BLOCKS = (N4 + 255) / 256;

    // launches 1-3
    wt_split6_kernel<<<dim3(16, 16, 6), 256>>>(Wq, Wk, Wv, Wiq, Wik, Wo,
                                               wqkvh, wiqh, wikh, woh);
    bias3_kernel<<<12, 256>>>(bq, bk, bv, bqkv);
    split_kernel<<<SPLIT_BLOCKS, 256>>>(x, xh, xl, N4);

    // launch #4 (profiled): fused QKV projection (fp16 2-pass) + RMS epilogue
    mma_gemm_kernel<<<dim3(D3/256, MROWS/128), 256, TC_SMEM_2P>>>(
        xh, xl, wqkvh, bqkv, nullptr, nullptr, nullptr, nullptr,
        nullptr, nullptr, nullptr, nullptr,
        qw, kw, qhg, qlg, khg, klg, vhg,
        MROWS, D3, D_, 0, 0, 0, 2, 4);

    // small prep
    zero_kernel<<<(MROWS+255)/256, 256>>>(gacc, MROWS);
    feat_kernel<<<MROWS, 256>>>(mask, embed, fh);

    // attention (S bf16 3-pass, PV fp16 2-pass; emits fp16 ah/al)
    flash_mma_kernel<<<dim3(SEQ/128, GH), 256, FL_SMEM>>>(qhg, qlg, khg, klg, vhg, ah, al);

    // iq & ik projections fused (fp16 1-pass; z selects operand set)
    mma_gemm_kernel<<<dim3(D_/256, MROWS/128, 2), 256, TC_SMEM_1P>>>(
        ah, nullptr, wiqh, biq, nullptr, iqh, nullptr, nullptr,
        fh, wikh, bik, ikh,
        nullptr, nullptr, nullptr, nullptr, nullptr, nullptr, nullptr,
        MROWS, D_, D_, 0, 0, 0, 1, 1);

    // gate: per-batch iq @ ik^T (fp16 1-pass) with fused sigmoid row-sum
    mma_gemm_kernel<<<dim3(2, 4, 8), 256, TC_SMEM_1P>>>(
        iqh, nullptr, ikh, nullptr, nullptr, nullptr, nullptr, gacc,
        nullptr, nullptr, nullptr, nullptr,
        nullptr, nullptr, nullptr, nullptr, nullptr, nullptr, nullptr,
        512, 512, D_, (long)512*D_, (long)512*D_, 0, 1, 3);

    // gated output projection (fp16 2-pass): out = diag(1+gacc/512)*(attn@Wo)+bo
    mma_gemm_kernel<<<dim3(D_/256, MROWS/128), 256, TC_SMEM_2P>>>(
        ah, al, woh, bo, out, nullptr, gacc, nullptr,
        nullptr, nullptr, nullptr, nullptr,
        nullptr, nullptr, nullptr, nullptr, nullptr, nullptr, nullptr,
        MROWS, D_, D_, 0, 0, 0, 2, 2);
}

// round 12
// speedup vs baseline: 1.3031x; 1.0006x over previous
#include <cuda_runtime.h>
#include <cuda_bf16.h>
#include <cuda_fp16.h>
#include <math.h>
#include <stdint.h>

// Problem constants
#define B_    8
#define N_    512
#define D_    1024
#define H_    16
#define HD_   64
#define NI_   4
#define G_    2
#define MROWS (B_*N_)      // 4096
#define SEQ   (NI_*N_)     // 2048
#define GH    (G_*H_)      // 32
#define D3    3072
#define SCALE 0.125f
#define S2    0.0078125f   // SCALE / H

// ---------------- scratch (device globals) -----------------------------------
static __device__ float g_gacc[MROWS];
static __device__ float g_bqkv[D3];

// attention operands, grouped [GH, SEQ, HD]: q/k bf16 hi/lo (3-pass S), v fp16
#define AELEMS (GH*SEQ*HD_)
static __device__ __align__(256) __nv_bfloat16 g_qhg[AELEMS], g_qlg[AELEMS];
static __device__ __align__(256) __nv_bfloat16 g_khg[AELEMS], g_klg[AELEMS];
static __device__ __align__(256) __half g_vhg[AELEMS];

// fp16 weights (hi only) and fp16 activations (hi/lo where needed)
static __device__ __align__(256) __half g_wqkvh[D3*D_];
static __device__ __align__(256) __half g_wiqh[D_*D_];
static __device__ __align__(256) __half g_wikh[D_*D_];
static __device__ __align__(256) __half g_woh[D_*D_];
static __device__ __align__(256) __half g_xh[MROWS*D_],  g_xl[MROWS*D_];
static __device__ __align__(256) __half g_ah[MROWS*D_],  g_al[MROWS*D_];   // attn hi/lo
static __device__ __align__(256) __half g_fh[MROWS*D_];
static __device__ __align__(256) __half g_iqh[MROWS*D_];
static __device__ __align__(256) __half g_ikh[MROWS*D_];

// ---------------- PTX helpers --------------------------------------------------
__device__ __forceinline__ uint32_t smem_u32(const void* p) {
    uint32_t a;
    asm("{ .reg .u64 t; cvta.to.shared.u64 t, %1; cvt.u32.u64 %0, t; }"
        : "=r"(a) : "l"(p));
    return a;
}

#define LDSM4(r, addr) \
    asm volatile("ldmatrix.sync.aligned.m8n8.x4.shared.b16 {%0,%1,%2,%3}, [%4];" \
        : "=r"((r)[0]), "=r"((r)[1]), "=r"((r)[2]), "=r"((r)[3]) : "r"(addr))

#define LDSM4T(r, addr) \
    asm volatile("ldmatrix.sync.aligned.m8n8.x4.trans.shared.b16 {%0,%1,%2,%3}, [%4];" \
        : "=r"((r)[0]), "=r"((r)[1]), "=r"((r)[2]), "=r"((r)[3]) : "r"(addr))

// bf16 MMA (flash S)
#define MMAB(d, a, bv0, bv1) \
    asm volatile("mma.sync.aligned.m16n8k16.row.col.f32.bf16.bf16.f32 " \
        "{%0,%1,%2,%3}, {%4,%5,%6,%7}, {%8,%9}, {%0,%1,%2,%3};" \
        : "+f"((d)[0]), "+f"((d)[1]), "+f"((d)[2]), "+f"((d)[3]) \
        : "r"((a)[0]), "r"((a)[1]), "r"((a)[2]), "r"((a)[3]), "r"(bv0), "r"(bv1))

// fp16 MMA (projection GEMMs + flash PV)
#define MMAH(d, a, bv0, bv1) \
    asm volatile("mma.sync.aligned.m16n8k16.row.col.f32.f16.f16.f32 " \
        "{%0,%1,%2,%3}, {%4,%5,%6,%7}, {%8,%9}, {%0,%1,%2,%3};" \
        : "+f"((d)[0]), "+f"((d)[1]), "+f"((d)[2]), "+f"((d)[3]) \
        : "r"((a)[0]), "r"((a)[1]), "r"((a)[2]), "r"((a)[3]), "r"(bv0), "r"(bv1))

#define CP_ASYNC16(dst, src) \
    asm volatile("cp.async.cg.shared.global [%0], [%1], 16;" \
        :: "r"(dst), "l"(__cvta_generic_to_global(src)) : "memory")
#define CP_COMMIT() asm volatile("cp.async.commit_group;" ::: "memory")
#define CP_WAIT(n)  asm volatile("cp.async.wait_group %0;" :: "n"(n) : "memory")

__device__ __forceinline__ uint32_t packbf(float a, float b) {
    uint32_t d;
    asm("cvt.rn.bf16x2.f32 %0, %1, %2;" : "=r"(d) : "f"(b), "f"(a));
    return d;
}
__device__ __forceinline__ float bflo(uint32_t v) { return __uint_as_float(v << 16); }
__device__ __forceinline__ float bfhi(uint32_t v) { return __uint_as_float(v & 0xffff0000u); }

__device__ __forceinline__ uint32_t packhf(float a, float b) {
    __half2 t = __floats2half2_rn(a, b);   // low = a, high = b
    return *reinterpret_cast<uint32_t*>(&t);
}
__device__ __forceinline__ float hflo(uint32_t v) {
    __half2 t = *reinterpret_cast<__half2*>(&v);
    return __low2float(t);
}
__device__ __forceinline__ float hfhi(uint32_t v) {
    __half2 t = *reinterpret_cast<__half2*>(&v);
    return __high2float(t);
}

// -------- fp16 HMMA GEMM: CTA 128x256, warp 64x64, 3-stage ring, 1 sync/step --
// out_mode: 0 fp32 C+bias; 1 fp16 Chf (+bias, z selects operand set);
//           2 fp32 gate-scaled; 3 sigmoid row-sum atomics into gout;
//           4 QKV epilogue: bias + per-head RMS norm (q,k, bf16 hi/lo) + v fp16.
#define TC_SMEM_2P (3*65536)   // 196608
#define TC_SMEM_1P (3*49152)   // 147456
__global__ __launch_bounds__(256, 1)
void mma_gemm_kernel(const __half* __restrict__ Ahp, const __half* __restrict__ Alp,
                     const __half* __restrict__ Bhp,
                     const float* __restrict__ bias, float* __restrict__ C,
                     __half* __restrict__ Chf,
                     const float* __restrict__ grow, float* __restrict__ gout,
                     const __half* __restrict__ Ahp2, const __half* __restrict__ Bhp2,
                     const float* __restrict__ bias2, __half* __restrict__ Chf2,
                     const float* __restrict__ qw, const float* __restrict__ kw,
                     __nv_bfloat16* __restrict__ qh_, __nv_bfloat16* __restrict__ ql_,
                     __nv_bfloat16* __restrict__ kh_, __nv_bfloat16* __restrict__ kl_,
                     __half* __restrict__ vhf_,
                     int M, int N, int K, long sA, long sB, long sC,
                     int npass, int out_mode)
{
    extern __shared__ char smem[];
    uint32_t sb = smem_u32(smem);
    int tid = threadIdx.x, wid = tid >> 5, lane = tid & 31;
    int m0 = blockIdx.y * 128, n0 = blockIdx.x * 256;
    long zb = blockIdx.z;
    const __half* Ah = Ahp + zb * sA;
    const __half* Al = (npass == 2) ? (Alp + zb * sA) : Ahp;
    const __half* Bh = Bhp + zb * sB;
    if (out_mode == 1 && blockIdx.z == 1) {
        Ah = Ahp2; Bh = Bhp2; bias = bias2; Chf = Chf2;
    }

    const int nsteps = K / 64;
    const uint32_t SS   = (npass == 2) ? 65536 : 49152;
    const uint32_t BOFF = (npass == 2) ? 32768 : 16384;
    const int ncp = (npass == 2) ? 16 : 12;

    auto issue = [&](int step, int stage) {
        uint32_t stb = sb + stage * SS;
        int k0 = step * 64;
#pragma unroll
        for (int i = 0; i < 16; i++) {
            if (i >= ncp) break;
            int c = i * 256 + tid;
            int tile = c >> 10;
            int w = c & 1023;
            int row = w >> 3, ch = w & 7;
            const __half* src;
            int gr;
            uint32_t tbase;
            if (npass == 2) {
                if      (tile == 0) { src = Ah; gr = m0 + row;        tbase = 0; }
                else if (tile == 1) { src = Al; gr = m0 + row;        tbase = 16384; }
                else if (tile == 2) { src = Bh; gr = n0 + row;        tbase = 32768; }
                else                { src = Bh; gr = n0 + 128 + row;  tbase = 49152; }
            } else {
                if      (tile == 0) { src = Ah; gr = m0 + row;        tbase = 0; }
                else if (tile == 1) { src = Bh; gr = n0 + row;        tbase = 16384; }
                else                { src = Bh; gr = n0 + 128 + row;  tbase = 32768; }
            }
            const __half* gp = src + (long)gr * K + k0 + ch * 8;
            uint32_t dst = stb + tbase + row * 128 + ((ch ^ (row & 7)) << 4);
            CP_ASYNC16(dst, gp);
        }
        CP_COMMIT();
    };

    int mbase = (wid >> 2) * 64;
    int nbase = (wid & 3) * 64;
    int arow = lane & 15;
    int brow = (lane & 7) + ((lane >> 4) & 1) * 8;

    float acc[4][8][4];
#pragma unroll
    for (int mt = 0; mt < 4; mt++)
#pragma unroll
        for (int nt = 0; nt < 8; nt++)
#pragma unroll
            for (int e = 0; e < 4; e++) acc[mt][nt][e] = 0.f;

    issue(0, 0);
    if (nsteps > 1) issue(1, 1);

    for (int step = 0; step < nsteps; step++) {
        if (step + 1 < nsteps) { CP_WAIT(1); } else { CP_WAIT(0); }
        // single barrier per step: proves stage step%3 data visible AND all
        // warps finished step-1 reads of stage (step+2)%3 (the issue target).
        __syncthreads();
        if (step + 2 < nsteps) issue(step + 2, (step + 2) % 3);

        uint32_t stb = sb + (uint32_t)(step % 3) * SS;
#pragma unroll
        for (int k16 = 0; k16 < 4; k16++) {
            uint32_t ahf[4][4], alf[4][4], bhf[4][4];
            int ach = 2 * k16 + (lane >> 4);
#pragma unroll
            for (int mt = 0; mt < 4; mt++) {
                int row = mbase + mt * 16 + arow;
                uint32_t ad = stb + row * 128 + ((ach ^ (row & 7)) << 4);
                LDSM4(ahf[mt], ad);
                if (npass == 2) LDSM4(alf[mt], ad + 16384);
            }
            int bch = 2 * k16 + ((lane >> 3) & 1);
#pragma unroll
            for (int j = 0; j < 4; j++) {
                int row = nbase + j * 16 + brow;
                uint32_t bd = stb + BOFF + row * 128 + ((bch ^ (row & 7)) << 4);
                LDSM4(bhf[j], bd);
            }
#pragma unroll
            for (int mt = 0; mt < 4; mt++)
#pragma unroll
                for (int nt = 0; nt < 8; nt++) {
                    int j = nt >> 1, p = (nt & 1) * 2;
                    MMAH(acc[mt][nt], ahf[mt], bhf[j][p], bhf[j][p+1]);
                }
            if (npass == 2) {
#pragma unroll
                for (int mt = 0; mt < 4; mt++)
#pragma unroll
                    for (int nt = 0; nt < 8; nt++) {
                        int j = nt >> 1, p = (nt & 1) * 2;
                        MMAH(acc[mt][nt], alf[mt], bhf[j][p], bhf[j][p+1]);
                    }
            }
        }
    }

    // ------------------------------ epilogues ---------------------------------
    if (out_mode == 4) {
        int c0 = n0 + nbase;             // multiple of 64
        int type = c0 >> 10;             // 0=q 1=k 2=v
        int hh = (c0 & 1023) >> 6;       // head index
        const float* wv = (type == 0) ? qw : kw;
        __nv_bfloat16 *ph = (type == 0) ? qh_ : kh_;
        __nv_bfloat16 *pl = (type == 0) ? ql_ : kl_;
#pragma unroll
        for (int mt = 0; mt < 4; mt++) {
            float vals[8][4];
            float ss0 = 0.f, ss1 = 0.f;
            int r0 = m0 + mbase + mt * 16 + (lane >> 2);
#pragma unroll
            for (int nt = 0; nt < 8; nt++) {
                int c = c0 + nt * 8 + 2 * (lane & 3);
                float b0 = bias[c], b1 = bias[c + 1];
                vals[nt][0] = acc[mt][nt][0] + b0;
                vals[nt][1] = acc[mt][nt][1] + b1;
                vals[nt][2] = acc[mt][nt][2] + b0;
                vals[nt][3] = acc[mt][nt][3] + b1;
                ss0 += vals[nt][0]*vals[nt][0] + vals[nt][1]*vals[nt][1];
                ss1 += vals[nt][2]*vals[nt][2] + vals[nt][3]*vals[nt][3];
            }
            ss0 += __shfl_xor_sync(0xffffffffu, ss0, 1, 4);
            ss0 += __shfl_xor_sync(0xffffffffu, ss0, 2, 4);
            ss1 += __shfl_xor_sync(0xffffffffu, ss1, 1, 4);
            ss1 += __shfl_xor_sync(0xffffffffu, ss1, 2, 4);
            float sc0 = 1.f, sc1 = 1.f;
            if (type == 0) {
                sc0 = rsqrtf(ss0 * (1.0f/64.0f) + 1e-6f) * SCALE;
                sc1 = rsqrtf(ss1 * (1.0f/64.0f) + 1e-6f) * SCALE;
            } else if (type == 1) {
                sc0 = rsqrtf(ss0 * (1.0f/64.0f) + 1e-6f);
                sc1 = rsqrtf(ss1 * (1.0f/64.0f) + 1e-6f);
            }
#pragma unroll
            for (int e = 0; e < 2; e++) {
                int r = r0 + 8 * e;
                int b = r >> 9, n = r & 511;
                int g = b >> 2, inst = b & 3;
                long obase = (((long)(g*16 + hh)) * SEQ + inst*512 + n) * HD_;
                float sc = e ? sc1 : sc0;
#pragma unroll
                for (int nt = 0; nt < 8; nt++) {
                    int colh = nt * 8 + 2 * (lane & 3);
                    if (type == 2) {
                        *(uint32_t*)&vhf_[obase + colh] =
                            packhf(vals[nt][2*e], vals[nt][2*e+1]);
                    } else {
                        float u0 = vals[nt][2*e]   * sc * wv[colh];
                        float u1 = vals[nt][2*e+1] * sc * wv[colh + 1];
                        uint32_t hp = packbf(u0, u1);
                        uint32_t lp = packbf(u0 - bflo(hp), u1 - bfhi(hp));
                        *(uint32_t*)&ph[obase + colh] = hp;
                        *(uint32_t*)&pl[obase + colh] = lp;
                    }
                }
            }
        }
        return;
    }

    if (out_mode == 3) {
#pragma unroll
        for (int mt = 0; mt < 4; mt++) {
            int r0 = m0 + mbase + mt * 16 + (lane >> 2);
            float ps0 = 0.f, ps1 = 0.f;
#pragma unroll
            for (int nt = 0; nt < 8; nt++) {
                ps0 += 1.0f / (1.0f + __expf(-acc[mt][nt][0] * S2));
                ps0 += 1.0f / (1.0f + __expf(-acc[mt][nt][1] * S2));
                ps1 += 1.0f / (1.0f + __expf(-acc[mt][nt][2] * S2));
                ps1 += 1.0f / (1.0f + __expf(-acc[mt][nt][3] * S2));
            }
            ps0 += __shfl_xor_sync(0xffffffffu, ps0, 1, 4);
            ps0 += __shfl_xor_sync(0xffffffffu, ps0, 2, 4);
            ps1 += __shfl_xor_sync(0xffffffffu, ps1, 1, 4);
            ps1 += __shfl_xor_sync(0xffffffffu, ps1, 2, 4);
            if ((lane & 3) == 0) {
                atomicAdd(&gout[zb * 512 + r0], ps0);
                atomicAdd(&gout[zb * 512 + r0 + 8], ps1);
            }
        }
        return;
    }

#pragma unroll
    for (int mt = 0; mt < 4; mt++) {
        int r0 = m0 + mbase + mt * 16 + (lane >> 2);
        float g0 = 1.f, g1 = 1.f;
        if (out_mode == 2) {
            g0 = 1.0f + grow[r0] * (1.0f/512.0f);
            g1 = 1.0f + grow[r0 + 8] * (1.0f/512.0f);
        }
#pragma unroll
        for (int nt = 0; nt < 8; nt++) {
            int c = n0 + nbase + nt * 8 + 2 * (lane & 3);
            float b0 = 0.f, b1 = 0.f;
            if (bias) { b0 = bias[c]; b1 = bias[c + 1]; }
            float v00 = acc[mt][nt][0] * g0 + b0, v01 = acc[mt][nt][1] * g0 + b1;
            float v10 = acc[mt][nt][2] * g1 + b0, v11 = acc[mt][nt][3] * g1 + b1;
            if (out_mode == 1) {
                *(uint32_t*)&Chf[(long)r0 * N + c]       = packhf(v00, v01);
                *(uint32_t*)&Chf[(long)(r0 + 8) * N + c] = packhf(v10, v11);
            } else {
                float* Cc = C + zb * sC;
                float2 w0; w0.x = v00; w0.y = v01;
                *(float2*)&Cc[(long)r0 * N + c] = w0;
                float2 w1; w1.x = v10; w1.y = v11;
                *(float2*)&Cc[(long)(r0 + 8) * N + c] = w1;
            }
        }
    }
}

// ---------------- weight transpose + fp16 convert (6 weights fused) ----------
__device__ __forceinline__ void wt_split_body(
    const float* __restrict__ W, __half* __restrict__ Th, float (*t)[65])
{
    int n0 = blockIdx.x * 64, k0 = blockIdx.y * 64;
    int tid = threadIdx.x;
#pragma unroll
    for (int it = 0; it < 4; it++) {
        int row = (tid >> 4) + it * 16;
        int c4 = (tid & 15) * 4;
        float4 v = *(const float4*)&W[(long)(k0 + row) * D_ + n0 + c4];
        t[row][c4+0] = v.x; t[row][c4+1] = v.y; t[row][c4+2] = v.z; t[row][c4+3] = v.w;
    }
    __syncthreads();
    int n = tid >> 2, kc = (tid & 3) * 16;
    uint32_t hb[8];
#pragma unroll
    for (int j = 0; j < 16; j += 2)
        hb[j >> 1] = packhf(t[kc + j][n], t[kc + j + 1][n]);
    long obase = (long)(n0 + n) * D_ + k0 + kc;
    *(uint4*)&Th[obase]     = make_uint4(hb[0], hb[1], hb[2], hb[3]);
    *(uint4*)&Th[obase + 8] = make_uint4(hb[4], hb[5], hb[6], hb[7]);
}

__global__ __launch_bounds__(256) void wt_split6_kernel(
    const float* __restrict__ Wq, const float* __restrict__ Wk, const float* __restrict__ Wv,
    const float* __restrict__ Wiq, const float* __restrict__ Wik, const float* __restrict__ Wo,
    __half* __restrict__ wqkvh, __half* __restrict__ wiqh,
    __half* __restrict__ wikh, __half* __restrict__ woh)
{
    __shared__ float t[64][65];
    const float* W;
    __half* Th;
    switch (blockIdx.z) {
        case 0: W = Wq;  Th = wqkvh;             break;
        case 1: W = Wk;  Th = wqkvh + 1024*1024; break;
        case 2: W = Wv;  Th = wqkvh + 2048*1024; break;
        case 3: W = Wiq; Th = wiqh;              break;
        case 4: W = Wik; Th = wikh;              break;
        default: W = Wo; Th = woh;               break;
    }
    wt_split_body(W, Th, t);
}

// ---------------- bias concat (bq|bk|bv) --------------------------------------
__global__ void bias3_kernel(const float* __restrict__ a, const float* __restrict__ b,
                             const float* __restrict__ c, float* __restrict__ o)
{
    int i = blockIdx.x * 256 + threadIdx.x;
    if (i < 1024)       o[i] = a[i];
    else if (i < 2048)  o[i] = b[i - 1024];
    else if (i < 3072)  o[i] = c[i - 2048];
}

// ---------------- activation split (fp16 hi/lo) -------------------------------
__global__ __launch_bounds__(256) void split_kernel(
    const float* __restrict__ src, __half* __restrict__ h,
    __half* __restrict__ l, int n4)
{
    int i = blockIdx.x * 256 + threadIdx.x;
    if (i >= n4) return;
    float4 f = ((const float4*)src)[i];
    uint32_t h0 = packhf(f.x, f.y), h1 = packhf(f.z, f.w);
    ((uint32_t*)h)[i*2+0] = h0;
    ((uint32_t*)h)[i*2+1] = h1;
    ((uint32_t*)l)[i*2+0] = packhf(f.x - hflo(h0), f.y - hfhi(h0));
    ((uint32_t*)l)[i*2+1] = packhf(f.z - hflo(h1), f.w - hfhi(h1));
}

// ---------------- flash attention: S bf16 3-pass, PV fp16 2-pass --------------
// 3-stage KV ring (48KB each), one sync per iteration; Q (32KB) at 147456.
#define FL_SMEM (3*49152 + 32768)   // 180224
__global__ __launch_bounds__(256, 1)
void flash_mma_kernel(const __nv_bfloat16* __restrict__ Qh_, const __nv_bfloat16* __restrict__ Ql_,
                      const __nv_bfloat16* __restrict__ Kh_, const __nv_bfloat16* __restrict__ Kl_,
                      const __half* __restrict__ Vh_,
                      __half* __restrict__ Oh, __half* __restrict__ Ol)
{
    extern __shared__ char smem[];
    uint32_t sb = smem_u32(smem);
    int tid = threadIdx.x, wid = tid >> 5, lane = tid & 31;
    int qt = blockIdx.x, gh = blockIdx.y;
    long ghoff = (long)gh * SEQ * HD_;
    const __nv_bfloat16* Qh = Qh_ + ghoff + (long)qt * 128 * HD_;
    const __nv_bfloat16* Ql = Ql_ + ghoff + (long)qt * 128 * HD_;
    const __nv_bfloat16* Kh = Kh_ + ghoff;
    const __nv_bfloat16* Kl = Kl_ + ghoff;
    const __half*        Vh = Vh_ + ghoff;

    const uint32_t QOFF = 147456;

    {
#pragma unroll
        for (int i = 0; i < 8; i++) {
            int c = i * 256 + tid;
            int arr = c >> 10, w = c & 1023, row = w >> 3, ch = w & 7;
            const __nv_bfloat16* src = (arr ? Ql : Qh) + (long)row * 64 + ch * 8;
            uint32_t dst = sb + QOFF + arr * 16384 + row * 128 + ((ch ^ (row & 7)) << 4);
            CP_ASYNC16(dst, src);
        }
        CP_COMMIT();
    }

    auto issueKV = [&](int it, int stage) {
        uint32_t stb = sb + stage * 49152;
#pragma unroll
        for (int i = 0; i < 12; i++) {
            int c = i * 256 + tid;
            int arr = c >> 10, w = c & 1023, row = w >> 3, ch = w & 7;
            uint32_t dst = stb + arr * 16384 + row * 128 + ((ch ^ (row & 7)) << 4);
            if (arr == 2) {
                const __half* src = Vh + (long)(it * 128 + row) * 64 + ch * 8;
                CP_ASYNC16(dst, src);
            } else {
                const __nv_bfloat16* src = (arr ? Kl : Kh) + (long)(it * 128 + row) * 64 + ch * 8;
                CP_ASYNC16(dst, src);
            }
        }
        CP_COMMIT();
    };

    issueKV(0, 0);
    issueKV(1, 1);

    // wait for Q (leaves KV0, KV1 in flight), load Q fragments
    CP_WAIT(2);
    __syncthreads();
    uint32_t qhf[4][4], qlf[4][4];
    {
        int arow = lane & 15;
#pragma unroll
        for (int kt = 0; kt < 4; kt++) {
            int row = wid * 16 + arow;
            int ach = 2 * kt + (lane >> 4);
            uint32_t ad = sb + QOFF + row * 128 + ((ach ^ (row & 7)) << 4);
            LDSM4(qhf[kt], ad);
            LDSM4(qlf[kt], ad + 16384);
        }
    }

    float o[8][4];
#pragma unroll
    for (int nt = 0; nt < 8; nt++)
#pragma unroll
        for (int e = 0; e < 4; e++) o[nt][e] = 0.f;
    float m0 = -1e30f, m1 = -1e30f, lp0 = 0.f, lp1 = 0.f;

    for (int it = 0; it < 16; it++) {
        if (it < 15) { CP_WAIT(1); } else { CP_WAIT(0); }
        __syncthreads();   // stage it%3 ready AND stage (it+2)%3 free
        if (it + 2 < 16) issueKV(it + 2, (it + 2) % 3);

        uint32_t stb = sb + (uint32_t)(it % 3) * 49152;

        float s[16][4];
#pragma unroll
        for (int t = 0; t < 16; t++)
#pragma unroll
            for (int e = 0; e < 4; e++) s[t][e] = 0.f;

        int brow = (lane & 7) + ((lane >> 4) & 1) * 8;
#pragma unroll
        for (int kt = 0; kt < 4; kt++) {
            int bch = 2 * kt + ((lane >> 3) & 1);
#pragma unroll
            for (int jp = 0; jp < 4; jp++) {
                uint32_t khf[2][4], klf[2][4];
#pragma unroll
                for (int j = 0; j < 2; j++) {
                    int row = (2 * jp + j) * 16 + brow;
                    uint32_t bd = stb + row * 128 + ((bch ^ (row & 7)) << 4);
                    LDSM4(khf[j], bd);
                    LDSM4(klf[j], bd + 16384);
                }
                int t0 = 4 * jp;
                MMAB(s[t0+0], qhf[kt], khf[0][0], khf[0][1]);
                MMAB(s[t0+1], qhf[kt], khf[0][2], khf[0][3]);
                MMAB(s[t0+2], qhf[kt], khf[1][0], khf[1][1]);
                MMAB(s[t0+3], qhf[kt], khf[1][2], khf[1][3]);
                MMAB(s[t0+0], qhf[kt], klf[0][0], klf[0][1]);
                MMAB(s[t0+1], qhf[kt], klf[0][2], klf[0][3]);
                MMAB(s[t0+2], qhf[kt], klf[1][0], klf[1][1]);
                MMAB(s[t0+3], qhf[kt], klf[1][2], klf[1][3]);
                MMAB(s[t0+0], qlf[kt], khf[0][0], khf[0][1]);
                MMAB(s[t0+1], qlf[kt], khf[0][2], khf[0][3]);
                MMAB(s[t0+2], qlf[kt], khf[1][0], khf[1][1]);
                MMAB(s[t0+3], qlf[kt], khf[1][2], khf[1][3]);
            }
        }

        float t0 = -1e30f, t1 = -1e30f;
#pragma unroll
        for (int t = 0; t < 16; t++) {
            t0 = fmaxf(t0, fmaxf(s[t][0], s[t][1]));
            t1 = fmaxf(t1, fmaxf(s[t][2], s[t][3]));
        }
        t0 = fmaxf(t0, __shfl_xor_sync(0xffffffffu, t0, 1, 4));
        t0 = fmaxf(t0, __shfl_xor_sync(0xffffffffu, t0, 2, 4));
        t1 = fmaxf(t1, __shfl_xor_sync(0xffffffffu, t1, 1, 4));
        t1 = fmaxf(t1, __shfl_xor_sync(0xffffffffu, t1, 2, 4));
        float mn0 = fmaxf(m0, t0), mn1 = fmaxf(m1, t1);
        float c0 = __expf(m0 - mn0), c1 = __expf(m1 - mn1);
        m0 = mn0; m1 = mn1;
        lp0 *= c0; lp1 *= c1;
#pragma unroll
        for (int nt = 0; nt < 8; nt++) {
            o[nt][0] *= c0; o[nt][1] *= c0;
            o[nt][2] *= c1; o[nt][3] *= c1;
        }
#pragma unroll
        for (int t = 0; t < 16; t++) {
            s[t][0] = __expf(s[t][0] - m0);
            s[t][1] = __expf(s[t][1] - m0);
            s[t][2] = __expf(s[t][2] - m1);
            s[t][3] = __expf(s[t][3] - m1);
            lp0 += s[t][0] + s[t][1];
            lp1 += s[t][2] + s[t][3];
        }

        // ---- O += P @ V : fp16 2-pass (P hi/lo fp16, V fp16) ----
        int vrow = lane & 15;
#pragma unroll
        for (int kt = 0; kt < 8; kt++) {
            uint32_t pha[4], pla[4];
#pragma unroll
            for (int q = 0; q < 2; q++) {
                float a0 = s[2*kt + q][0], a1 = s[2*kt + q][1];
                float a2 = s[2*kt + q][2], a3 = s[2*kt + q][3];
                uint32_t h0 = packhf(a0, a1);
                uint32_t h1 = packhf(a2, a3);
                pha[2*q]   = h0;
                pha[2*q+1] = h1;
                pla[2*q]   = packhf(a0 - hflo(h0), a1 - hfhi(h0));
                pla[2*q+1] = packhf(a2 - hflo(h1), a3 - hfhi(h1));
            }
            int row = kt * 16 + vrow;
#pragma unroll
            for (int np = 0; np < 2; np++) {
                uint32_t vhf[2][4];
#pragma unroll
                for (int j = 0; j < 2; j++) {
                    int ch = 2 * (2 * np + j) + (lane >> 4);
                    uint32_t vd = stb + 32768 + row * 128 + ((ch ^ (row & 7)) << 4);
                    LDSM4T(vhf[j], vd);
                }
                int ob = 4 * np;
                MMAH(o[ob+0], pha, vhf[0][0], vhf[0][1]);
                MMAH(o[ob+1], pha, vhf[0][2], vhf[0][3]);
                MMAH(o[ob+2], pha, vhf[1][0], vhf[1][1]);
                MMAH(o[ob+3], pha, vhf[1][2], vhf[1][3]);
                MMAH(o[ob+0], pla, vhf[0][0], vhf[0][1]);
                MMAH(o[ob+1], pla, vhf[0][2], vhf[0][3]);
                MMAH(o[ob+2], pla, vhf[1][0], vhf[1][1]);
                MMAH(o[ob+3], pla, vhf[1][2], vhf[1][3]);
            }
        }
    }

    lp0 += __shfl_xor_sync(0xffffffffu, lp0, 1, 4);
    lp0 += __shfl_xor_sync(0xffffffffu, lp0, 2, 4);
    lp1 += __shfl_xor_sync(0xffffffffu, lp1, 1, 4);
    lp1 += __shfl_xor_sync(0xffffffffu, lp1, 2, 4);
    float inv0 = 1.0f / lp0, inv1 = 1.0f / lp1;

    int g = gh >> 4, h = gh & 15;
#pragma unroll
    for (int e = 0; e < 2; e++) {
        int r = qt * 128 + wid * 16 + (lane >> 2) + 8 * e;
        int inst = r >> 9, n = r & 511;
        int b = g * 4 + inst;
        float inv = e ? inv1 : inv0;
        long base = ((long)(b * 512 + n)) * D_ + h * HD_;
#pragma unroll
        for (int nt = 0; nt < 8; nt++) {
            float v0 = o[nt][2*e] * inv, v1 = o[nt][2*e+1] * inv;
            uint32_t hp = packhf(v0, v1);
            uint32_t lp = packhf(v0 - hflo(hp), v1 - hfhi(hp));
            long idx = base + nt * 8 + 2 * (lane & 3);
            *(uint32_t*)&Oh[idx] = hp;
            *(uint32_t*)&Ol[idx] = lp;
        }
    }
}

// ---------------- instance feature -> fp16 ------------------------------------
__global__ __launch_bounds__(256) void feat_kernel(
    const float* __restrict__ mask, const float* __restrict__ embed,
    __half* __restrict__ fh)
{
    int row = blockIdx.x;
    float m0 = mask[row*4+0], m1 = mask[row*4+1];
    float m2 = mask[row*4+2], m3 = mask[row*4+3];
    for (int c = threadIdx.x * 2; c < D_; c += 512) {
        float f0 = m0*embed[c]   + m1*embed[D_ + c]   + m2*embed[2*D_ + c]   + m3*embed[3*D_ + c];
        float f1 = m0*embed[c+1] + m1*embed[D_ + c+1] + m2*embed[2*D_ + c+1] + m3*embed[3*D_ + c+1];
        *(uint32_t*)&fh[(long)row*D_ + c] = packhf(f0, f1);
    }
}

__global__ void zero_kernel(float* __restrict__ p, int n)
{
    int i = blockIdx.x * blockDim.x + threadIdx.x;
    if (i < n) p[i] = 0.f;
}

// ------------------------------- launch --------------------------------------
extern "C" void kernel_launch(void* const* d_in, const int* in_sizes, int n_in,
                              void* d_out, int out_size)
{
    const float* x     = (const float*)d_in[0];
    const float* mask  = (const float*)d_in[1];
    const float* Wq    = (const float*)d_in[2];
    const float* bq    = (const float*)d_in[3];
    const float* Wk    = (const float*)d_in[4];
    const float* bk    = (const float*)d_in[5];
    const float* Wv    = (const float*)d_in[6];
    const float* bv    = (const float*)d_in[7];
    const float* Wo    = (const float*)d_in[8];
    const float* bo    = (const float*)d_in[9];
    const float* Wiq   = (const float*)d_in[10];
    const float* biq   = (const float*)d_in[11];
    const float* Wik   = (const float*)d_in[12];
    const float* bik   = (const float*)d_in[13];
    const float* embed = (const float*)d_in[14];
    const float* qw    = (const float*)d_in[15];
    const float* kw    = (const float*)d_in[16];
    float* out = (float*)d_out;

    float *gacc,*bqkv;
    cudaGetSymbolAddress((void**)&gacc, g_gacc);
    cudaGetSymbolAddress((void**)&bqkv, g_bqkv);

    __nv_bfloat16 *qhg,*qlg,*khg,*klg;
    __half *vhg;
    cudaGetSymbolAddress((void**)&qhg, g_qhg);   cudaGetSymbolAddress((void**)&qlg, g_qlg);
    cudaGetSymbolAddress((void**)&khg, g_khg);   cudaGetSymbolAddress((void**)&klg, g_klg);
    cudaGetSymbolAddress((void**)&vhg, g_vhg);

    __half *wqkvh,*wiqh,*wikh,*woh,*xh,*xl,*ah,*al,*fh,*iqh,*ikh;
    cudaGetSymbolAddress((void**)&wqkvh, g_wqkvh);
    cudaGetSymbolAddress((void**)&wiqh, g_wiqh);
    cudaGetSymbolAddress((void**)&wikh, g_wikh);
    cudaGetSymbolAddress((void**)&woh, g_woh);
    cudaGetSymbolAddress((void**)&xh, g_xh);       cudaGetSymbolAddress((void**)&xl, g_xl);
    cudaGetSymbolAddress((void**)&ah, g_ah);       cudaGetSymbolAddress((void**)&al, g_al);
    cudaGetSymbolAddress((void**)&fh, g_fh);
    cudaGetSymbolAddress((void**)&iqh, g_iqh);     cudaGetSymbolAddress((void**)&ikh, g_ikh);

    cudaFuncSetAttribute((const void*)mma_gemm_kernel,
                         cudaFuncAttributeMaxDynamicSharedMemorySize, TC_SMEM_2P);
    cudaFuncSetAttribute((const void*)flash_mma_kernel,
                         cudaFuncAttributeMaxDynamicSharedMemorySize, FL_SMEM);

    const int N4 = MROWS * D_ / 4;
    const int SPLIT_BLOCKS = (N4 + 255) / 256;

    // launches 1-3
    wt_split6_kernel<<<dim3(16, 16, 6), 256>>>(Wq, Wk, Wv, Wiq, Wik, Wo,
                                               wqkvh, wiqh, wikh, woh);
    bias3_kernel<<<12, 256>>>(bq, bk, bv, bqkv);
    split_kernel<<<SPLIT_BLOCKS, 256>>>(x, xh, xl, N4);

    // launch #4 (profiled): fused QKV projection (fp16 2-pass) + RMS epilogue
    mma_gemm_kernel<<<dim3(D3/256, MROWS/128), 256, TC_SMEM_2P>>>(
        xh, xl, wqkvh, bqkv, nullptr, nullptr, nullptr, nullptr,
        nullptr, nullptr, nullptr, nullptr,
        qw, kw, qhg, qlg, khg, klg, vhg,
        MROWS, D3, D_, 0, 0, 0, 2, 4);

    // small prep
    zero_kernel<<<(MROWS+255)/256, 256>>>(gacc, MROWS);
    feat_kernel<<<MROWS, 256>>>(mask, embed, fh);

    // attention (S bf16 3-pass, PV fp16 2-pass; emits fp16 ah/al)
    flash_mma_kernel<<<dim3(SEQ/128, GH), 256, FL_SMEM>>>(qhg, qlg, khg, klg, vhg, ah, al);

    // iq & ik projections fused (fp16 1-pass; z selects operand set)
    mma_gemm_kernel<<<dim3(D_/256, MROWS/128, 2), 256, TC_SMEM_1P>>>(
        ah, nullptr, wiqh, biq, nullptr, iqh, nullptr, nullptr,
        fh, wikh, bik, ikh,
        nullptr, nullptr, nullptr, nullptr, nullptr, nullptr, nullptr,
        MROWS, D_, D_, 0, 0, 0, 1, 1);

    // gate: per-batch iq @ ik^T (fp16 1-pass) with fused sigmoid row-sum
    mma_gemm_kernel<<<dim3(2, 4, 8), 256, TC_SMEM_1P>>>(
        iqh, nullptr, ikh, nullptr, nullptr, nullptr, nullptr, gacc,
        nullptr, nullptr, nullptr, nullptr,
        nullptr, nullptr, nullptr, nullptr, nullptr, nullptr, nullptr,
        512, 512, D_, (long)512*D_, (long)512*D_, 0, 1, 3);

    // gated output projection (fp16 2-pass): out = diag(1+gacc/512)*(attn@Wo)+bo
    mma_gemm_kernel<<<dim3(D_/256, MROWS/128), 256, TC_SMEM_2P>>>(
        ah, al, woh, bo, out, nullptr, gacc, nullptr,
        nullptr, nullptr, nullptr, nullptr,
        nullptr, nullptr, nullptr, nullptr, nullptr, nullptr, nullptr,
        MROWS, D_, D_, 0, 0, 0, 2, 2);
}

// round 13
// speedup vs baseline: 1.3322x; 1.0223x over previous
#include <cuda_runtime.h>
#include <cuda_bf16.h>
#include <cuda_fp16.h>
#include <math.h>
#include <stdint.h>

// Problem constants
#define B_    8
#define N_    512
#define D_    1024
#define H_    16
#define HD_   64
#define NI_   4
#define G_    2
#define MROWS (B_*N_)      // 4096
#define SEQ   (NI_*N_)     // 2048
#define GH    (G_*H_)      // 32
#define D3    3072
#define SCALE 0.125f
#define S2    0.0078125f   // SCALE / H

// ---------------- scratch (device globals) -----------------------------------
static __device__ float g_gacc[MROWS];
static __device__ float g_bqkv[D3];

// attention operands, grouped [GH, SEQ, HD]: q/k bf16 hi/lo (3-pass S), v fp16
#define AELEMS (GH*SEQ*HD_)
static __device__ __align__(256) __nv_bfloat16 g_qhg[AELEMS], g_qlg[AELEMS];
static __device__ __align__(256) __nv_bfloat16 g_khg[AELEMS], g_klg[AELEMS];
static __device__ __align__(256) __half g_vhg[AELEMS];

// fp16 weights (hi only) and fp16 activations (hi/lo where needed)
static __device__ __align__(256) __half g_wqkvh[D3*D_];
static __device__ __align__(256) __half g_wiqh[D_*D_];
static __device__ __align__(256) __half g_wikh[D_*D_];
static __device__ __align__(256) __half g_woh[D_*D_];
static __device__ __align__(256) __half g_xh[MROWS*D_],  g_xl[MROWS*D_];
static __device__ __align__(256) __half g_ah[MROWS*D_],  g_al[MROWS*D_];   // attn hi/lo
static __device__ __align__(256) __half g_fh[MROWS*D_];
static __device__ __align__(256) __half g_iqh[MROWS*D_];
static __device__ __align__(256) __half g_ikh[MROWS*D_];

// ---------------- PTX helpers --------------------------------------------------
__device__ __forceinline__ uint32_t smem_u32(const void* p) {
    uint32_t a;
    asm("{ .reg .u64 t; cvta.to.shared.u64 t, %1; cvt.u32.u64 %0, t; }"
        : "=r"(a) : "l"(p));
    return a;
}

#define LDSM4(r, addr) \
    asm volatile("ldmatrix.sync.aligned.m8n8.x4.shared.b16 {%0,%1,%2,%3}, [%4];" \
        : "=r"((r)[0]), "=r"((r)[1]), "=r"((r)[2]), "=r"((r)[3]) : "r"(addr))

#define LDSM4T(r, addr) \
    asm volatile("ldmatrix.sync.aligned.m8n8.x4.trans.shared.b16 {%0,%1,%2,%3}, [%4];" \
        : "=r"((r)[0]), "=r"((r)[1]), "=r"((r)[2]), "=r"((r)[3]) : "r"(addr))

// bf16 MMA (flash S)
#define MMAB(d, a, bv0, bv1) \
    asm volatile("mma.sync.aligned.m16n8k16.row.col.f32.bf16.bf16.f32 " \
        "{%0,%1,%2,%3}, {%4,%5,%6,%7}, {%8,%9}, {%0,%1,%2,%3};" \
        : "+f"((d)[0]), "+f"((d)[1]), "+f"((d)[2]), "+f"((d)[3]) \
        : "r"((a)[0]), "r"((a)[1]), "r"((a)[2]), "r"((a)[3]), "r"(bv0), "r"(bv1))

// fp16 MMA (projection GEMMs + flash PV)
#define MMAH(d, a, bv0, bv1) \
    asm volatile("mma.sync.aligned.m16n8k16.row.col.f32.f16.f16.f32 " \
        "{%0,%1,%2,%3}, {%4,%5,%6,%7}, {%8,%9}, {%0,%1,%2,%3};" \
        : "+f"((d)[0]), "+f"((d)[1]), "+f"((d)[2]), "+f"((d)[3]) \
        : "r"((a)[0]), "r"((a)[1]), "r"((a)[2]), "r"((a)[3]), "r"(bv0), "r"(bv1))

#define CP_ASYNC16(dst, src) \
    asm volatile("cp.async.cg.shared.global [%0], [%1], 16;" \
        :: "r"(dst), "l"(__cvta_generic_to_global(src)) : "memory")
#define CP_COMMIT() asm volatile("cp.async.commit_group;" ::: "memory")
#define CP_WAIT(n)  asm volatile("cp.async.wait_group %0;" :: "n"(n) : "memory")

__device__ __forceinline__ uint32_t packbf(float a, float b) {
    uint32_t d;
    asm("cvt.rn.bf16x2.f32 %0, %1, %2;" : "=r"(d) : "f"(b), "f"(a));
    return d;
}
__device__ __forceinline__ float bflo(uint32_t v) { return __uint_as_float(v << 16); }
__device__ __forceinline__ float bfhi(uint32_t v) { return __uint_as_float(v & 0xffff0000u); }

__device__ __forceinline__ uint32_t packhf(float a, float b) {
    __half2 t = __floats2half2_rn(a, b);   // low = a, high = b
    return *reinterpret_cast<uint32_t*>(&t);
}
__device__ __forceinline__ float hflo(uint32_t v) {
    __half2 t = *reinterpret_cast<__half2*>(&v);
    return __low2float(t);
}
__device__ __forceinline__ float hfhi(uint32_t v) {
    __half2 t = *reinterpret_cast<__half2*>(&v);
    return __high2float(t);
}

// -------- fp16 HMMA GEMM: CTA 128x128, warp 32x64, 2 CTAs/SM ------------------
// out_mode: 0 fp32 C+bias; 1 fp16 Chf (+bias, z selects operand set);
//           2 fp32 gate-scaled; 3 sigmoid row-sum atomics into gout;
//           4 QKV epilogue: bias + per-head RMS norm (q,k, bf16 hi/lo) + v fp16.
// stage 2-pass (48KB): Ah@0(16K) Al@16K Bh@32K(16K)
// stage 1-pass (32KB): Ah@0(16K) Bh@16K(16K)
#define TC_SMEM_2P (2*49152)   // 98304
#define TC_SMEM_1P (2*32768)   // 65536
__global__ __launch_bounds__(256, 2)
void mma_gemm_kernel(const __half* __restrict__ Ahp, const __half* __restrict__ Alp,
                     const __half* __restrict__ Bhp,
                     const float* __restrict__ bias, float* __restrict__ C,
                     __half* __restrict__ Chf,
                     const float* __restrict__ grow, float* __restrict__ gout,
                     const __half* __restrict__ Ahp2, const __half* __restrict__ Bhp2,
                     const float* __restrict__ bias2, __half* __restrict__ Chf2,
                     const float* __restrict__ qw, const float* __restrict__ kw,
                     __nv_bfloat16* __restrict__ qh_, __nv_bfloat16* __restrict__ ql_,
                     __nv_bfloat16* __restrict__ kh_, __nv_bfloat16* __restrict__ kl_,
                     __half* __restrict__ vhf_,
                     int M, int N, int K, long sA, long sB, long sC,
                     int npass, int out_mode)
{
    extern __shared__ char smem[];
    uint32_t sb = smem_u32(smem);
    int tid = threadIdx.x, wid = tid >> 5, lane = tid & 31;
    int m0 = blockIdx.y * 128, n0 = blockIdx.x * 128;
    long zb = blockIdx.z;
    const __half* Ah = Ahp + zb * sA;
    const __half* Al = (npass == 2) ? (Alp + zb * sA) : Ahp;
    const __half* Bh = Bhp + zb * sB;
    if (out_mode == 1 && blockIdx.z == 1) {
        Ah = Ahp2; Bh = Bhp2; bias = bias2; Chf = Chf2;
    }

    const int nsteps = K / 64;
    const uint32_t SS   = (npass == 2) ? 49152 : 32768;
    const uint32_t BOFF = (npass == 2) ? 32768 : 16384;
    const int ncp = (npass == 2) ? 12 : 8;

    auto issue = [&](int step, int stage) {
        uint32_t stb = sb + stage * SS;
        int k0 = step * 64;
#pragma unroll
        for (int i = 0; i < 12; i++) {
            if (i >= ncp) break;
            int c = i * 256 + tid;
            int tile = c >> 10;          // 0:Ah 1:Al/Bh 2:Bh
            int w = c & 1023;
            int row = w >> 3, ch = w & 7;
            const __half* src;
            uint32_t tbase;
            if (npass == 2) {
                if      (tile == 0) { src = Ah; tbase = 0; }
                else if (tile == 1) { src = Al; tbase = 16384; }
                else                { src = Bh; tbase = 32768; }
            } else {
                if      (tile == 0) { src = Ah; tbase = 0; }
                else                { src = Bh; tbase = 16384; }
            }
            int gr = ((npass == 2 ? tile == 2 : tile == 1) ? n0 : m0) + row;
            const __half* gp = src + (long)gr * K + k0 + ch * 8;
            uint32_t dst = stb + tbase + row * 128 + ((ch ^ (row & 7)) << 4);
            CP_ASYNC16(dst, gp);
        }
        CP_COMMIT();
    };

    int mbase = (wid >> 1) * 32;   // 0/32/64/96
    int nbase = (wid & 1) * 64;    // 0/64
    int arow = lane & 15;
    int brow = (lane & 7) + ((lane >> 4) & 1) * 8;

    float acc[2][8][4];
#pragma unroll
    for (int mt = 0; mt < 2; mt++)
#pragma unroll
        for (int nt = 0; nt < 8; nt++)
#pragma unroll
            for (int e = 0; e < 4; e++) acc[mt][nt][e] = 0.f;

    issue(0, 0);
    if (nsteps > 1) issue(1, 1);

    for (int step = 0; step < nsteps; step++) {
        if (step + 1 < nsteps) { CP_WAIT(1); } else { CP_WAIT(0); }
        __syncthreads();

        uint32_t stb = sb + (uint32_t)(step & 1) * SS;
#pragma unroll
        for (int k16 = 0; k16 < 4; k16++) {
            uint32_t ahf[2][4], alf[2][4], bhf[4][4];
            int ach = 2 * k16 + (lane >> 4);
#pragma unroll
            for (int mt = 0; mt < 2; mt++) {
                int row = mbase + mt * 16 + arow;
                uint32_t ad = stb + row * 128 + ((ach ^ (row & 7)) << 4);
                LDSM4(ahf[mt], ad);
                if (npass == 2) LDSM4(alf[mt], ad + 16384);
            }
            int bch = 2 * k16 + ((lane >> 3) & 1);
#pragma unroll
            for (int j = 0; j < 4; j++) {
                int row = nbase + j * 16 + brow;
                uint32_t bd = stb + BOFF + row * 128 + ((bch ^ (row & 7)) << 4);
                LDSM4(bhf[j], bd);
            }
#pragma unroll
            for (int mt = 0; mt < 2; mt++)
#pragma unroll
                for (int nt = 0; nt < 8; nt++) {
                    int j = nt >> 1, p = (nt & 1) * 2;
                    MMAH(acc[mt][nt], ahf[mt], bhf[j][p], bhf[j][p+1]);
                }
            if (npass == 2) {
#pragma unroll
                for (int mt = 0; mt < 2; mt++)
#pragma unroll
                    for (int nt = 0; nt < 8; nt++) {
                        int j = nt >> 1, p = (nt & 1) * 2;
                        MMAH(acc[mt][nt], alf[mt], bhf[j][p], bhf[j][p+1]);
                    }
            }
        }
        __syncthreads();
        if (step + 2 < nsteps) issue(step + 2, step & 1);
    }

    // ------------------------------ epilogues ---------------------------------
    if (out_mode == 4) {
        int c0 = n0 + nbase;             // multiple of 64
        int type = c0 >> 10;             // 0=q 1=k 2=v
        int hh = (c0 & 1023) >> 6;       // head index
        const float* wv = (type == 0) ? qw : kw;
        __nv_bfloat16 *ph = (type == 0) ? qh_ : kh_;
        __nv_bfloat16 *pl = (type == 0) ? ql_ : kl_;
#pragma unroll
        for (int mt = 0; mt < 2; mt++) {
            float vals[8][4];
            float ss0 = 0.f, ss1 = 0.f;
            int r0 = m0 + mbase + mt * 16 + (lane >> 2);
#pragma unroll
            for (int nt = 0; nt < 8; nt++) {
                int c = c0 + nt * 8 + 2 * (lane & 3);
                float b0 = bias[c], b1 = bias[c + 1];
                vals[nt][0] = acc[mt][nt][0] + b0;
                vals[nt][1] = acc[mt][nt][1] + b1;
                vals[nt][2] = acc[mt][nt][2] + b0;
                vals[nt][3] = acc[mt][nt][3] + b1;
                ss0 += vals[nt][0]*vals[nt][0] + vals[nt][1]*vals[nt][1];
                ss1 += vals[nt][2]*vals[nt][2] + vals[nt][3]*vals[nt][3];
            }
            ss0 += __shfl_xor_sync(0xffffffffu, ss0, 1, 4);
            ss0 += __shfl_xor_sync(0xffffffffu, ss0, 2, 4);
            ss1 += __shfl_xor_sync(0xffffffffu, ss1, 1, 4);
            ss1 += __shfl_xor_sync(0xffffffffu, ss1, 2, 4);
            float sc0 = 1.f, sc1 = 1.f;
            if (type == 0) {
                sc0 = rsqrtf(ss0 * (1.0f/64.0f) + 1e-6f) * SCALE;
                sc1 = rsqrtf(ss1 * (1.0f/64.0f) + 1e-6f) * SCALE;
            } else if (type == 1) {
                sc0 = rsqrtf(ss0 * (1.0f/64.0f) + 1e-6f);
                sc1 = rsqrtf(ss1 * (1.0f/64.0f) + 1e-6f);
            }
#pragma unroll
            for (int e = 0; e < 2; e++) {
                int r = r0 + 8 * e;
                int b = r >> 9, n = r & 511;
                int g = b >> 2, inst = b & 3;
                long obase = (((long)(g*16 + hh)) * SEQ + inst*512 + n) * HD_;
                float sc = e ? sc1 : sc0;
#pragma unroll
                for (int nt = 0; nt < 8; nt++) {
                    int colh = nt * 8 + 2 * (lane & 3);
                    if (type == 2) {
                        *(uint32_t*)&vhf_[obase + colh] =
                            packhf(vals[nt][2*e], vals[nt][2*e+1]);
                    } else {
                        float u0 = vals[nt][2*e]   * sc * wv[colh];
                        float u1 = vals[nt][2*e+1] * sc * wv[colh + 1];
                        uint32_t hp = packbf(u0, u1);
                        uint32_t lp = packbf(u0 - bflo(hp), u1 - bfhi(hp));
                        *(uint32_t*)&ph[obase + colh] = hp;
                        *(uint32_t*)&pl[obase + colh] = lp;
                    }
                }
            }
        }
        return;
    }

    if (out_mode == 3) {
#pragma unroll
        for (int mt = 0; mt < 2; mt++) {
            int r0 = m0 + mbase + mt * 16 + (lane >> 2);
            float ps0 = 0.f, ps1 = 0.f;
#pragma unroll
            for (int nt = 0; nt < 8; nt++) {
                ps0 += 1.0f / (1.0f + __expf(-acc[mt][nt][0] * S2));
                ps0 += 1.0f / (1.0f + __expf(-acc[mt][nt][1] * S2));
                ps1 += 1.0f / (1.0f + __expf(-acc[mt][nt][2] * S2));
                ps1 += 1.0f / (1.0f + __expf(-acc[mt][nt][3] * S2));
            }
            ps0 += __shfl_xor_sync(0xffffffffu, ps0, 1, 4);
            ps0 += __shfl_xor_sync(0xffffffffu, ps0, 2, 4);
            ps1 += __shfl_xor_sync(0xffffffffu, ps1, 1, 4);
            ps1 += __shfl_xor_sync(0xffffffffu, ps1, 2, 4);
            if ((lane & 3) == 0) {
                atomicAdd(&gout[zb * 512 + r0], ps0);
                atomicAdd(&gout[zb * 512 + r0 + 8], ps1);
            }
        }
        return;
    }

#pragma unroll
    for (int mt = 0; mt < 2; mt++) {
        int r0 = m0 + mbase + mt * 16 + (lane >> 2);
        float g0 = 1.f, g1 = 1.f;
        if (out_mode == 2) {
            g0 = 1.0f + grow[r0] * (1.0f/512.0f);
            g1 = 1.0f + grow[r0 + 8] * (1.0f/512.0f);
        }
#pragma unroll
        for (int nt = 0; nt < 8; nt++) {
            int c = n0 + nbase + nt * 8 + 2 * (lane & 3);
            float b0 = 0.f, b1 = 0.f;
            if (bias) { b0 = bias[c]; b1 = bias[c + 1]; }
            float v00 = acc[mt][nt][0] * g0 + b0, v01 = acc[mt][nt][1] * g0 + b1;
            float v10 = acc[mt][nt][2] * g1 + b0, v11 = acc[mt][nt][3] * g1 + b1;
            if (out_mode == 1) {
                *(uint32_t*)&Chf[(long)r0 * N + c]       = packhf(v00, v01);
                *(uint32_t*)&Chf[(long)(r0 + 8) * N + c] = packhf(v10, v11);
            } else {
                float* Cc = C + zb * sC;
                float2 w0; w0.x = v00; w0.y = v01;
                *(float2*)&Cc[(long)r0 * N + c] = w0;
                float2 w1; w1.x = v10; w1.y = v11;
                *(float2*)&Cc[(long)(r0 + 8) * N + c] = w1;
            }
        }
    }
}

// ---------------- weight transpose + fp16 convert (6 weights fused) ----------
__device__ __forceinline__ void wt_split_body(
    const float* __restrict__ W, __half* __restrict__ Th, float (*t)[65])
{
    int n0 = blockIdx.x * 64, k0 = blockIdx.y * 64;
    int tid = threadIdx.x;
#pragma unroll
    for (int it = 0; it < 4; it++) {
        int row = (tid >> 4) + it * 16;
        int c4 = (tid & 15) * 4;
        float4 v = *(const float4*)&W[(long)(k0 + row) * D_ + n0 + c4];
        t[row][c4+0] = v.x; t[row][c4+1] = v.y; t[row][c4+2] = v.z; t[row][c4+3] = v.w;
    }
    __syncthreads();
    int n = tid >> 2, kc = (tid & 3) * 16;
    uint32_t hb[8];
#pragma unroll
    for (int j = 0; j < 16; j += 2)
        hb[j >> 1] = packhf(t[kc + j][n], t[kc + j + 1][n]);
    long obase = (long)(n0 + n) * D_ + k0 + kc;
    *(uint4*)&Th[obase]     = make_uint4(hb[0], hb[1], hb[2], hb[3]);
    *(uint4*)&Th[obase + 8] = make_uint4(hb[4], hb[5], hb[6], hb[7]);
}

__global__ __launch_bounds__(256) void wt_split6_kernel(
    const float* __restrict__ Wq, const float* __restrict__ Wk, const float* __restrict__ Wv,
    const float* __restrict__ Wiq, const float* __restrict__ Wik, const float* __restrict__ Wo,
    __half* __restrict__ wqkvh, __half* __restrict__ wiqh,
    __half* __restrict__ wikh, __half* __restrict__ woh)
{
    __shared__ float t[64][65];
    const float* W;
    __half* Th;
    switch (blockIdx.z) {
        case 0: W = Wq;  Th = wqkvh;             break;
        case 1: W = Wk;  Th = wqkvh + 1024*1024; break;
        case 2: W = Wv;  Th = wqkvh + 2048*1024; break;
        case 3: W = Wiq; Th = wiqh;              break;
        case 4: W = Wik; Th = wikh;              break;
        default: W = Wo; Th = woh;               break;
    }
    wt_split_body(W, Th, t);
}

// ---------------- bias concat (bq|bk|bv) --------------------------------------
__global__ void bias3_kernel(const float* __restrict__ a, const float* __restrict__ b,
                             const float* __restrict__ c, float* __restrict__ o)
{
    int i = blockIdx.x * 256 + threadIdx.x;
    if (i < 1024)       o[i] = a[i];
    else if (i < 2048)  o[i] = b[i - 1024];
    else if (i < 3072)  o[i] = c[i - 2048];
}

// ---------------- activation split (fp16 hi/lo) -------------------------------
__global__ __launch_bounds__(256) void split_kernel(
    const float* __restrict__ src, __half* __restrict__ h,
    __half* __restrict__ l, int n4)
{
    int i = blockIdx.x * 256 + threadIdx.x;
    if (i >= n4) return;
    float4 f = ((const float4*)src)[i];
    uint32_t h0 = packhf(f.x, f.y), h1 = packhf(f.z, f.w);
    ((uint32_t*)h)[i*2+0] = h0;
    ((uint32_t*)h)[i*2+1] = h1;
    ((uint32_t*)l)[i*2+0] = packhf(f.x - hflo(h0), f.y - hfhi(h0));
    ((uint32_t*)l)[i*2+1] = packhf(f.z - hflo(h1), f.w - hfhi(h1));
}

// ---------------- flash attention: S bf16 3-pass, PV fp16 2-pass --------------
// 3-stage KV ring (48KB each), one sync per iteration; Q (32KB) at 147456.
#define FL_SMEM (3*49152 + 32768)   // 180224
__global__ __launch_bounds__(256, 1)
void flash_mma_kernel(const __nv_bfloat16* __restrict__ Qh_, const __nv_bfloat16* __restrict__ Ql_,
                      const __nv_bfloat16* __restrict__ Kh_, const __nv_bfloat16* __restrict__ Kl_,
                      const __half* __restrict__ Vh_,
                      __half* __restrict__ Oh, __half* __restrict__ Ol)
{
    extern __shared__ char smem[];
    uint32_t sb = smem_u32(smem);
    int tid = threadIdx.x, wid = tid >> 5, lane = tid & 31;
    int qt = blockIdx.x, gh = blockIdx.y;
    long ghoff = (long)gh * SEQ * HD_;
    const __nv_bfloat16* Qh = Qh_ + ghoff + (long)qt * 128 * HD_;
    const __nv_bfloat16* Ql = Ql_ + ghoff + (long)qt * 128 * HD_;
    const __nv_bfloat16* Kh = Kh_ + ghoff;
    const __nv_bfloat16* Kl = Kl_ + ghoff;
    const __half*        Vh = Vh_ + ghoff;

    const uint32_t QOFF = 147456;

    {
#pragma unroll
        for (int i = 0; i < 8; i++) {
            int c = i * 256 + tid;
            int arr = c >> 10, w = c & 1023, row = w >> 3, ch = w & 7;
            const __nv_bfloat16* src = (arr ? Ql : Qh) + (long)row * 64 + ch * 8;
            uint32_t dst = sb + QOFF + arr * 16384 + row * 128 + ((ch ^ (row & 7)) << 4);
            CP_ASYNC16(dst, src);
        }
        CP_COMMIT();
    }

    auto issueKV = [&](int it, int stage) {
        uint32_t stb = sb + stage * 49152;
#pragma unroll
        for (int i = 0; i < 12; i++) {
            int c = i * 256 + tid;
            int arr = c >> 10, w = c & 1023, row = w >> 3, ch = w & 7;
            uint32_t dst = stb + arr * 16384 + row * 128 + ((ch ^ (row & 7)) << 4);
            if (arr == 2) {
                const __half* src = Vh + (long)(it * 128 + row) * 64 + ch * 8;
                CP_ASYNC16(dst, src);
            } else {
                const __nv_bfloat16* src = (arr ? Kl : Kh) + (long)(it * 128 + row) * 64 + ch * 8;
                CP_ASYNC16(dst, src);
            }
        }
        CP_COMMIT();
    };

    issueKV(0, 0);
    issueKV(1, 1);

    CP_WAIT(2);
    __syncthreads();
    uint32_t qhf[4][4], qlf[4][4];
    {
        int arow = lane & 15;
#pragma unroll
        for (int kt = 0; kt < 4; kt++) {
            int row = wid * 16 + arow;
            int ach = 2 * kt + (lane >> 4);
            uint32_t ad = sb + QOFF + row * 128 + ((ach ^ (row & 7)) << 4);
            LDSM4(qhf[kt], ad);
            LDSM4(qlf[kt], ad + 16384);
        }
    }

    float o[8][4];
#pragma unroll
    for (int nt = 0; nt < 8; nt++)
#pragma unroll
        for (int e = 0; e < 4; e++) o[nt][e] = 0.f;
    float m0 = -1e30f, m1 = -1e30f, lp0 = 0.f, lp1 = 0.f;

    for (int it = 0; it < 16; it++) {
        if (it < 15) { CP_WAIT(1); } else { CP_WAIT(0); }
        __syncthreads();
        if (it + 2 < 16) issueKV(it + 2, (it + 2) % 3);

        uint32_t stb = sb + (uint32_t)(it % 3) * 49152;

        float s[16][4];
#pragma unroll
        for (int t = 0; t < 16; t++)
#pragma unroll
            for (int e = 0; e < 4; e++) s[t][e] = 0.f;

        int brow = (lane & 7) + ((lane >> 4) & 1) * 8;
#pragma unroll
        for (int kt = 0; kt < 4; kt++) {
            int bch = 2 * kt + ((lane >> 3) & 1);
#pragma unroll
            for (int jp = 0; jp < 4; jp++) {
                uint32_t khf[2][4], klf[2][4];
#pragma unroll
                for (int j = 0; j < 2; j++) {
                    int row = (2 * jp + j) * 16 + brow;
                    uint32_t bd = stb + row * 128 + ((bch ^ (row & 7)) << 4);
                    LDSM4(khf[j], bd);
                    LDSM4(klf[j], bd + 16384);
                }
                int t0 = 4 * jp;
                MMAB(s[t0+0], qhf[kt], khf[0][0], khf[0][1]);
                MMAB(s[t0+1], qhf[kt], khf[0][2], khf[0][3]);
                MMAB(s[t0+2], qhf[kt], khf[1][0], khf[1][1]);
                MMAB(s[t0+3], qhf[kt], khf[1][2], khf[1][3]);
                MMAB(s[t0+0], qhf[kt], klf[0][0], klf[0][1]);
                MMAB(s[t0+1], qhf[kt], klf[0][2], klf[0][3]);
                MMAB(s[t0+2], qhf[kt], klf[1][0], klf[1][1]);
                MMAB(s[t0+3], qhf[kt], klf[1][2], klf[1][3]);
                MMAB(s[t0+0], qlf[kt], khf[0][0], khf[0][1]);
                MMAB(s[t0+1], qlf[kt], khf[0][2], khf[0][3]);
                MMAB(s[t0+2], qlf[kt], khf[1][0], khf[1][1]);
                MMAB(s[t0+3], qlf[kt], khf[1][2], khf[1][3]);
            }
        }

        float t0 = -1e30f, t1 = -1e30f;
#pragma unroll
        for (int t = 0; t < 16; t++) {
            t0 = fmaxf(t0, fmaxf(s[t][0], s[t][1]));
            t1 = fmaxf(t1, fmaxf(s[t][2], s[t][3]));
        }
        t0 = fmaxf(t0, __shfl_xor_sync(0xffffffffu, t0, 1, 4));
        t0 = fmaxf(t0, __shfl_xor_sync(0xffffffffu, t0, 2, 4));
        t1 = fmaxf(t1, __shfl_xor_sync(0xffffffffu, t1, 1, 4));
        t1 = fmaxf(t1, __shfl_xor_sync(0xffffffffu, t1, 2, 4));
        float mn0 = fmaxf(m0, t0), mn1 = fmaxf(m1, t1);
        float c0 = __expf(m0 - mn0), c1 = __expf(m1 - mn1);
        m0 = mn0; m1 = mn1;
        lp0 *= c0; lp1 *= c1;
#pragma unroll
        for (int nt = 0; nt < 8; nt++) {
            o[nt][0] *= c0; o[nt][1] *= c0;
            o[nt][2] *= c1; o[nt][3] *= c1;
        }
#pragma unroll
        for (int t = 0; t < 16; t++) {
            s[t][0] = __expf(s[t][0] - m0);
            s[t][1] = __expf(s[t][1] - m0);
            s[t][2] = __expf(s[t][2] - m1);
            s[t][3] = __expf(s[t][3] - m1);
            lp0 += s[t][0] + s[t][1];
            lp1 += s[t][2] + s[t][3];
        }

        int vrow = lane & 15;
#pragma unroll
        for (int kt = 0; kt < 8; kt++) {
            uint32_t pha[4], pla[4];
#pragma unroll
            for (int q = 0; q < 2; q++) {
                float a0 = s[2*kt + q][0], a1 = s[2*kt + q][1];
                float a2 = s[2*kt + q][2], a3 = s[2*kt + q][3];
                uint32_t h0 = packhf(a0, a1);
                uint32_t h1 = packhf(a2, a3);
                pha[2*q]   = h0;
                pha[2*q+1] = h1;
                pla[2*q]   = packhf(a0 - hflo(h0), a1 - hfhi(h0));
                pla[2*q+1] = packhf(a2 - hflo(h1), a3 - hfhi(h1));
            }
            int row = kt * 16 + vrow;
#pragma unroll
            for (int np = 0; np < 2; np++) {
                uint32_t vhf[2][4];
#pragma unroll
                for (int j = 0; j < 2; j++) {
                    int ch = 2 * (2 * np + j) + (lane >> 4);
                    uint32_t vd = stb + 32768 + row * 128 + ((ch ^ (row & 7)) << 4);
                    LDSM4T(vhf[j], vd);
                }
                int ob = 4 * np;
                MMAH(o[ob+0], pha, vhf[0][0], vhf[0][1]);
                MMAH(o[ob+1], pha, vhf[0][2], vhf[0][3]);
                MMAH(o[ob+2], pha, vhf[1][0], vhf[1][1]);
                MMAH(o[ob+3], pha, vhf[1][2], vhf[1][3]);
                MMAH(o[ob+0], pla, vhf[0][0], vhf[0][1]);
                MMAH(o[ob+1], pla, vhf[0][2], vhf[0][3]);
                MMAH(o[ob+2], pla, vhf[1][0], vhf[1][1]);
                MMAH(o[ob+3], pla, vhf[1][2], vhf[1][3]);
            }
        }
    }

    lp0 += __shfl_xor_sync(0xffffffffu, lp0, 1, 4);
    lp0 += __shfl_xor_sync(0xffffffffu, lp0, 2, 4);
    lp1 += __shfl_xor_sync(0xffffffffu, lp1, 1, 4);
    lp1 += __shfl_xor_sync(0xffffffffu, lp1, 2, 4);
    float inv0 = 1.0f / lp0, inv1 = 1.0f / lp1;

    int g = gh >> 4, h = gh & 15;
#pragma unroll
    for (int e = 0; e < 2; e++) {
        int r = qt * 128 + wid * 16 + (lane >> 2) + 8 * e;
        int inst = r >> 9, n = r & 511;
        int b = g * 4 + inst;
        float inv = e ? inv1 : inv0;
        long base = ((long)(b * 512 + n)) * D_ + h * HD_;
#pragma unroll
        for (int nt = 0; nt < 8; nt++) {
            float v0 = o[nt][2*e] * inv, v1 = o[nt][2*e+1] * inv;
            uint32_t hp = packhf(v0, v1);
            uint32_t lp = packhf(v0 - hflo(hp), v1 - hfhi(hp));
            long idx = base + nt * 8 + 2 * (lane & 3);
            *(uint32_t*)&Oh[idx] = hp;
            *(uint32_t*)&Ol[idx] = lp;
        }
    }
}

// ---------------- instance feature -> fp16 ------------------------------------
__global__ __launch_bounds__(256) void feat_kernel(
    const float* __restrict__ mask, const float* __restrict__ embed,
    __half* __restrict__ fh)
{
    int row = blockIdx.x;
    float m0 = mask[row*4+0], m1 = mask[row*4+1];
    float m2 = mask[row*4+2], m3 = mask[row*4+3];
    for (int c = threadIdx.x * 2; c < D_; c += 512) {
        float f0 = m0*embed[c]   + m1*embed[D_ + c]   + m2*embed[2*D_ + c]   + m3*embed[3*D_ + c];
        float f1 = m0*embed[c+1] + m1*embed[D_ + c+1] + m2*embed[2*D_ + c+1] + m3*embed[3*D_ + c+1];
        *(uint32_t*)&fh[(long)row*D_ + c] = packhf(f0, f1);
    }
}

__global__ void zero_kernel(float* __restrict__ p, int n)
{
    int i = blockIdx.x * blockDim.x + threadIdx.x;
    if (i < n) p[i] = 0.f;
}

// ------------------------------- launch --------------------------------------
extern "C" void kernel_launch(void* const* d_in, const int* in_sizes, int n_in,
                              void* d_out, int out_size)
{
    const float* x     = (const float*)d_in[0];
    const float* mask  = (const float*)d_in[1];
    const float* Wq    = (const float*)d_in[2];
    const float* bq    = (const float*)d_in[3];
    const float* Wk    = (const float*)d_in[4];
    const float* bk    = (const float*)d_in[5];
    const float* Wv    = (const float*)d_in[6];
    const float* bv    = (const float*)d_in[7];
    const float* Wo    = (const float*)d_in[8];
    const float* bo    = (const float*)d_in[9];
    const float* Wiq   = (const float*)d_in[10];
    const float* biq   = (const float*)d_in[11];
    const float* Wik   = (const float*)d_in[12];
    const float* bik   = (const float*)d_in[13];
    const float* embed = (const float*)d_in[14];
    const float* qw    = (const float*)d_in[15];
    const float* kw    = (const float*)d_in[16];
    float* out = (float*)d_out;

    float *gacc,*bqkv;
    cudaGetSymbolAddress((void**)&gacc, g_gacc);
    cudaGetSymbolAddress((void**)&bqkv, g_bqkv);

    __nv_bfloat16 *qhg,*qlg,*khg,*klg;
    __half *vhg;
    cudaGetSymbolAddress((void**)&qhg, g_qhg);   cudaGetSymbolAddress((void**)&qlg, g_qlg);
    cudaGetSymbolAddress((void**)&khg, g_khg);   cudaGetSymbolAddress((void**)&klg, g_klg);
    cudaGetSymbolAddress((void**)&vhg, g_vhg);

    __half *wqkvh,*wiqh,*wikh,*woh,*xh,*xl,*ah,*al,*fh,*iqh,*ikh;
    cudaGetSymbolAddress((void**)&wqkvh, g_wqkvh);
    cudaGetSymbolAddress((void**)&wiqh, g_wiqh);
    cudaGetSymbolAddress((void**)&wikh, g_wikh);
    cudaGetSymbolAddress((void**)&woh, g_woh);
    cudaGetSymbolAddress((void**)&xh, g_xh);       cudaGetSymbolAddress((void**)&xl, g_xl);
    cudaGetSymbolAddress((void**)&ah, g_ah);       cudaGetSymbolAddress((void**)&al, g_al);
    cudaGetSymbolAddress((void**)&fh, g_fh);
    cudaGetSymbolAddress((void**)&iqh, g_iqh);     cudaGetSymbolAddress((void**)&ikh, g_ikh);

    cudaFuncSetAttribute((const void*)mma_gemm_kernel,
                         cudaFuncAttributeMaxDynamicSharedMemorySize, TC_SMEM_2P);
    cudaFuncSetAttribute((const void*)flash_mma_kernel,
                         cudaFuncAttributeMaxDynamicSharedMemorySize, FL_SMEM);

    const int N4 = MROWS * D_ / 4;
    const int SPLIT_BLOCKS = (N4 + 255) / 256;

    // launches 1-3
    wt_split6_kernel<<<dim3(16, 16, 6), 256>>>(Wq, Wk, Wv, Wiq, Wik, Wo,
                                               wqkvh, wiqh, wikh, woh);
    bias3_kernel<<<12, 256>>>(bq, bk, bv, bqkv);
    split_kernel<<<SPLIT_BLOCKS, 256>>>(x, xh, xl, N4);

    // launch #4 (profiled): fused QKV projection (fp16 2-pass) + RMS epilogue
    mma_gemm_kernel<<<dim3(D3/128, MROWS/128), 256, TC_SMEM_2P>>>(
        xh, xl, wqkvh, bqkv, nullptr, nullptr, nullptr, nullptr,
        nullptr, nullptr, nullptr, nullptr,
        qw, kw, qhg, qlg, khg, klg, vhg,
        MROWS, D3, D_, 0, 0, 0, 2, 4);

    // small prep
    zero_kernel<<<(MROWS+255)/256, 256>>>(gacc, MROWS);
    feat_kernel<<<MROWS, 256>>>(mask, embed, fh);

    // attention (S bf16 3-pass, PV fp16 2-pass; emits fp16 ah/al)
    flash_mma_kernel<<<dim3(SEQ/128, GH), 256, FL_SMEM>>>(qhg, qlg, khg, klg, vhg, ah, al);

    // iq & ik projections fused (fp16 1-pass; z selects operand set)
    mma_gemm_kernel<<<dim3(D_/128, MROWS/128, 2), 256, TC_SMEM_1P>>>(
        ah, nullptr, wiqh, biq, nullptr, iqh, nullptr, nullptr,
        fh, wikh, bik, ikh,
        nullptr, nullptr, nullptr, nullptr, nullptr, nullptr, nullptr,
        MROWS, D_, D_, 0, 0, 0, 1, 1);

    // gate: per-batch iq @ ik^T (fp16 1-pass) with fused sigmoid row-sum
    mma_gemm_kernel<<<dim3(4, 4, 8), 256, TC_SMEM_1P>>>(
        iqh, nullptr, ikh, nullptr, nullptr, nullptr, nullptr, gacc,
        nullptr, nullptr, nullptr, nullptr,
        nullptr, nullptr, nullptr, nullptr, nullptr, nullptr, nullptr,
        512, 512, D_, (long)512*D_, (long)512*D_, 0, 1, 3);

    // gated output projection (fp16 2-pass): out = diag(1+gacc/512)*(attn@Wo)+bo
    mma_gemm_kernel<<<dim3(D_/128, MROWS/128), 256, TC_SMEM_2P>>>(
        ah, al, woh, bo, out, nullptr, gacc, nullptr,
        nullptr, nullptr, nullptr, nullptr,
        nullptr, nullptr, nullptr, nullptr, nullptr, nullptr, nullptr,
        MROWS, D_, D_, 0, 0, 0, 2, 2);
}

// round 14
// speedup vs baseline: 1.4378x; 1.0793x over previous
#include <cuda_runtime.h>
#include <cuda_bf16.h>
#include <cuda_fp16.h>
#include <math.h>
#include <stdint.h>

// Problem constants
#define B_    8
#define N_    512
#define D_    1024
#define H_    16
#define HD_   64
#define NI_   4
#define G_    2
#define MROWS (B_*N_)      // 4096
#define SEQ   (NI_*N_)     // 2048
#define GH    (G_*H_)      // 32
#define D3    3072
#define SCALE 0.125f
#define S2    0.0078125f   // SCALE / H

// ---------------- scratch (device globals) -----------------------------------
static __device__ float g_gacc[MROWS];
static __device__ float g_bqkv[D3];

// attention operands, grouped [GH, SEQ, HD]: q fp16 hi/lo, k fp16, v fp16
#define AELEMS (GH*SEQ*HD_)
static __device__ __align__(256) __half g_qhg[AELEMS], g_qlg[AELEMS];
static __device__ __align__(256) __half g_khg[AELEMS];
static __device__ __align__(256) __half g_vhg[AELEMS];

// fp16 weights (hi only) and fp16 activations (hi/lo where needed)
static __device__ __align__(256) __half g_wqkvh[D3*D_];
static __device__ __align__(256) __half g_wiqh[D_*D_];
static __device__ __align__(256) __half g_wikh[D_*D_];
static __device__ __align__(256) __half g_woh[D_*D_];
static __device__ __align__(256) __half g_xh[MROWS*D_],  g_xl[MROWS*D_];
static __device__ __align__(256) __half g_ah[MROWS*D_],  g_al[MROWS*D_];   // attn hi/lo
static __device__ __align__(256) __half g_fh[MROWS*D_];
static __device__ __align__(256) __half g_iqh[MROWS*D_];
static __device__ __align__(256) __half g_ikh[MROWS*D_];

// ---------------- PTX helpers --------------------------------------------------
__device__ __forceinline__ uint32_t smem_u32(const void* p) {
    uint32_t a;
    asm("{ .reg .u64 t; cvta.to.shared.u64 t, %1; cvt.u32.u64 %0, t; }"
        : "=r"(a) : "l"(p));
    return a;
}

#define LDSM4(r, addr) \
    asm volatile("ldmatrix.sync.aligned.m8n8.x4.shared.b16 {%0,%1,%2,%3}, [%4];" \
        : "=r"((r)[0]), "=r"((r)[1]), "=r"((r)[2]), "=r"((r)[3]) : "r"(addr))

#define LDSM4T(r, addr) \
    asm volatile("ldmatrix.sync.aligned.m8n8.x4.trans.shared.b16 {%0,%1,%2,%3}, [%4];" \
        : "=r"((r)[0]), "=r"((r)[1]), "=r"((r)[2]), "=r"((r)[3]) : "r"(addr))

// fp16 MMA (all tensor work)
#define MMAH(d, a, bv0, bv1) \
    asm volatile("mma.sync.aligned.m16n8k16.row.col.f32.f16.f16.f32 " \
        "{%0,%1,%2,%3}, {%4,%5,%6,%7}, {%8,%9}, {%0,%1,%2,%3};" \
        : "+f"((d)[0]), "+f"((d)[1]), "+f"((d)[2]), "+f"((d)[3]) \
        : "r"((a)[0]), "r"((a)[1]), "r"((a)[2]), "r"((a)[3]), "r"(bv0), "r"(bv1))

#define CP_ASYNC16(dst, src) \
    asm volatile("cp.async.cg.shared.global [%0], [%1], 16;" \
        :: "r"(dst), "l"(__cvta_generic_to_global(src)) : "memory")
#define CP_COMMIT() asm volatile("cp.async.commit_group;" ::: "memory")
#define CP_WAIT(n)  asm volatile("cp.async.wait_group %0;" :: "n"(n) : "memory")

__device__ __forceinline__ uint32_t packhf(float a, float b) {
    __half2 t = __floats2half2_rn(a, b);   // low = a, high = b
    return *reinterpret_cast<uint32_t*>(&t);
}
__device__ __forceinline__ float hflo(uint32_t v) {
    __half2 t = *reinterpret_cast<__half2*>(&v);
    return __low2float(t);
}
__device__ __forceinline__ float hfhi(uint32_t v) {
    __half2 t = *reinterpret_cast<__half2*>(&v);
    return __high2float(t);
}

// -------- fp16 HMMA GEMM: CTA 128x128, warp 32x64, 2 CTAs/SM ------------------
// out_mode: 0 fp32 C+bias; 1 fp16 Chf (+bias, z selects operand set);
//           2 fp32 gate-scaled; 3 sigmoid row-sum atomics into gout;
//           4 QKV epilogue: bias + per-head RMS norm (q hi/lo, k fp16) + v fp16.
#define TC_SMEM_2P (2*49152)   // 98304
#define TC_SMEM_1P (2*32768)   // 65536
__global__ __launch_bounds__(256, 2)
void mma_gemm_kernel(const __half* __restrict__ Ahp, const __half* __restrict__ Alp,
                     const __half* __restrict__ Bhp,
                     const float* __restrict__ bias, float* __restrict__ C,
                     __half* __restrict__ Chf,
                     const float* __restrict__ grow, float* __restrict__ gout,
                     const __half* __restrict__ Ahp2, const __half* __restrict__ Bhp2,
                     const float* __restrict__ bias2, __half* __restrict__ Chf2,
                     const float* __restrict__ qw, const float* __restrict__ kw,
                     __half* __restrict__ qh_, __half* __restrict__ ql_,
                     __half* __restrict__ kh_, __half* __restrict__ vhf_,
                     int M, int N, int K, long sA, long sB, long sC,
                     int npass, int out_mode)
{
    extern __shared__ char smem[];
    uint32_t sb = smem_u32(smem);
    int tid = threadIdx.x, wid = tid >> 5, lane = tid & 31;
    int m0 = blockIdx.y * 128, n0 = blockIdx.x * 128;
    long zb = blockIdx.z;
    const __half* Ah = Ahp + zb * sA;
    const __half* Al = (npass == 2) ? (Alp + zb * sA) : Ahp;
    const __half* Bh = Bhp + zb * sB;
    if (out_mode == 1 && blockIdx.z == 1) {
        Ah = Ahp2; Bh = Bhp2; bias = bias2; Chf = Chf2;
    }

    const int nsteps = K / 64;
    const uint32_t SS   = (npass == 2) ? 49152 : 32768;
    const uint32_t BOFF = (npass == 2) ? 32768 : 16384;
    const int ncp = (npass == 2) ? 12 : 8;

    auto issue = [&](int step, int stage) {
        uint32_t stb = sb + stage * SS;
        int k0 = step * 64;
#pragma unroll
        for (int i = 0; i < 12; i++) {
            if (i >= ncp) break;
            int c = i * 256 + tid;
            int tile = c >> 10;
            int w = c & 1023;
            int row = w >> 3, ch = w & 7;
            const __half* src;
            uint32_t tbase;
            if (npass == 2) {
                if      (tile == 0) { src = Ah; tbase = 0; }
                else if (tile == 1) { src = Al; tbase = 16384; }
                else                { src = Bh; tbase = 32768; }
            } else {
                if      (tile == 0) { src = Ah; tbase = 0; }
                else                { src = Bh; tbase = 16384; }
            }
            int gr = ((npass == 2 ? tile == 2 : tile == 1) ? n0 : m0) + row;
            const __half* gp = src + (long)gr * K + k0 + ch * 8;
            uint32_t dst = stb + tbase + row * 128 + ((ch ^ (row & 7)) << 4);
            CP_ASYNC16(dst, gp);
        }
        CP_COMMIT();
    };

    int mbase = (wid >> 1) * 32;   // 0/32/64/96
    int nbase = (wid & 1) * 64;    // 0/64
    int arow = lane & 15;
    int brow = (lane & 7) + ((lane >> 4) & 1) * 8;

    float acc[2][8][4];
#pragma unroll
    for (int mt = 0; mt < 2; mt++)
#pragma unroll
        for (int nt = 0; nt < 8; nt++)
#pragma unroll
            for (int e = 0; e < 4; e++) acc[mt][nt][e] = 0.f;

    issue(0, 0);
    if (nsteps > 1) issue(1, 1);

    for (int step = 0; step < nsteps; step++) {
        if (step + 1 < nsteps) { CP_WAIT(1); } else { CP_WAIT(0); }
        __syncthreads();

        uint32_t stb = sb + (uint32_t)(step & 1) * SS;
#pragma unroll
        for (int k16 = 0; k16 < 4; k16++) {
            uint32_t ahf[2][4], alf[2][4], bhf[4][4];
            int ach = 2 * k16 + (lane >> 4);
#pragma unroll
            for (int mt = 0; mt < 2; mt++) {
                int row = mbase + mt * 16 + arow;
                uint32_t ad = stb + row * 128 + ((ach ^ (row & 7)) << 4);
                LDSM4(ahf[mt], ad);
                if (npass == 2) LDSM4(alf[mt], ad + 16384);
            }
            int bch = 2 * k16 + ((lane >> 3) & 1);
#pragma unroll
            for (int j = 0; j < 4; j++) {
                int row = nbase + j * 16 + brow;
                uint32_t bd = stb + BOFF + row * 128 + ((bch ^ (row & 7)) << 4);
                LDSM4(bhf[j], bd);
            }
#pragma unroll
            for (int mt = 0; mt < 2; mt++)
#pragma unroll
                for (int nt = 0; nt < 8; nt++) {
                    int j = nt >> 1, p = (nt & 1) * 2;
                    MMAH(acc[mt][nt], ahf[mt], bhf[j][p], bhf[j][p+1]);
                }
            if (npass == 2) {
#pragma unroll
                for (int mt = 0; mt < 2; mt++)
#pragma unroll
                    for (int nt = 0; nt < 8; nt++) {
                        int j = nt >> 1, p = (nt & 1) * 2;
                        MMAH(acc[mt][nt], alf[mt], bhf[j][p], bhf[j][p+1]);
                    }
            }
        }
        __syncthreads();
        if (step + 2 < nsteps) issue(step + 2, step & 1);
    }

    // ------------------------------ epilogues ---------------------------------
    if (out_mode == 4) {
        int c0 = n0 + nbase;             // multiple of 64
        int type = c0 >> 10;             // 0=q 1=k 2=v
        int hh = (c0 & 1023) >> 6;       // head index
        const float* wv = (type == 0) ? qw : kw;
#pragma unroll
        for (int mt = 0; mt < 2; mt++) {
            float vals[8][4];
            float ss0 = 0.f, ss1 = 0.f;
            int r0 = m0 + mbase + mt * 16 + (lane >> 2);
#pragma unroll
            for (int nt = 0; nt < 8; nt++) {
                int c = c0 + nt * 8 + 2 * (lane & 3);
                float b0 = bias[c], b1 = bias[c + 1];
                vals[nt][0] = acc[mt][nt][0] + b0;
                vals[nt][1] = acc[mt][nt][1] + b1;
                vals[nt][2] = acc[mt][nt][2] + b0;
                vals[nt][3] = acc[mt][nt][3] + b1;
                ss0 += vals[nt][0]*vals[nt][0] + vals[nt][1]*vals[nt][1];
                ss1 += vals[nt][2]*vals[nt][2] + vals[nt][3]*vals[nt][3];
            }
            ss0 += __shfl_xor_sync(0xffffffffu, ss0, 1, 4);
            ss0 += __shfl_xor_sync(0xffffffffu, ss0, 2, 4);
            ss1 += __shfl_xor_sync(0xffffffffu, ss1, 1, 4);
            ss1 += __shfl_xor_sync(0xffffffffu, ss1, 2, 4);
            float sc0 = 1.f, sc1 = 1.f;
            if (type == 0) {
                sc0 = rsqrtf(ss0 * (1.0f/64.0f) + 1e-6f) * SCALE;
                sc1 = rsqrtf(ss1 * (1.0f/64.0f) + 1e-6f) * SCALE;
            } else if (type == 1) {
                sc0 = rsqrtf(ss0 * (1.0f/64.0f) + 1e-6f);
                sc1 = rsqrtf(ss1 * (1.0f/64.0f) + 1e-6f);
            }
#pragma unroll
            for (int e = 0; e < 2; e++) {
                int r = r0 + 8 * e;
                int b = r >> 9, n = r & 511;
                int g = b >> 2, inst = b & 3;
                long obase = (((long)(g*16 + hh)) * SEQ + inst*512 + n) * HD_;
                float sc = e ? sc1 : sc0;
#pragma unroll
                for (int nt = 0; nt < 8; nt++) {
                    int colh = nt * 8 + 2 * (lane & 3);
                    if (type == 2) {
                        *(uint32_t*)&vhf_[obase + colh] =
                            packhf(vals[nt][2*e], vals[nt][2*e+1]);
                    } else if (type == 1) {
                        float u0 = vals[nt][2*e]   * sc * wv[colh];
                        float u1 = vals[nt][2*e+1] * sc * wv[colh + 1];
                        *(uint32_t*)&kh_[obase + colh] = packhf(u0, u1);
                    } else {
                        float u0 = vals[nt][2*e]   * sc * wv[colh];
                        float u1 = vals[nt][2*e+1] * sc * wv[colh + 1];
                        uint32_t hp = packhf(u0, u1);
                        uint32_t lp = packhf(u0 - hflo(hp), u1 - hfhi(hp));
                        *(uint32_t*)&qh_[obase + colh] = hp;
                        *(uint32_t*)&ql_[obase + colh] = lp;
                    }
                }
            }
        }
        return;
    }

    if (out_mode == 3) {
#pragma unroll
        for (int mt = 0; mt < 2; mt++) {
            int r0 = m0 + mbase + mt * 16 + (lane >> 2);
            float ps0 = 0.f, ps1 = 0.f;
#pragma unroll
            for (int nt = 0; nt < 8; nt++) {
                ps0 += 1.0f / (1.0f + __expf(-acc[mt][nt][0] * S2));
                ps0 += 1.0f / (1.0f + __expf(-acc[mt][nt][1] * S2));
                ps1 += 1.0f / (1.0f + __expf(-acc[mt][nt][2] * S2));
                ps1 += 1.0f / (1.0f + __expf(-acc[mt][nt][3] * S2));
            }
            ps0 += __shfl_xor_sync(0xffffffffu, ps0, 1, 4);
            ps0 += __shfl_xor_sync(0xffffffffu, ps0, 2, 4);
            ps1 += __shfl_xor_sync(0xffffffffu, ps1, 1, 4);
            ps1 += __shfl_xor_sync(0xffffffffu, ps1, 2, 4);
            if ((lane & 3) == 0) {
                atomicAdd(&gout[zb * 512 + r0], ps0);
                atomicAdd(&gout[zb * 512 + r0 + 8], ps1);
            }
        }
        return;
    }

#pragma unroll
    for (int mt = 0; mt < 2; mt++) {
        int r0 = m0 + mbase + mt * 16 + (lane >> 2);
        float g0 = 1.f, g1 = 1.f;
        if (out_mode == 2) {
            g0 = 1.0f + grow[r0] * (1.0f/512.0f);
            g1 = 1.0f + grow[r0 + 8] * (1.0f/512.0f);
        }
#pragma unroll
        for (int nt = 0; nt < 8; nt++) {
            int c = n0 + nbase + nt * 8 + 2 * (lane & 3);
            float b0 = 0.f, b1 = 0.f;
            if (bias) { b0 = bias[c]; b1 = bias[c + 1]; }
            float v00 = acc[mt][nt][0] * g0 + b0, v01 = acc[mt][nt][1] * g0 + b1;
            float v10 = acc[mt][nt][2] * g1 + b0, v11 = acc[mt][nt][3] * g1 + b1;
            if (out_mode == 1) {
                *(uint32_t*)&Chf[(long)r0 * N + c]       = packhf(v00, v01);
                *(uint32_t*)&Chf[(long)(r0 + 8) * N + c] = packhf(v10, v11);
            } else {
                float* Cc = C + zb * sC;
                float2 w0; w0.x = v00; w0.y = v01;
                *(float2*)&Cc[(long)r0 * N + c] = w0;
                float2 w1; w1.x = v10; w1.y = v11;
                *(float2*)&Cc[(long)(r0 + 8) * N + c] = w1;
            }
        }
    }
}

// ---------------- weight transpose + fp16 convert (6 weights fused) ----------
__device__ __forceinline__ void wt_split_body(
    const float* __restrict__ W, __half* __restrict__ Th, float (*t)[65])
{
    int n0 = blockIdx.x * 64, k0 = blockIdx.y * 64;
    int tid = threadIdx.x;
#pragma unroll
    for (int it = 0; it < 4; it++) {
        int row = (tid >> 4) + it * 16;
        int c4 = (tid & 15) * 4;
        float4 v = *(const float4*)&W[(long)(k0 + row) * D_ + n0 + c4];
        t[row][c4+0] = v.x; t[row][c4+1] = v.y; t[row][c4+2] = v.z; t[row][c4+3] = v.w;
    }
    __syncthreads();
    int n = tid >> 2, kc = (tid & 3) * 16;
    uint32_t hb[8];
#pragma unroll
    for (int j = 0; j < 16; j += 2)
        hb[j >> 1] = packhf(t[kc + j][n], t[kc + j + 1][n]);
    long obase = (long)(n0 + n) * D_ + k0 + kc;
    *(uint4*)&Th[obase]     = make_uint4(hb[0], hb[1], hb[2], hb[3]);
    *(uint4*)&Th[obase + 8] = make_uint4(hb[4], hb[5], hb[6], hb[7]);
}

__global__ __launch_bounds__(256) void wt_split6_kernel(
    const float* __restrict__ Wq, const float* __restrict__ Wk, const float* __restrict__ Wv,
    const float* __restrict__ Wiq, const float* __restrict__ Wik, const float* __restrict__ Wo,
    __half* __restrict__ wqkvh, __half* __restrict__ wiqh,
    __half* __restrict__ wikh, __half* __restrict__ woh)
{
    __shared__ float t[64][65];
    const float* W;
    __half* Th;
    switch (blockIdx.z) {
        case 0: W = Wq;  Th = wqkvh;             break;
        case 1: W = Wk;  Th = wqkvh + 1024*1024; break;
        case 2: W = Wv;  Th = wqkvh + 2048*1024; break;
        case 3: W = Wiq; Th = wiqh;              break;
        case 4: W = Wik; Th = wikh;              break;
        default: W = Wo; Th = woh;               break;
    }
    wt_split_body(W, Th, t);
}

// ---------------- bias concat (bq|bk|bv) --------------------------------------
__global__ void bias3_kernel(const float* __restrict__ a, const float* __restrict__ b,
                             const float* __restrict__ c, float* __restrict__ o)
{
    int i = blockIdx.x * 256 + threadIdx.x;
    if (i < 1024)       o[i] = a[i];
    else if (i < 2048)  o[i] = b[i - 1024];
    else if (i < 3072)  o[i] = c[i - 2048];
}

// ---------------- activation split (fp16 hi/lo) -------------------------------
__global__ __launch_bounds__(256) void split_kernel(
    const float* __restrict__ src, __half* __restrict__ h,
    __half* __restrict__ l, int n4)
{
    int i = blockIdx.x * 256 + threadIdx.x;
    if (i >= n4) return;
    float4 f = ((const float4*)src)[i];
    uint32_t h0 = packhf(f.x, f.y), h1 = packhf(f.z, f.w);
    ((uint32_t*)h)[i*2+0] = h0;
    ((uint32_t*)h)[i*2+1] = h1;
    ((uint32_t*)l)[i*2+0] = packhf(f.x - hflo(h0), f.y - hfhi(h0));
    ((uint32_t*)l)[i*2+1] = packhf(f.z - hflo(h1), f.w - hfhi(h1));
}

// ---------------- flash attention: S fp16 2-pass, PV fp16 2-pass --------------
// 3-stage KV ring (32KB each: Kh 16K + Vh 16K), one sync/iter; Q hi/lo 32KB.
#define FL_SMEM (3*32768 + 32768)   // 131072
__global__ __launch_bounds__(256, 1)
void flash_mma_kernel(const __half* __restrict__ Qh_, const __half* __restrict__ Ql_,
                      const __half* __restrict__ Kh_, const __half* __restrict__ Vh_,
                      __half* __restrict__ Oh, __half* __restrict__ Ol)
{
    extern __shared__ char smem[];
    uint32_t sb = smem_u32(smem);
    int tid = threadIdx.x, wid = tid >> 5, lane = tid & 31;
    int qt = blockIdx.x, gh = blockIdx.y;
    long ghoff = (long)gh * SEQ * HD_;
    const __half* Qh = Qh_ + ghoff + (long)qt * 128 * HD_;
    const __half* Ql = Ql_ + ghoff + (long)qt * 128 * HD_;
    const __half* Kh = Kh_ + ghoff;
    const __half* Vh = Vh_ + ghoff;

    const uint32_t QOFF = 98304;

    {
#pragma unroll
        for (int i = 0; i < 8; i++) {
            int c = i * 256 + tid;
            int arr = c >> 10, w = c & 1023, row = w >> 3, ch = w & 7;
            const __half* src = (arr ? Ql : Qh) + (long)row * 64 + ch * 8;
            uint32_t dst = sb + QOFF + arr * 16384 + row * 128 + ((ch ^ (row & 7)) << 4);
            CP_ASYNC16(dst, src);
        }
        CP_COMMIT();
    }

    auto issueKV = [&](int it, int stage) {
        uint32_t stb = sb + stage * 32768;
#pragma unroll
        for (int i = 0; i < 8; i++) {
            int c = i * 256 + tid;
            int arr = c >> 10, w = c & 1023, row = w >> 3, ch = w & 7;
            const __half* src = (arr ? Vh : Kh) + (long)(it * 128 + row) * 64 + ch * 8;
            uint32_t dst = stb + arr * 16384 + row * 128 + ((ch ^ (row & 7)) << 4);
            CP_ASYNC16(dst, src);
        }
        CP_COMMIT();
    };

    issueKV(0, 0);
    issueKV(1, 1);

    CP_WAIT(2);
    __syncthreads();
    uint32_t qhf[4][4], qlf[4][4];
    {
        int arow = lane & 15;
#pragma unroll
        for (int kt = 0; kt < 4; kt++) {
            int row = wid * 16 + arow;
            int ach = 2 * kt + (lane >> 4);
            uint32_t ad = sb + QOFF + row * 128 + ((ach ^ (row & 7)) << 4);
            LDSM4(qhf[kt], ad);
            LDSM4(qlf[kt], ad + 16384);
        }
    }

    float o[8][4];
#pragma unroll
    for (int nt = 0; nt < 8; nt++)
#pragma unroll
        for (int e = 0; e < 4; e++) o[nt][e] = 0.f;
    float m0 = -1e30f, m1 = -1e30f, lp0 = 0.f, lp1 = 0.f;

    for (int it = 0; it < 16; it++) {
        if (it < 15) { CP_WAIT(1); } else { CP_WAIT(0); }
        __syncthreads();
        if (it + 2 < 16) issueKV(it + 2, (it + 2) % 3);

        uint32_t stb = sb + (uint32_t)(it % 3) * 32768;

        float s[16][4];
#pragma unroll
        for (int t = 0; t < 16; t++)
#pragma unroll
            for (int e = 0; e < 4; e++) s[t][e] = 0.f;

        int brow = (lane & 7) + ((lane >> 4) & 1) * 8;
#pragma unroll
        for (int kt = 0; kt < 4; kt++) {
            int bch = 2 * kt + ((lane >> 3) & 1);
#pragma unroll
            for (int jp = 0; jp < 4; jp++) {
                uint32_t khf[2][4];
#pragma unroll
                for (int j = 0; j < 2; j++) {
                    int row = (2 * jp + j) * 16 + brow;
                    uint32_t bd = stb + row * 128 + ((bch ^ (row & 7)) << 4);
                    LDSM4(khf[j], bd);
                }
                int t0 = 4 * jp;
                MMAH(s[t0+0], qhf[kt], khf[0][0], khf[0][1]);
                MMAH(s[t0+1], qhf[kt], khf[0][2], khf[0][3]);
                MMAH(s[t0+2], qhf[kt], khf[1][0], khf[1][1]);
                MMAH(s[t0+3], qhf[kt], khf[1][2], khf[1][3]);
                MMAH(s[t0+0], qlf[kt], khf[0][0], khf[0][1]);
                MMAH(s[t0+1], qlf[kt], khf[0][2], khf[0][3]);
                MMAH(s[t0+2], qlf[kt], khf[1][0], khf[1][1]);
                MMAH(s[t0+3], qlf[kt], khf[1][2], khf[1][3]);
            }
        }

        float t0 = -1e30f, t1 = -1e30f;
#pragma unroll
        for (int t = 0; t < 16; t++) {
            t0 = fmaxf(t0, fmaxf(s[t][0], s[t][1]));
            t1 = fmaxf(t1, fmaxf(s[t][2], s[t][3]));
        }
        t0 = fmaxf(t0, __shfl_xor_sync(0xffffffffu, t0, 1, 4));
        t0 = fmaxf(t0, __shfl_xor_sync(0xffffffffu, t0, 2, 4));
        t1 = fmaxf(t1, __shfl_xor_sync(0xffffffffu, t1, 1, 4));
        t1 = fmaxf(t1, __shfl_xor_sync(0xffffffffu, t1, 2, 4));
        float mn0 = fmaxf(m0, t0), mn1 = fmaxf(m1, t1);
        float c0 = __expf(m0 - mn0), c1 = __expf(m1 - mn1);
        m0 = mn0; m1 = mn1;
        lp0 *= c0; lp1 *= c1;
#pragma unroll
        for (int nt = 0; nt < 8; nt++) {
            o[nt][0] *= c0; o[nt][1] *= c0;
            o[nt][2] *= c1; o[nt][3] *= c1;
        }
#pragma unroll
        for (int t = 0; t < 16; t++) {
            s[t][0] = __expf(s[t][0] - m0);
            s[t][1] = __expf(s[t][1] - m0);
            s[t][2] = __expf(s[t][2] - m1);
            s[t][3] = __expf(s[t][3] - m1);
            lp0 += s[t][0] + s[t][1];
            lp1 += s[t][2] + s[t][3];
        }

        int vrow = lane & 15;
#pragma unroll
        for (int kt = 0; kt < 8; kt++) {
            uint32_t pha[4], pla[4];
#pragma unroll
            for (int q = 0; q < 2; q++) {
                float a0 = s[2*kt + q][0], a1 = s[2*kt + q][1];
                float a2 = s[2*kt + q][2], a3 = s[2*kt + q][3];
                uint32_t h0 = packhf(a0, a1);
                uint32_t h1 = packhf(a2, a3);
                pha[2*q]   = h0;
                pha[2*q+1] = h1;
                pla[2*q]   = packhf(a0 - hflo(h0), a1 - hfhi(h0));
                pla[2*q+1] = packhf(a2 - hflo(h1), a3 - hfhi(h1));
            }
            int row = kt * 16 + vrow;
#pragma unroll
            for (int np = 0; np < 2; np++) {
                uint32_t vhf[2][4];
#pragma unroll
                for (int j = 0; j < 2; j++) {
                    int ch = 2 * (2 * np + j) + (lane >> 4);
                    uint32_t vd = stb + 16384 + row * 128 + ((ch ^ (row & 7)) << 4);
                    LDSM4T(vhf[j], vd);
                }
                int ob = 4 * np;
                MMAH(o[ob+0], pha, vhf[0][0], vhf[0][1]);
                MMAH(o[ob+1], pha, vhf[0][2], vhf[0][3]);
                MMAH(o[ob+2], pha, vhf[1][0], vhf[1][1]);
                MMAH(o[ob+3], pha, vhf[1][2], vhf[1][3]);
                MMAH(o[ob+0], pla, vhf[0][0], vhf[0][1]);
                MMAH(o[ob+1], pla, vhf[0][2], vhf[0][3]);
                MMAH(o[ob+2], pla, vhf[1][0], vhf[1][1]);
                MMAH(o[ob+3], pla, vhf[1][2], vhf[1][3]);
            }
        }
    }

    lp0 += __shfl_xor_sync(0xffffffffu, lp0, 1, 4);
    lp0 += __shfl_xor_sync(0xffffffffu, lp0, 2, 4);
    lp1 += __shfl_xor_sync(0xffffffffu, lp1, 1, 4);
    lp1 += __shfl_xor_sync(0xffffffffu, lp1, 2, 4);
    float inv0 = 1.0f / lp0, inv1 = 1.0f / lp1;

    int g = gh >> 4, h = gh & 15;
#pragma unroll
    for (int e = 0; e < 2; e++) {
        int r = qt * 128 + wid * 16 + (lane >> 2) + 8 * e;
        int inst = r >> 9, n = r & 511;
        int b = g * 4 + inst;
        float inv = e ? inv1 : inv0;
        long base = ((long)(b * 512 + n)) * D_ + h * HD_;
#pragma unroll
        for (int nt = 0; nt < 8; nt++) {
            float v0 = o[nt][2*e] * inv, v1 = o[nt][2*e+1] * inv;
            uint32_t hp = packhf(v0, v1);
            uint32_t lp = packhf(v0 - hflo(hp), v1 - hfhi(hp));
            long idx = base + nt * 8 + 2 * (lane & 3);
            *(uint32_t*)&Oh[idx] = hp;
            *(uint32_t*)&Ol[idx] = lp;
        }
    }
}

// ---------------- instance feature -> fp16 ------------------------------------
__global__ __launch_bounds__(256) void feat_kernel(
    const float* __restrict__ mask, const float* __restrict__ embed,
    __half* __restrict__ fh)
{
    int row = blockIdx.x;
    float m0 = mask[row*4+0], m1 = mask[row*4+1];
    float m2 = mask[row*4+2], m3 = mask[row*4+3];
    for (int c = threadIdx.x * 2; c < D_; c += 512) {
        float f0 = m0*embed[c]   + m1*embed[D_ + c]   + m2*embed[2*D_ + c]   + m3*embed[3*D_ + c];
        float f1 = m0*embed[c+1] + m1*embed[D_ + c+1] + m2*embed[2*D_ + c+1] + m3*embed[3*D_ + c+1];
        *(uint32_t*)&fh[(long)row*D_ + c] = packhf(f0, f1);
    }
}

__global__ void zero_kernel(float* __restrict__ p, int n)
{
    int i = blockIdx.x * blockDim.x + threadIdx.x;
    if (i < n) p[i] = 0.f;
}

// ------------------------------- launch --------------------------------------
extern "C" void kernel_launch(void* const* d_in, const int* in_sizes, int n_in,
                              void* d_out, int out_size)
{
    const float* x     = (const float*)d_in[0];
    const float* mask  = (const float*)d_in[1];
    const float* Wq    = (const float*)d_in[2];
    const float* bq    = (const float*)d_in[3];
    const float* Wk    = (const float*)d_in[4];
    const float* bk    = (const float*)d_in[5];
    const float* Wv    = (const float*)d_in[6];
    const float* bv    = (const float*)d_in[7];
    const float* Wo    = (const float*)d_in[8];
    const float* bo    = (const float*)d_in[9];
    const float* Wiq   = (const float*)d_in[10];
    const float* biq   = (const float*)d_in[11];
    const float* Wik   = (const float*)d_in[12];
    const float* bik   = (const float*)d_in[13];
    const float* embed = (const float*)d_in[14];
    const float* qw    = (const float*)d_in[15];
    const float* kw    = (const float*)d_in[16];
    float* out = (float*)d_out;

    float *gacc,*bqkv;
    cudaGetSymbolAddress((void**)&gacc, g_gacc);
    cudaGetSymbolAddress((void**)&bqkv, g_bqkv);

    __half *qhg,*qlg,*khg,*vhg;
    cudaGetSymbolAddress((void**)&qhg, g_qhg);   cudaGetSymbolAddress((void**)&qlg, g_qlg);
    cudaGetSymbolAddress((void**)&khg, g_khg);   cudaGetSymbolAddress((void**)&vhg, g_vhg);

    __half *wqkvh,*wiqh,*wikh,*woh,*xh,*xl,*ah,*al,*fh,*iqh,*ikh;
    cudaGetSymbolAddress((void**)&wqkvh, g_wqkvh);
    cudaGetSymbolAddress((void**)&wiqh, g_wiqh);
    cudaGetSymbolAddress((void**)&wikh, g_wikh);
    cudaGetSymbolAddress((void**)&woh, g_woh);
    cudaGetSymbolAddress((void**)&xh, g_xh);       cudaGetSymbolAddress((void**)&xl, g_xl);
    cudaGetSymbolAddress((void**)&ah, g_ah);       cudaGetSymbolAddress((void**)&al, g_al);
    cudaGetSymbolAddress((void**)&fh, g_fh);
    cudaGetSymbolAddress((void**)&iqh, g_iqh);     cudaGetSymbolAddress((void**)&ikh, g_ikh);

    cudaFuncSetAttribute((const void*)mma_gemm_kernel,
                         cudaFuncAttributeMaxDynamicSharedMemorySize, TC_SMEM_2P);
    cudaFuncSetAttribute((const void*)flash_mma_kernel,
                         cudaFuncAttributeMaxDynamicSharedMemorySize, FL_SMEM);

    const int N4 = MROWS * D_ / 4;
    const int SPLIT_BLOCKS = (N4 + 255) / 256;

    // launches 1-3
    wt_split6_kernel<<<dim3(16, 16, 6), 256>>>(Wq, Wk, Wv, Wiq, Wik, Wo,
                                               wqkvh, wiqh, wikh, woh);
    bias3_kernel<<<12, 256>>>(bq, bk, bv, bqkv);
    split_kernel<<<SPLIT_BLOCKS, 256>>>(x, xh, xl, N4);

    // launch #4 (profiled): fused QKV projection (fp16 2-pass) + RMS epilogue
    mma_gemm_kernel<<<dim3(D3/128, MROWS/128), 256, TC_SMEM_2P>>>(
        xh, xl, wqkvh, bqkv, nullptr, nullptr, nullptr, nullptr,
        nullptr, nullptr, nullptr, nullptr,
        qw, kw, qhg, qlg, khg, vhg,
        MROWS, D3, D_, 0, 0, 0, 2, 4);

    // small prep
    zero_kernel<<<(MROWS+255)/256, 256>>>(gacc, MROWS);
    feat_kernel<<<MROWS, 256>>>(mask, embed, fh);

    // attention (S fp16 2-pass, PV fp16 2-pass; emits fp16 ah/al)
    flash_mma_kernel<<<dim3(SEQ/128, GH), 256, FL_SMEM>>>(qhg, qlg, khg, vhg, ah, al);

    // iq & ik projections fused (fp16 1-pass; z selects operand set)
    mma_gemm_kernel<<<dim3(D_/128, MROWS/128, 2), 256, TC_SMEM_1P>>>(
        ah, nullptr, wiqh, biq, nullptr, iqh, nullptr, nullptr,
        fh, wikh, bik, ikh,
        nullptr, nullptr, nullptr, nullptr, nullptr, nullptr,
        MROWS, D_, D_, 0, 0, 0, 1, 1);

    // gate: per-batch iq @ ik^T (fp16 1-pass) with fused sigmoid row-sum
    mma_gemm_kernel<<<dim3(4, 4, 8), 256, TC_SMEM_1P>>>(
        iqh, nullptr, ikh, nullptr, nullptr, nullptr, nullptr, gacc,
        nullptr, nullptr, nullptr, nullptr,
        nullptr, nullptr, nullptr, nullptr, nullptr, nullptr,
        512, 512, D_, (long)512*D_, (long)512*D_, 0, 1, 3);

    // gated output projection (fp16 2-pass): out = diag(1+gacc/512)*(attn@Wo)+bo
    mma_gemm_kernel<<<dim3(D_/128, MROWS/128), 256, TC_SMEM_2P>>>(
        ah, al, woh, bo, out, nullptr, gacc, nullptr,
        nullptr, nullptr, nullptr, nullptr,
        nullptr, nullptr, nullptr, nullptr, nullptr, nullptr,
        MROWS, D_, D_, 0, 0, 0, 2, 2);
}